// round 9
// baseline (speedup 1.0000x reference)
#include <cuda_runtime.h>
#include <cuda_bf16.h>
#include <cstdint>
#include <math.h>

#define BB   2
#define SS   4096
#define DD   1024
#define HH   16
#define DKK  64
#define BLL  128
#define GG   16
#define GLL  256
#define NBUCK 32
#define NEGV (-1e10f)
#define SROW (SS + GLL)

// ---------------- scratch (device globals: allocation-free) ----------------
__device__ float g_qkv[BB*SS*3*DD];    // [row][q|k|v]
__device__ float g_skv[BB*GLL*2*DD];   // [row][sk|sv]
__device__ float g_gi [BB*GLL*DD];
__device__ float g_pb [HH*512];
__device__ float g_gb [HH*512];
__device__ int   g_bid [BB*SS];
__device__ int   g_gseg[BB*GLL];
__device__ int   g_full[BB];

// bf16 hi/lo split buffers
__device__ __nv_bfloat16 g_hs_hi  [BB*SS*DD];
__device__ __nv_bfloat16 g_hs_lo  [BB*SS*DD];
__device__ __nv_bfloat16 g_ctx_hi [BB*SS*DD];
__device__ __nv_bfloat16 g_ctx_lo [BB*SS*DD];
__device__ __nv_bfloat16 g_gi_hi  [BB*GLL*DD];
__device__ __nv_bfloat16 g_gi_lo  [BB*GLL*DD];
__device__ __nv_bfloat16 g_wqkv_hi[DD*3*DD];
__device__ __nv_bfloat16 g_wqkv_lo[DD*3*DD];
__device__ __nv_bfloat16 g_wo_hi  [DD*DD];
__device__ __nv_bfloat16 g_wo_lo  [DD*DD];
// pre-split attention K/V: rows [0,SS) local, [SS,SS+GLL) side
__device__ __nv_bfloat16 g_kat_hi [BB*SROW*DD];
__device__ __nv_bfloat16 g_kat_lo [BB*SROW*DD];
__device__ __nv_bfloat16 g_vat_hi [BB*SROW*DD];
__device__ __nv_bfloat16 g_vat_lo [BB*SROW*DD];

// ---------------- helpers ----------------
__device__ __forceinline__ uint32_t smem_u32(const void* p) {
    uint32_t a;
    asm("{ .reg .u64 t; cvta.to.shared.u64 t, %1; cvt.u32.u64 %0, t; }" : "=r"(a) : "l"(p));
    return a;
}

#define CP16(dst, src) asm volatile("cp.async.cg.shared.global [%0], [%1], 16;" :: "r"(dst), "l"(src) : "memory")
#define CP_COMMIT()    asm volatile("cp.async.commit_group;" ::: "memory")
#define CP_WAIT2()     asm volatile("cp.async.wait_group 2;" ::: "memory")
#define CP_WAIT1()     asm volatile("cp.async.wait_group 1;" ::: "memory")
#define CP_WAIT0()     asm volatile("cp.async.wait_group 0;" ::: "memory")

__device__ __forceinline__ void ldsm4(uint32_t* r, uint32_t a) {
    asm volatile("ldmatrix.sync.aligned.m8n8.x4.shared.b16 {%0,%1,%2,%3}, [%4];"
        : "=r"(r[0]), "=r"(r[1]), "=r"(r[2]), "=r"(r[3]) : "r"(a));
}
__device__ __forceinline__ void ldsm4t(uint32_t* r, uint32_t a) {
    asm volatile("ldmatrix.sync.aligned.m8n8.x4.trans.shared.b16 {%0,%1,%2,%3}, [%4];"
        : "=r"(r[0]), "=r"(r[1]), "=r"(r[2]), "=r"(r[3]) : "r"(a));
}
__device__ __forceinline__ void mma_bf16(float* d, const uint32_t* a, uint32_t b0, uint32_t b1) {
    asm volatile("mma.sync.aligned.m16n8k16.row.col.f32.bf16.bf16.f32 "
        "{%0,%1,%2,%3}, {%4,%5,%6,%7}, {%8,%9}, {%0,%1,%2,%3};"
        : "+f"(d[0]), "+f"(d[1]), "+f"(d[2]), "+f"(d[3])
        : "r"(a[0]), "r"(a[1]), "r"(a[2]), "r"(a[3]), "r"(b0), "r"(b1));
}

__device__ __forceinline__ void split4(float4 a, uint2& h, uint2& l) {
    __nv_bfloat162 h01 = __floats2bfloat162_rn(a.x, a.y);
    __nv_bfloat162 h23 = __floats2bfloat162_rn(a.z, a.w);
    float l0 = a.x - __bfloat162float(h01.x);
    float l1 = a.y - __bfloat162float(h01.y);
    float l2 = a.z - __bfloat162float(h23.x);
    float l3 = a.w - __bfloat162float(h23.y);
    __nv_bfloat162 q01 = __floats2bfloat162_rn(l0, l1);
    __nv_bfloat162 q23 = __floats2bfloat162_rn(l2, l3);
    h = make_uint2(*(uint32_t*)&h01, *(uint32_t*)&h23);
    l = make_uint2(*(uint32_t*)&q01, *(uint32_t*)&q23);
}

__device__ __forceinline__ void packhl(float a, float b, uint32_t& hp, uint32_t& lp) {
    __nv_bfloat162 hv = __floats2bfloat162_rn(a, b);
    __nv_bfloat162 lv = __floats2bfloat162_rn(a - __bfloat162float(hv.x),
                                              b - __bfloat162float(hv.y));
    hp = *(uint32_t*)&hv;
    lp = *(uint32_t*)&lv;
}

// ---------------- fp32 -> bf16 hi/lo split ----------------
__global__ void k_split(const float4* __restrict__ src,
                        uint2* __restrict__ hi, uint2* __restrict__ lo, int n4) {
    int i = blockIdx.x * 256 + threadIdx.x;
    if (i >= n4) return;
    uint2 h, l;
    split4(src[i], h, l);
    hi[i] = h; lo[i] = l;
}

// ---- weight split: 3 sources -> interleaved [k][3*DD] layout --------------
__global__ void k_split_qkv(const float4* __restrict__ Wq, const float4* __restrict__ Wk,
                            const float4* __restrict__ Wv,
                            uint2* __restrict__ hi, uint2* __restrict__ lo) {
    const int NW4 = DD * DD / 4;
    int idx = blockIdx.x * 256 + threadIdx.x;
    if (idx >= 3 * NW4) return;
    int i = idx / NW4;
    int r = idx % NW4;
    int k  = r >> 8;
    int n4 = r & 255;
    const float4* src = (i == 0) ? Wq : (i == 1) ? Wk : Wv;
    uint2 h, l;
    split4(src[r], h, l);
    int d = k * (3 * DD / 4) + i * (DD / 4) + n4;
    hi[d] = h; lo[d] = l;
}

// ---- attention K/V pre-split: local k/v rows + side rows, unified layout ----
__global__ void k_split_kv() {
    const int N4 = BB * SROW * DD / 4;
    int i4 = blockIdx.x * 256 + threadIdx.x;
    if (i4 >= N4) return;
    int c4  = (i4 & (DD / 4 - 1)) * 4;
    int row = i4 / (DD / 4);
    int b = row / SROW;
    int r = row % SROW;
    const float *kp, *vp;
    if (r < SS) {
        const float* base = g_qkv + ((size_t)(b * SS + r)) * (3 * DD) + c4;
        kp = base + DD; vp = base + 2 * DD;
    } else {
        const float* base = g_skv + ((size_t)(b * GLL + (r - SS))) * (2 * DD) + c4;
        kp = base; vp = base + DD;
    }
    uint2 kh, kl, vh, vl;
    split4(*(const float4*)kp, kh, kl);
    split4(*(const float4*)vp, vh, vl);
    size_t d = (size_t)row * DD + c4;
    *(uint2*)(g_kat_hi + d) = kh;
    *(uint2*)(g_kat_lo + d) = kl;
    *(uint2*)(g_vat_hi + d) = vh;
    *(uint2*)(g_vat_lo + d) = vl;
}

// ============ bf16-split GEMM (3-stage cp.async pipeline) ============
#define SH_A0   0
#define SH_A1   5120
#define SH_B0   10240
#define SH_B1   14592
#define SH_STG  18944
#define BGE_SMEM_BYTES (3 * SH_STG * 2)

__global__ __launch_bounds__(256, 2)
void bgemm(const __nv_bfloat16* __restrict__ Ahi, const __nv_bfloat16* __restrict__ Alo, int lda,
           const __nv_bfloat16* __restrict__ Bhi, const __nv_bfloat16* __restrict__ Blo, int ldb,
           float* __restrict__ C, int ldc, int K) {
    extern __shared__ __nv_bfloat16 sh[];
    uint32_t sbase = smem_u32(sh);

    int tid = threadIdx.x;
    int wid = tid >> 5, lane = tid & 31;
    int wm = wid & 3, wn = wid >> 2;
    int bx = blockIdx.x, by = blockIdx.y;

    float acc[2][8][4];
#pragma unroll
    for (int mt = 0; mt < 2; mt++)
#pragma unroll
        for (int nt = 0; nt < 8; nt++)
#pragma unroll
            for (int j = 0; j < 4; j++) acc[mt][nt][j] = 0.f;

    int ar0 = tid >> 2,          ac0 = (tid & 3) * 8;
    int ar1 = (tid + 256) >> 2,  ac1 = ((tid + 256) & 3) * 8;
    int br0 = tid >> 4,          bc0 = (tid & 15) * 8;
    int br1 = (tid + 256) >> 4,  bc1 = ((tid + 256) & 15) * 8;

    auto load_stage = [&](int c, int stage) {
        int k0 = c * 32;
        uint32_t s0 = sbase + (uint32_t)(stage * SH_STG) * 2;
        {
            size_t ga0 = (size_t)(by * 128 + ar0) * lda + k0 + ac0;
            size_t ga1 = (size_t)(by * 128 + ar1) * lda + k0 + ac1;
            uint32_t d0 = s0 + (SH_A0 + ar0 * 40 + ac0) * 2;
            uint32_t d1 = s0 + (SH_A0 + ar1 * 40 + ac1) * 2;
            CP16(d0, Ahi + ga0); CP16(d1, Ahi + ga1);
            CP16(d0 + (SH_A1 - SH_A0) * 2, Alo + ga0);
            CP16(d1 + (SH_A1 - SH_A0) * 2, Alo + ga1);
        }
        {
            size_t gb0 = (size_t)(k0 + br0) * ldb + bx * 128 + bc0;
            size_t gb1 = (size_t)(k0 + br1) * ldb + bx * 128 + bc1;
            uint32_t d0 = s0 + (SH_B0 + br0 * 136 + bc0) * 2;
            uint32_t d1 = s0 + (SH_B0 + br1 * 136 + bc1) * 2;
            CP16(d0, Bhi + gb0); CP16(d1, Bhi + gb1);
            CP16(d0 + (SH_B1 - SH_B0) * 2, Blo + gb0);
            CP16(d1 + (SH_B1 - SH_B0) * 2, Blo + gb1);
        }
        CP_COMMIT();
    };

    int nch = K >> 5;
    load_stage(0, 0);
    load_stage(1, 1);
    int stg = 0;   // stage of chunk c
    for (int c = 0; c < nch; c++) {
        if (c + 2 < nch) {
            int s2 = stg + 2; if (s2 >= 3) s2 -= 3;
            load_stage(c + 2, s2);
            CP_WAIT2();
        } else if (c + 1 < nch) { CP_WAIT1(); }
        else                    { CP_WAIT0(); }
        __syncthreads();
        uint32_t s0 = sbase + (uint32_t)(stg * SH_STG) * 2;
#pragma unroll
        for (int ks = 0; ks < 2; ks++) {
            uint32_t ah[2][4], al[2][4];
#pragma unroll
            for (int mt = 0; mt < 2; mt++) {
                int row = wm * 32 + mt * 16 + (lane & 15);
                int col = ks * 16 + (lane >> 4) * 8;
                uint32_t a = s0 + (uint32_t)(SH_A0 + row * 40 + col) * 2;
                ldsm4(ah[mt], a);
                ldsm4(al[mt], a + (SH_A1 - SH_A0) * 2);
            }
#pragma unroll
            for (int nt2 = 0; nt2 < 4; nt2++) {
                uint32_t bh[4], bl[4];
                int krow = ks * 16 + (lane & 15);
                int ncol = wn * 64 + nt2 * 16 + (lane >> 4) * 8;
                uint32_t a = s0 + (uint32_t)(SH_B0 + krow * 136 + ncol) * 2;
                ldsm4t(bh, a);
                ldsm4t(bl, a + (SH_B1 - SH_B0) * 2);
#pragma unroll
                for (int p = 0; p < 2; p++) {
                    int nt = nt2 * 2 + p;
#pragma unroll
                    for (int mt = 0; mt < 2; mt++) {
                        mma_bf16(acc[mt][nt], ah[mt], bh[2 * p], bh[2 * p + 1]);
                        mma_bf16(acc[mt][nt], ah[mt], bl[2 * p], bl[2 * p + 1]);
                        mma_bf16(acc[mt][nt], al[mt], bh[2 * p], bh[2 * p + 1]);
                    }
                }
            }
        }
        __syncthreads();
        if (++stg == 3) stg = 0;
    }

#pragma unroll
    for (int mt = 0; mt < 2; mt++) {
#pragma unroll
        for (int nt = 0; nt < 8; nt++) {
            int r  = by * 128 + wm * 32 + mt * 16 + (lane >> 2);
            int cc = bx * 128 + wn * 64 + nt * 8 + (lane & 3) * 2;
            *(float2*)&C[(size_t)r * ldc + cc] =
                make_float2(acc[mt][nt][0], acc[mt][nt][1]);
            *(float2*)&C[(size_t)(r + 8) * ldc + cc] =
                make_float2(acc[mt][nt][2], acc[mt][nt][3]);
        }
    }
}

// ---------------- T5 bidirectional relative bucket ----------------
__device__ __forceinline__ int rel_bucket(int rp) {
    int rb = (rp > 0) ? (NBUCK / 2) : 0;
    int a  = rp < 0 ? -rp : rp;
    if (a < 8) return rb + a;
    float rf = (float)a;
    int large = 8 + (int)(logf(rf * 0.125f) * (8.0f / 2.772588722239781f));
    if (large > 15) large = 15;
    return rb + large;
}

// ---------------- 1D bias tables ----------------
__global__ void k_pgtab(const float* __restrict__ relb, const float* __restrict__ grel) {
    int idx = blockIdx.x * 256 + threadIdx.x;
    if (idx >= HH * 512) return;
    int h = idx >> 9;
    int i = idx & 511;
    int rel = i - 255;
    int bk = rel_bucket(rel);
    g_pb[idx] = relb[bk * HH + h];
    g_gb[idx] = grel[bk * HH + h];
}

// ---------------- block ids / global segments ----------------
__global__ void k_block_ids(const int* __restrict__ mask) {
    int b = blockIdx.x;
    __shared__ int s_cnt, s_max;
    if (threadIdx.x == 0) { s_cnt = 0; s_max = -1; }
    __syncthreads();
    int lc = 0;
    for (int i = threadIdx.x; i < SS; i += blockDim.x)
        if (((i & (GG - 1)) == GG - 1) && mask[b * SS + i] != 0) lc++;
    atomicAdd(&s_cnt, lc);
    __syncthreads();
    int full = s_cnt - 1;
    int lm = -1;
    for (int i = threadIdx.x; i < SS; i += blockDim.x) {
        int id;
        if (mask[b * SS + i] != 0) { id = i / GG; if (id > full) id = full; }
        else id = -1;
        g_bid[b * SS + i] = id;
        if (id > lm) lm = id;
    }
    atomicMax(&s_max, lm);
    __syncthreads();
    for (int g = threadIdx.x; g < GLL; g += blockDim.x)
        g_gseg[b * GLL + g] = (g <= s_max) ? 1 : 0;
    if (threadIdx.x == 0) g_full[b] = full;
}

// ---------------- global aggregates + RMSNorm ----------------
__global__ void k_global_agg(const float* __restrict__ hs, const float* __restrict__ gln_w) {
    int g = blockIdx.x, b = blockIdx.y;
    int t = threadIdx.x;
    int full = g_full[b];
    float acc0 = 0.f, acc1 = 0.f, acc2 = 0.f, acc3 = 0.f;
    if (g <= full) {
        int s_begin = g * GG;
        int s_end   = (g == full) ? SS : (g + 1) * GG;
#pragma unroll 1
        for (int s = s_begin; s < s_end; s++) {
            if (g_bid[b * SS + s] == g) {
                const float* row = hs + ((size_t)(b * SS + s)) * DD;
                acc0 += row[t];
                acc1 += row[t + 256];
                acc2 += row[t + 512];
                acc3 += row[t + 768];
            }
        }
    }
    __shared__ float red[256];
    red[t] = acc0 * acc0 + acc1 * acc1 + acc2 * acc2 + acc3 * acc3;
    __syncthreads();
    for (int off = 128; off > 0; off >>= 1) {
        if (t < off) red[t] += red[t + off];
        __syncthreads();
    }
    float var = red[0] * (1.0f / (float)DD);
    float sc = rsqrtf(var + 1e-6f);
    float* out = g_gi + ((size_t)(b * GLL + g)) * DD;
    out[t]       = acc0 * sc * gln_w[t];
    out[t + 256] = acc1 * sc * gln_w[t + 256];
    out[t + 512] = acc2 * sc * gln_w[t + 512];
    out[t + 768] = acc3 * sc * gln_w[t + 768];
}

// ================= tensor-core attention (double-buffered cp.async K/V) =====
#define ATT_QHI  0
#define ATT_QLO  18432
#define ATT_KV0  36864     // per-stage: KHI(18432) KLO VHI VLO ; stride 73728
#define ATT_PB   184320
#define ATT_GB   186368
#define ATT_KVAL 188416    // 2 x 128 ints
#define ATT_GSEG 189440    // 256 ints
#define ATT_SMEM 190464

__global__ __launch_bounds__(256, 1)
void k_attn(const int* __restrict__ mask) {
    extern __shared__ char sm[];
    uint32_t sbase = smem_u32(sm);
    int h = blockIdx.x, n = blockIdx.y, b = blockIdx.z;
    int tid = threadIdx.x;
    int w = tid >> 5, lane = tid & 31;
    int g4 = lane >> 2, q4 = lane & 3;

    // ---- stage Q (bf16 hi/lo), tables, gseg (synchronous) ----
#pragma unroll
    for (int i = 0; i < 8; i++) {
        int f4 = i * 256 + tid;
        int row = f4 >> 4;
        int c4 = (f4 & 15) * 4;
        const float* qp = g_qkv + ((size_t)(b * SS + n * BLL + row)) * (3 * DD) + h * DKK + c4;
        float4 qv = *(const float4*)qp;
        uint2 qh, ql;
        split4(qv, qh, ql);
        uint32_t off = row * 144 + c4 * 2;
        *(uint2*)(sm + ATT_QHI + off) = qh;
        *(uint2*)(sm + ATT_QLO + off) = ql;
    }
    ((float*)(sm + ATT_PB))[tid]       = g_pb[h * 512 + tid];
    ((float*)(sm + ATT_PB))[tid + 256] = g_pb[h * 512 + tid + 256];
    ((float*)(sm + ATT_GB))[tid]       = g_gb[h * 512 + tid];
    ((float*)(sm + ATT_GB))[tid + 256] = g_gb[h * 512 + tid + 256];
    ((int*)(sm + ATT_GSEG))[tid]       = g_gseg[b * GLL + tid];

    int r0  = w * 16 + g4;
    int sq0 = n * BLL + r0;
    int mq0 = mask[b * SS + sq0], mq1 = mask[b * SS + sq0 + 8];
    int bid0 = g_bid[b * SS + sq0], bid1 = g_bid[b * SS + sq0 + 8];

    const float* pb_s   = (const float*)(sm + ATT_PB);
    const float* gb_s   = (const float*)(sm + ATT_GB);
    const int*   kval_s = (const int*)(sm + ATT_KVAL);
    const int*   gseg_s = (const int*)(sm + ATT_GSEG);

    // ---- cp.async staging of pre-split K/V chunks ----
    auto stage = [&](int c, int buf) {
        uint32_t sb = sbase + ATT_KV0 + (uint32_t)buf * 73728;
#pragma unroll
        for (int i = 0; i < 4; i++) {
            int seg = i * 256 + tid;        // 0..1023
            int row = seg >> 3;
            int s8  = (seg & 7) * 8;
            int srcrow;
            if (c < 3) {
                int t = (n - 1 + c) * BLL + row;
                srcrow = min(max(t, 0), SS - 1);
            } else {
                srcrow = SS + (c - 3) * BLL + row;
            }
            size_t goff = ((size_t)(b * SROW + srcrow)) * DD + h * DKK + s8;
            uint32_t soff = row * 144 + s8 * 2;
            CP16(sb + soff,         g_kat_hi + goff);
            CP16(sb + 18432 + soff, g_kat_lo + goff);
            CP16(sb + 36864 + soff, g_vat_hi + goff);
            CP16(sb + 55296 + soff, g_vat_lo + goff);
        }
        if (c < 3 && tid < BLL) {
            int t = (n - 1 + c) * BLL + tid;
            ((int*)(sm + ATT_KVAL))[buf * 128 + tid] = (t >= 0 && t < SS) ? mask[b * SS + t] : 0;
        }
        CP_COMMIT();
    };

    float o[8][4];
#pragma unroll
    for (int nt = 0; nt < 8; nt++)
#pragma unroll
        for (int j = 0; j < 4; j++) o[nt][j] = 0.f;
    float m0 = -1e30f, m1 = -1e30f, l0 = 0.f, l1 = 0.f;

    stage(0, 0);
    for (int c = 0; c < 5; c++) {
        int buf = c & 1;
        __syncthreads();   // prior compute done before overwriting its buffer
        if (c + 1 < 5) { stage(c + 1, (c + 1) & 1); CP_WAIT1(); }
        else           { CP_WAIT0(); }
        __syncthreads();

        uint32_t kb = sbase + ATT_KV0 + (uint32_t)buf * 73728;

        // ---- S = Q K^T (3-term bf16 split) ----
        float s[16][4];
#pragma unroll
        for (int nt = 0; nt < 16; nt++)
#pragma unroll
            for (int j = 0; j < 4; j++) s[nt][j] = 0.f;

#pragma unroll
        for (int kt = 0; kt < 4; kt++) {
            uint32_t qh[4], ql[4];
            uint32_t qa = sbase + ATT_QHI + (w * 16 + (lane & 15)) * 144
                        + (kt * 16 + (lane >> 4) * 8) * 2;
            ldsm4(qh, qa);
            ldsm4(ql, qa + (ATT_QLO - ATT_QHI));
#pragma unroll
            for (int nt2 = 0; nt2 < 8; nt2++) {
                uint32_t kh[4], kl[4];
                uint32_t ka = kb + (nt2 * 16 + (lane & 15)) * 144
                            + (kt * 16 + (lane >> 4) * 8) * 2;
                ldsm4(kh, ka);
                ldsm4(kl, ka + 18432);
                mma_bf16(s[2 * nt2],     qh, kh[0], kh[2]);
                mma_bf16(s[2 * nt2],     qh, kl[0], kl[2]);
                mma_bf16(s[2 * nt2],     ql, kh[0], kh[2]);
                mma_bf16(s[2 * nt2 + 1], qh, kh[1], kh[3]);
                mma_bf16(s[2 * nt2 + 1], qh, kl[1], kl[3]);
                mma_bf16(s[2 * nt2 + 1], ql, kh[1], kh[3]);
            }
        }

        // ---- bias + mask ----
#pragma unroll
        for (int nt = 0; nt < 16; nt++) {
            int cn = 8 * nt + 2 * q4;
            if (c < 3) {
                int kv0 = kval_s[buf * 128 + cn], kv1 = kval_s[buf * 128 + cn + 1];
                int rel0 = c * BLL + cn - BLL - r0;
                int rel1 = rel0 - 8;
                s[nt][0] += pb_s[rel0 + 255] +
                    ((mq0 && kv0 && rel0 > -BLL && rel0 < BLL) ? 0.f : NEGV);
                s[nt][1] += pb_s[rel0 + 256] +
                    ((mq0 && kv1 && rel0 + 1 > -BLL && rel0 + 1 < BLL) ? 0.f : NEGV);
                s[nt][2] += pb_s[rel1 + 255] +
                    ((mq1 && kv0 && rel1 > -BLL && rel1 < BLL) ? 0.f : NEGV);
                s[nt][3] += pb_s[rel1 + 256] +
                    ((mq1 && kv1 && rel1 + 1 > -BLL && rel1 + 1 < BLL) ? 0.f : NEGV);
            } else {
                int g0 = (c - 3) * BLL + cn;
                int gs0 = gseg_s[g0], gs1 = gseg_s[g0 + 1];
                int sp0 = g0 - bid0, sp1 = g0 - bid1;
                s[nt][0] += gb_s[sp0 + 255] + ((mq0 == gs0) ? 0.f : NEGV);
                s[nt][1] += gb_s[sp0 + 256] + ((mq0 == gs1) ? 0.f : NEGV);
                s[nt][2] += gb_s[sp1 + 255] + ((mq1 == gs0) ? 0.f : NEGV);
                s[nt][3] += gb_s[sp1 + 256] + ((mq1 == gs1) ? 0.f : NEGV);
            }
        }

        // ---- online softmax ----
        float mx0 = -1e30f, mx1 = -1e30f;
#pragma unroll
        for (int nt = 0; nt < 16; nt++) {
            mx0 = fmaxf(mx0, fmaxf(s[nt][0], s[nt][1]));
            mx1 = fmaxf(mx1, fmaxf(s[nt][2], s[nt][3]));
        }
        mx0 = fmaxf(mx0, __shfl_xor_sync(0xFFFFFFFF, mx0, 1));
        mx0 = fmaxf(mx0, __shfl_xor_sync(0xFFFFFFFF, mx0, 2));
        mx1 = fmaxf(mx1, __shfl_xor_sync(0xFFFFFFFF, mx1, 1));
        mx1 = fmaxf(mx1, __shfl_xor_sync(0xFFFFFFFF, mx1, 2));
        float nm0 = fmaxf(m0, mx0), nm1 = fmaxf(m1, mx1);
        float rs0 = __expf(m0 - nm0), rs1 = __expf(m1 - nm1);
        m0 = nm0; m1 = nm1;

        float ps0 = 0.f, ps1 = 0.f;
#pragma unroll
        for (int nt = 0; nt < 16; nt++) {
            s[nt][0] = __expf(s[nt][0] - nm0); ps0 += s[nt][0];
            s[nt][1] = __expf(s[nt][1] - nm0); ps0 += s[nt][1];
            s[nt][2] = __expf(s[nt][2] - nm1); ps1 += s[nt][2];
            s[nt][3] = __expf(s[nt][3] - nm1); ps1 += s[nt][3];
        }
        ps0 += __shfl_xor_sync(0xFFFFFFFF, ps0, 1);
        ps0 += __shfl_xor_sync(0xFFFFFFFF, ps0, 2);
        ps1 += __shfl_xor_sync(0xFFFFFFFF, ps1, 1);
        ps1 += __shfl_xor_sync(0xFFFFFFFF, ps1, 2);
        l0 = l0 * rs0 + ps0;
        l1 = l1 * rs1 + ps1;

#pragma unroll
        for (int nt = 0; nt < 8; nt++) {
            o[nt][0] *= rs0; o[nt][1] *= rs0;
            o[nt][2] *= rs1; o[nt][3] *= rs1;
        }

        // ---- O += P V ----
#pragma unroll
        for (int kt = 0; kt < 8; kt++) {
            uint32_t ahi[4], alo[4];
            packhl(s[2 * kt][0],     s[2 * kt][1],     ahi[0], alo[0]);
            packhl(s[2 * kt][2],     s[2 * kt][3],     ahi[1], alo[1]);
            packhl(s[2 * kt + 1][0], s[2 * kt + 1][1], ahi[2], alo[2]);
            packhl(s[2 * kt + 1][2], s[2 * kt + 1][3], ahi[3], alo[3]);
#pragma unroll
            for (int nt2 = 0; nt2 < 4; nt2++) {
                uint32_t vh[4], vl[4];
                uint32_t va = kb + 36864 + (kt * 16 + (lane & 15)) * 144
                            + (nt2 * 16 + (lane >> 4) * 8) * 2;
                ldsm4t(vh, va);
                ldsm4t(vl, va + 18432);
                mma_bf16(o[2 * nt2],     ahi, vh[0], vh[1]);
                mma_bf16(o[2 * nt2],     ahi, vl[0], vl[1]);
                mma_bf16(o[2 * nt2],     alo, vh[0], vh[1]);
                mma_bf16(o[2 * nt2 + 1], ahi, vh[2], vh[3]);
                mma_bf16(o[2 * nt2 + 1], ahi, vl[2], vl[3]);
                mma_bf16(o[2 * nt2 + 1], alo, vh[2], vh[3]);
            }
        }
    }

    // ---- epilogue: write ctx as bf16 hi/lo directly ----
    float inv0 = 1.0f / l0, inv1 = 1.0f / l1;
    size_t co0 = ((size_t)(b * SS + sq0)) * DD + h * DKK;
    size_t co1 = ((size_t)(b * SS + sq0 + 8)) * DD + h * DKK;
#pragma unroll
    for (int nt = 0; nt < 8; nt++) {
        int cc = 8 * nt + 2 * q4;
        uint32_t hp, lp;
        packhl(o[nt][0] * inv0, o[nt][1] * inv0, hp, lp);
        *(uint32_t*)(g_ctx_hi + co0 + cc) = hp;
        *(uint32_t*)(g_ctx_lo + co0 + cc) = lp;
        packhl(o[nt][2] * inv1, o[nt][3] * inv1, hp, lp);
        *(uint32_t*)(g_ctx_hi + co1 + cc) = hp;
        *(uint32_t*)(g_ctx_lo + co1 + cc) = lp;
    }
}

// ---------------- launch ----------------
extern "C" void kernel_launch(void* const* d_in, const int* in_sizes, int n_in,
                              void* d_out, int out_size) {
    const float* hs   = (const float*)d_in[0];
    const float* Wq   = (const float*)d_in[1];
    const float* Wk   = (const float*)d_in[2];
    const float* Wv   = (const float*)d_in[3];
    const float* Wo   = (const float*)d_in[4];
    const float* relb = (const float*)d_in[5];
    const float* grel = (const float*)d_in[6];
    const float* gln  = (const float*)d_in[7];
    const int*   mask = (const int*)d_in[8];
    float* out = (float*)d_out;

    float *p_qkv, *p_skv, *p_gi;
    cudaGetSymbolAddress((void**)&p_qkv, g_qkv);
    cudaGetSymbolAddress((void**)&p_skv, g_skv);
    cudaGetSymbolAddress((void**)&p_gi,  g_gi);

    __nv_bfloat16 *hs_hi, *hs_lo, *ctx_hi, *ctx_lo, *gi_hi, *gi_lo;
    __nv_bfloat16 *wqkv_hi, *wqkv_lo, *wo_hi, *wo_lo;
    cudaGetSymbolAddress((void**)&hs_hi,   g_hs_hi);
    cudaGetSymbolAddress((void**)&hs_lo,   g_hs_lo);
    cudaGetSymbolAddress((void**)&ctx_hi,  g_ctx_hi);
    cudaGetSymbolAddress((void**)&ctx_lo,  g_ctx_lo);
    cudaGetSymbolAddress((void**)&gi_hi,   g_gi_hi);
    cudaGetSymbolAddress((void**)&gi_lo,   g_gi_lo);
    cudaGetSymbolAddress((void**)&wqkv_hi, g_wqkv_hi);
    cudaGetSymbolAddress((void**)&wqkv_lo, g_wqkv_lo);
    cudaGetSymbolAddress((void**)&wo_hi,   g_wo_hi);
    cudaGetSymbolAddress((void**)&wo_lo,   g_wo_lo);

    cudaFuncSetAttribute(bgemm, cudaFuncAttributeMaxDynamicSharedMemorySize, BGE_SMEM_BYTES);
    cudaFuncSetAttribute(k_attn, cudaFuncAttributeMaxDynamicSharedMemorySize, ATT_SMEM);

    const int NHS4 = BB * SS * DD / 4;
    const int NW4  = DD * DD / 4;
    const int NGI4 = BB * GLL * DD / 4;
    const int NKV4 = BB * SROW * DD / 4;

    // #1..#3: prerequisites for the big QKV GEMM
    k_split_qkv<<<(3 * NW4 + 255) / 256, 256>>>((const float4*)Wq, (const float4*)Wk,
                                                (const float4*)Wv, (uint2*)wqkv_hi, (uint2*)wqkv_lo);
    k_split<<<(NHS4 + 255) / 256, 256>>>((const float4*)hs, (uint2*)hs_hi, (uint2*)hs_lo, NHS4);
    k_block_ids<<<BB, 256>>>(mask);

    // #4: fused QKV GEMM (profiled slot)
    bgemm<<<dim3(3 * DD / 128, (BB * SS) / 128), 256, BGE_SMEM_BYTES>>>(
        hs_hi, hs_lo, DD, wqkv_hi, wqkv_lo, 3 * DD, p_qkv, 3 * DD, DD);

    // global path
    k_global_agg<<<dim3(GLL, BB), 256>>>(hs, gln);
    k_split<<<(NGI4 + 255) / 256, 256>>>((const float4*)p_gi, (uint2*)gi_hi, (uint2*)gi_lo, NGI4);
    bgemm<<<dim3(2 * DD / 128, (BB * GLL) / 128), 256, BGE_SMEM_BYTES>>>(
        gi_hi, gi_lo, DD, wqkv_hi + DD, wqkv_lo + DD, 3 * DD, p_skv, 2 * DD, DD);

    // pre-split K/V for attention (local + side rows, unified layout)
    k_split_kv<<<(NKV4 + 255) / 256, 256>>>();

    // bias tables + Wo split
    k_pgtab<<<(HH * 512 + 255) / 256, 256>>>(relb, grel);
    k_split<<<(NW4 + 255) / 256, 256>>>((const float4*)Wo, (uint2*)wo_hi, (uint2*)wo_lo, NW4);

    // attention (tensor-core, async-staged)
    k_attn<<<dim3(HH, SS / BLL, BB), 256, ATT_SMEM>>>(mask);

    // output projection (reads ctx hi/lo written by attention)
    bgemm<<<dim3(DD / 128, (BB * SS) / 128), 256, BGE_SMEM_BYTES>>>(
        ctx_hi, ctx_lo, DD, wo_hi, wo_lo, DD, out, DD, DD);
}

// round 10
// speedup vs baseline: 1.4052x; 1.4052x over previous
#include <cuda_runtime.h>
#include <cuda_bf16.h>
#include <cuda_fp16.h>
#include <cstdint>
#include <math.h>

#define BB   2
#define SS   4096
#define DD   1024
#define HH   16
#define DKK  64
#define BLL  128
#define GG   16
#define GLL  256
#define NBUCK 32
#define NEGV (-1e10f)

// ---------------- scratch (device globals: allocation-free) ----------------
__device__ float g_qkv[BB*SS*3*DD];    // [row][q|k|v]
__device__ float g_skv[BB*GLL*2*DD];   // [row][sk|sv]
__device__ float g_gi [BB*GLL*DD];
__device__ float g_pb [HH*512];
__device__ float g_gb [HH*512];
__device__ int   g_bid [BB*SS];
__device__ int   g_gseg[BB*GLL];
__device__ int   g_full[BB];

// fp16 split buffers: activations hi/lo, weights single
__device__ __half g_hs_hi  [BB*SS*DD];
__device__ __half g_hs_lo  [BB*SS*DD];
__device__ __half g_ctx_hi [BB*SS*DD];
__device__ __half g_ctx_lo [BB*SS*DD];
__device__ __half g_gi_hi  [BB*GLL*DD];
__device__ __half g_gi_lo  [BB*GLL*DD];
__device__ __half g_wqkv   [DD*3*DD];   // [k][3*DD] interleaved q|k|v cols
__device__ __half g_wo     [DD*DD];

// ---------------- helpers ----------------
__device__ __forceinline__ uint32_t smem_u32(const void* p) {
    uint32_t a;
    asm("{ .reg .u64 t; cvta.to.shared.u64 t, %1; cvt.u32.u64 %0, t; }" : "=r"(a) : "l"(p));
    return a;
}

#define CP16(dst, src) asm volatile("cp.async.cg.shared.global [%0], [%1], 16;" :: "r"(dst), "l"(src) : "memory")
#define CP_COMMIT()    asm volatile("cp.async.commit_group;" ::: "memory")
#define CP_WAIT1()     asm volatile("cp.async.wait_group 1;" ::: "memory")
#define CP_WAIT0()     asm volatile("cp.async.wait_group 0;" ::: "memory")

__device__ __forceinline__ void ldsm4(uint32_t* r, uint32_t a) {
    asm volatile("ldmatrix.sync.aligned.m8n8.x4.shared.b16 {%0,%1,%2,%3}, [%4];"
        : "=r"(r[0]), "=r"(r[1]), "=r"(r[2]), "=r"(r[3]) : "r"(a));
}
__device__ __forceinline__ void ldsm4t(uint32_t* r, uint32_t a) {
    asm volatile("ldmatrix.sync.aligned.m8n8.x4.trans.shared.b16 {%0,%1,%2,%3}, [%4];"
        : "=r"(r[0]), "=r"(r[1]), "=r"(r[2]), "=r"(r[3]) : "r"(a));
}
__device__ __forceinline__ void mma_f16(float* d, const uint32_t* a, uint32_t b0, uint32_t b1) {
    asm volatile("mma.sync.aligned.m16n8k16.row.col.f32.f16.f16.f32 "
        "{%0,%1,%2,%3}, {%4,%5,%6,%7}, {%8,%9}, {%0,%1,%2,%3};"
        : "+f"(d[0]), "+f"(d[1]), "+f"(d[2]), "+f"(d[3])
        : "r"(a[0]), "r"(a[1]), "r"(a[2]), "r"(a[3]), "r"(b0), "r"(b1));
}

// fp32x4 -> fp16 hi (uint2 = 4 halves) + fp16 lo
__device__ __forceinline__ void split4h(float4 a, uint2& h, uint2& l) {
    __half2 h01 = __floats2half2_rn(a.x, a.y);
    __half2 h23 = __floats2half2_rn(a.z, a.w);
    float l0 = a.x - __half2float(__low2half(h01));
    float l1 = a.y - __half2float(__high2half(h01));
    float l2 = a.z - __half2float(__low2half(h23));
    float l3 = a.w - __half2float(__high2half(h23));
    __half2 q01 = __floats2half2_rn(l0, l1);
    __half2 q23 = __floats2half2_rn(l2, l3);
    h = make_uint2(*(uint32_t*)&h01, *(uint32_t*)&h23);
    l = make_uint2(*(uint32_t*)&q01, *(uint32_t*)&q23);
}

// fp32x4 -> fp16 single
__device__ __forceinline__ uint2 cvt4h(float4 a) {
    __half2 h01 = __floats2half2_rn(a.x, a.y);
    __half2 h23 = __floats2half2_rn(a.z, a.w);
    return make_uint2(*(uint32_t*)&h01, *(uint32_t*)&h23);
}

// two floats -> fp16 hi pair + lo pair (packed)
__device__ __forceinline__ void packhl_h(float a, float b, uint32_t& hp, uint32_t& lp) {
    __half2 hv = __floats2half2_rn(a, b);
    __half2 lv = __floats2half2_rn(a - __half2float(__low2half(hv)),
                                   b - __half2float(__high2half(hv)));
    hp = *(uint32_t*)&hv;
    lp = *(uint32_t*)&lv;
}

// ---------------- fp32 -> fp16 hi/lo split (activations) ----------------
__global__ void k_split(const float4* __restrict__ src,
                        uint2* __restrict__ hi, uint2* __restrict__ lo, int n4) {
    int i = blockIdx.x * 256 + threadIdx.x;
    if (i >= n4) return;
    uint2 h, l;
    split4h(src[i], h, l);
    hi[i] = h; lo[i] = l;
}

// ---- weight conversions (single fp16) ----
__global__ void k_cvt_w(const float4* __restrict__ src, uint2* __restrict__ dst, int n4) {
    int i = blockIdx.x * 256 + threadIdx.x;
    if (i >= n4) return;
    dst[i] = cvt4h(src[i]);
}

__global__ void k_cvt_qkvw(const float4* __restrict__ Wq, const float4* __restrict__ Wk,
                           const float4* __restrict__ Wv, uint2* __restrict__ dst) {
    const int NW4 = DD * DD / 4;
    int idx = blockIdx.x * 256 + threadIdx.x;
    if (idx >= 3 * NW4) return;
    int i = idx / NW4;
    int r = idx % NW4;
    int k  = r >> 8;
    int n4 = r & 255;
    const float4* src = (i == 0) ? Wq : (i == 1) ? Wk : Wv;
    dst[k * (3 * DD / 4) + i * (DD / 4) + n4] = cvt4h(src[r]);
}

// ============ fp16 2-term GEMM: C = (Ahi+Alo)[.,K](lda) @ Bh[K,.](ldb) ======
// smem halves per stage: Ahi[128*40] Alo[128*40] B[32*136]
#define SH_A0   0
#define SH_A1   5120
#define SH_B0   10240
#define SH_STG  14592
#define BGE_SMEM_BYTES (3 * SH_STG * 2)

__global__ __launch_bounds__(256, 2)
void bgemm(const __half* __restrict__ Ahi, const __half* __restrict__ Alo, int lda,
           const __half* __restrict__ Bh, int ldb,
           float* __restrict__ C, int ldc, int K) {
    extern __shared__ __half sh[];
    uint32_t sbase = smem_u32(sh);

    int tid = threadIdx.x;
    int wid = tid >> 5, lane = tid & 31;
    int wm = wid & 3, wn = wid >> 2;
    int bx = blockIdx.x, by = blockIdx.y;

    float acc[2][8][4];
#pragma unroll
    for (int mt = 0; mt < 2; mt++)
#pragma unroll
        for (int nt = 0; nt < 8; nt++)
#pragma unroll
            for (int j = 0; j < 4; j++) acc[mt][nt][j] = 0.f;

    int ar0 = tid >> 2,          ac0 = (tid & 3) * 8;
    int ar1 = (tid + 256) >> 2,  ac1 = ((tid + 256) & 3) * 8;
    int br0 = tid >> 4,          bc0 = (tid & 15) * 8;
    int br1 = (tid + 256) >> 4,  bc1 = ((tid + 256) & 15) * 8;

    auto load_stage = [&](int c, int stage) {
        int k0 = c * 32;
        uint32_t s0 = sbase + (uint32_t)(stage * SH_STG) * 2;
        size_t ga0 = (size_t)(by * 128 + ar0) * lda + k0 + ac0;
        size_t ga1 = (size_t)(by * 128 + ar1) * lda + k0 + ac1;
        uint32_t d0 = s0 + (SH_A0 + ar0 * 40 + ac0) * 2;
        uint32_t d1 = s0 + (SH_A0 + ar1 * 40 + ac1) * 2;
        CP16(d0, Ahi + ga0); CP16(d1, Ahi + ga1);
        CP16(d0 + (SH_A1 - SH_A0) * 2, Alo + ga0);
        CP16(d1 + (SH_A1 - SH_A0) * 2, Alo + ga1);
        size_t gb0 = (size_t)(k0 + br0) * ldb + bx * 128 + bc0;
        size_t gb1 = (size_t)(k0 + br1) * ldb + bx * 128 + bc1;
        CP16(s0 + (SH_B0 + br0 * 136 + bc0) * 2, Bh + gb0);
        CP16(s0 + (SH_B0 + br1 * 136 + bc1) * 2, Bh + gb1);
        CP_COMMIT();
    };

    int nch = K >> 5;
    load_stage(0, 0);
    load_stage(1, 1);
    int stg = 0;
    for (int c = 0; c < nch; c++) {
        if (c + 1 < nch) { CP_WAIT1(); } else { CP_WAIT0(); }
        __syncthreads();   // stage stg data visible to all warps; prev compute retired
        if (c + 2 < nch) {
            int s2 = stg + 2; if (s2 >= 3) s2 -= 3;
            load_stage(c + 2, s2);
        }
        uint32_t s0 = sbase + (uint32_t)(stg * SH_STG) * 2;
#pragma unroll
        for (int ks = 0; ks < 2; ks++) {
            uint32_t ah[2][4], al[2][4];
#pragma unroll
            for (int mt = 0; mt < 2; mt++) {
                int row = wm * 32 + mt * 16 + (lane & 15);
                int col = ks * 16 + (lane >> 4) * 8;
                uint32_t a = s0 + (uint32_t)(SH_A0 + row * 40 + col) * 2;
                ldsm4(ah[mt], a);
                ldsm4(al[mt], a + (SH_A1 - SH_A0) * 2);
            }
#pragma unroll
            for (int nt2 = 0; nt2 < 4; nt2++) {
                uint32_t bh[4];
                int krow = ks * 16 + (lane & 15);
                int ncol = wn * 64 + nt2 * 16 + (lane >> 4) * 8;
                ldsm4t(bh, s0 + (uint32_t)(SH_B0 + krow * 136 + ncol) * 2);
#pragma unroll
                for (int p = 0; p < 2; p++) {
                    int nt = nt2 * 2 + p;
#pragma unroll
                    for (int mt = 0; mt < 2; mt++) {
                        mma_f16(acc[mt][nt], ah[mt], bh[2 * p], bh[2 * p + 1]);
                        mma_f16(acc[mt][nt], al[mt], bh[2 * p], bh[2 * p + 1]);
                    }
                }
            }
        }
        if (++stg == 3) stg = 0;
    }
    __syncthreads();

#pragma unroll
    for (int mt = 0; mt < 2; mt++) {
#pragma unroll
        for (int nt = 0; nt < 8; nt++) {
            int r  = by * 128 + wm * 32 + mt * 16 + (lane >> 2);
            int cc = bx * 128 + wn * 64 + nt * 8 + (lane & 3) * 2;
            *(float2*)&C[(size_t)r * ldc + cc] =
                make_float2(acc[mt][nt][0], acc[mt][nt][1]);
            *(float2*)&C[(size_t)(r + 8) * ldc + cc] =
                make_float2(acc[mt][nt][2], acc[mt][nt][3]);
        }
    }
}

// ---------------- T5 bidirectional relative bucket ----------------
__device__ __forceinline__ int rel_bucket(int rp) {
    int rb = (rp > 0) ? (NBUCK / 2) : 0;
    int a  = rp < 0 ? -rp : rp;
    if (a < 8) return rb + a;
    float rf = (float)a;
    int large = 8 + (int)(logf(rf * 0.125f) * (8.0f / 2.772588722239781f));
    if (large > 15) large = 15;
    return rb + large;
}

// ---------------- 1D bias tables ----------------
__global__ void k_pgtab(const float* __restrict__ relb, const float* __restrict__ grel) {
    int idx = blockIdx.x * 256 + threadIdx.x;
    if (idx >= HH * 512) return;
    int h = idx >> 9;
    int i = idx & 511;
    int rel = i - 255;
    int bk = rel_bucket(rel);
    g_pb[idx] = relb[bk * HH + h];
    g_gb[idx] = grel[bk * HH + h];
}

// ---------------- block ids / global segments ----------------
__global__ void k_block_ids(const int* __restrict__ mask) {
    int b = blockIdx.x;
    __shared__ int s_cnt, s_max;
    if (threadIdx.x == 0) { s_cnt = 0; s_max = -1; }
    __syncthreads();
    int lc = 0;
    for (int i = threadIdx.x; i < SS; i += blockDim.x)
        if (((i & (GG - 1)) == GG - 1) && mask[b * SS + i] != 0) lc++;
    atomicAdd(&s_cnt, lc);
    __syncthreads();
    int full = s_cnt - 1;
    int lm = -1;
    for (int i = threadIdx.x; i < SS; i += blockDim.x) {
        int id;
        if (mask[b * SS + i] != 0) { id = i / GG; if (id > full) id = full; }
        else id = -1;
        g_bid[b * SS + i] = id;
        if (id > lm) lm = id;
    }
    atomicMax(&s_max, lm);
    __syncthreads();
    for (int g = threadIdx.x; g < GLL; g += blockDim.x)
        g_gseg[b * GLL + g] = (g <= s_max) ? 1 : 0;
    if (threadIdx.x == 0) g_full[b] = full;
}

// ---------------- global aggregates + RMSNorm ----------------
__global__ void k_global_agg(const float* __restrict__ hs, const float* __restrict__ gln_w) {
    int g = blockIdx.x, b = blockIdx.y;
    int t = threadIdx.x;
    int full = g_full[b];
    float acc0 = 0.f, acc1 = 0.f, acc2 = 0.f, acc3 = 0.f;
    if (g <= full) {
        int s_begin = g * GG;
        int s_end   = (g == full) ? SS : (g + 1) * GG;
#pragma unroll 1
        for (int s = s_begin; s < s_end; s++) {
            if (g_bid[b * SS + s] == g) {
                const float* row = hs + ((size_t)(b * SS + s)) * DD;
                acc0 += row[t];
                acc1 += row[t + 256];
                acc2 += row[t + 512];
                acc3 += row[t + 768];
            }
        }
    }
    __shared__ float red[256];
    red[t] = acc0 * acc0 + acc1 * acc1 + acc2 * acc2 + acc3 * acc3;
    __syncthreads();
    for (int off = 128; off > 0; off >>= 1) {
        if (t < off) red[t] += red[t + off];
        __syncthreads();
    }
    float var = red[0] * (1.0f / (float)DD);
    float sc = rsqrtf(var + 1e-6f);
    float* out = g_gi + ((size_t)(b * GLL + g)) * DD;
    out[t]       = acc0 * sc * gln_w[t];
    out[t + 256] = acc1 * sc * gln_w[t + 256];
    out[t + 512] = acc2 * sc * gln_w[t + 512];
    out[t + 768] = acc3 * sc * gln_w[t + 768];
}

// ================= tensor-core attention (fp16 2-term) =================
// Q: fp16 hi/lo; K,V: single fp16. one CTA per (h,n,b); 8 warps x 16 q rows.
#define ATT_QHI  0
#define ATT_QLO  18432
#define ATT_KH   36864
#define ATT_VH   55296
#define ATT_PB   73728
#define ATT_GB   75776
#define ATT_KVAL 77824
#define ATT_GSEG 78336
#define ATT_SMEM 79360

__global__ __launch_bounds__(256, 1)
void k_attn(const int* __restrict__ mask) {
    extern __shared__ char sm[];
    uint32_t sbase = smem_u32(sm);
    int h = blockIdx.x, n = blockIdx.y, b = blockIdx.z;
    int tid = threadIdx.x;
    int w = tid >> 5, lane = tid & 31;
    int g4 = lane >> 2, q4 = lane & 3;

    // ---- stage Q (fp16 hi/lo), tables, gseg ----
#pragma unroll
    for (int i = 0; i < 8; i++) {
        int f4 = i * 256 + tid;
        int row = f4 >> 4;
        int c4 = (f4 & 15) * 4;
        const float* qp = g_qkv + ((size_t)(b * SS + n * BLL + row)) * (3 * DD) + h * DKK + c4;
        float4 qv = *(const float4*)qp;
        uint2 qh, ql;
        split4h(qv, qh, ql);
        uint32_t off = row * 144 + c4 * 2;
        *(uint2*)(sm + ATT_QHI + off) = qh;
        *(uint2*)(sm + ATT_QLO + off) = ql;
    }
    ((float*)(sm + ATT_PB))[tid]       = g_pb[h * 512 + tid];
    ((float*)(sm + ATT_PB))[tid + 256] = g_pb[h * 512 + tid + 256];
    ((float*)(sm + ATT_GB))[tid]       = g_gb[h * 512 + tid];
    ((float*)(sm + ATT_GB))[tid + 256] = g_gb[h * 512 + tid + 256];
    ((int*)(sm + ATT_GSEG))[tid]       = g_gseg[b * GLL + tid];

    int r0  = w * 16 + g4;
    int sq0 = n * BLL + r0;
    int mq0 = mask[b * SS + sq0], mq1 = mask[b * SS + sq0 + 8];
    int bid0 = g_bid[b * SS + sq0], bid1 = g_bid[b * SS + sq0 + 8];

    const float* pb_s   = (const float*)(sm + ATT_PB);
    const float* gb_s   = (const float*)(sm + ATT_GB);
    const int*   kval_s = (const int*)(sm + ATT_KVAL);
    const int*   gseg_s = (const int*)(sm + ATT_GSEG);

    float o[8][4];
#pragma unroll
    for (int nt = 0; nt < 8; nt++)
#pragma unroll
        for (int j = 0; j < 4; j++) o[nt][j] = 0.f;
    float m0 = -1e30f, m1 = -1e30f, l0 = 0.f, l1 = 0.f;

    for (int c = 0; c < 5; c++) {
        __syncthreads();   // previous chunk's compute done before K/V overwrite
        // ---- stage K/V chunk (128 keys) as single fp16 ----
#pragma unroll
        for (int i = 0; i < 8; i++) {
            int f4 = i * 256 + tid;
            int row = f4 >> 4;
            int c4 = (f4 & 15) * 4;
            const float *kp, *vp;
            if (c < 3) {
                int t = (n - 1 + c) * BLL + row;
                int tc = min(max(t, 0), SS - 1);
                const float* base = g_qkv + ((size_t)(b * SS + tc)) * (3 * DD) + h * DKK + c4;
                kp = base + DD; vp = base + 2 * DD;
            } else {
                int gI = (c - 3) * BLL + row;
                const float* base = g_skv + ((size_t)(b * GLL + gI)) * (2 * DD) + h * DKK + c4;
                kp = base; vp = base + DD;
            }
            uint32_t off = row * 144 + c4 * 2;
            *(uint2*)(sm + ATT_KH + off) = cvt4h(*(const float4*)kp);
            *(uint2*)(sm + ATT_VH + off) = cvt4h(*(const float4*)vp);
        }
        if (c < 3 && tid < BLL) {
            int t = (n - 1 + c) * BLL + tid;
            ((int*)(sm + ATT_KVAL))[tid] = (t >= 0 && t < SS) ? mask[b * SS + t] : 0;
        }
        __syncthreads();

        // ---- S = Q K^T (2-term fp16) ----
        float s[16][4];
#pragma unroll
        for (int nt = 0; nt < 16; nt++)
#pragma unroll
            for (int j = 0; j < 4; j++) s[nt][j] = 0.f;

#pragma unroll
        for (int kt = 0; kt < 4; kt++) {
            uint32_t qh[4], ql[4];
            uint32_t qa = sbase + ATT_QHI + (w * 16 + (lane & 15)) * 144
                        + (kt * 16 + (lane >> 4) * 8) * 2;
            ldsm4(qh, qa);
            ldsm4(ql, qa + (ATT_QLO - ATT_QHI));
#pragma unroll
            for (int nt2 = 0; nt2 < 8; nt2++) {
                uint32_t kh[4];
                uint32_t ka = sbase + ATT_KH + (nt2 * 16 + (lane & 15)) * 144
                            + (kt * 16 + (lane >> 4) * 8) * 2;
                ldsm4(kh, ka);
                mma_f16(s[2 * nt2],     qh, kh[0], kh[2]);
                mma_f16(s[2 * nt2],     ql, kh[0], kh[2]);
                mma_f16(s[2 * nt2 + 1], qh, kh[1], kh[3]);
                mma_f16(s[2 * nt2 + 1], ql, kh[1], kh[3]);
            }
        }

        // ---- bias + mask ----
#pragma unroll
        for (int nt = 0; nt < 16; nt++) {
            int cn = 8 * nt + 2 * q4;
            if (c < 3) {
                int kv0 = kval_s[cn], kv1 = kval_s[cn + 1];
                int rel0 = c * BLL + cn - BLL - r0;
                int rel1 = rel0 - 8;
                s[nt][0] += pb_s[rel0 + 255] +
                    ((mq0 && kv0 && rel0 > -BLL && rel0 < BLL) ? 0.f : NEGV);
                s[nt][1] += pb_s[rel0 + 256] +
                    ((mq0 && kv1 && rel0 + 1 > -BLL && rel0 + 1 < BLL) ? 0.f : NEGV);
                s[nt][2] += pb_s[rel1 + 255] +
                    ((mq1 && kv0 && rel1 > -BLL && rel1 < BLL) ? 0.f : NEGV);
                s[nt][3] += pb_s[rel1 + 256] +
                    ((mq1 && kv1 && rel1 + 1 > -BLL && rel1 + 1 < BLL) ? 0.f : NEGV);
            } else {
                int g0 = (c - 3) * BLL + cn;
                int gs0 = gseg_s[g0], gs1 = gseg_s[g0 + 1];
                int sp0 = g0 - bid0, sp1 = g0 - bid1;
                s[nt][0] += gb_s[sp0 + 255] + ((mq0 == gs0) ? 0.f : NEGV);
                s[nt][1] += gb_s[sp0 + 256] + ((mq0 == gs1) ? 0.f : NEGV);
                s[nt][2] += gb_s[sp1 + 255] + ((mq1 == gs0) ? 0.f : NEGV);
                s[nt][3] += gb_s[sp1 + 256] + ((mq1 == gs1) ? 0.f : NEGV);
            }
        }

        // ---- online softmax ----
        float mx0 = -1e30f, mx1 = -1e30f;
#pragma unroll
        for (int nt = 0; nt < 16; nt++) {
            mx0 = fmaxf(mx0, fmaxf(s[nt][0], s[nt][1]));
            mx1 = fmaxf(mx1, fmaxf(s[nt][2], s[nt][3]));
        }
        mx0 = fmaxf(mx0, __shfl_xor_sync(0xFFFFFFFF, mx0, 1));
        mx0 = fmaxf(mx0, __shfl_xor_sync(0xFFFFFFFF, mx0, 2));
        mx1 = fmaxf(mx1, __shfl_xor_sync(0xFFFFFFFF, mx1, 1));
        mx1 = fmaxf(mx1, __shfl_xor_sync(0xFFFFFFFF, mx1, 2));
        float nm0 = fmaxf(m0, mx0), nm1 = fmaxf(m1, mx1);
        float rs0 = __expf(m0 - nm0), rs1 = __expf(m1 - nm1);
        m0 = nm0; m1 = nm1;

        float ps0 = 0.f, ps1 = 0.f;
#pragma unroll
        for (int nt = 0; nt < 16; nt++) {
            s[nt][0] = __expf(s[nt][0] - nm0); ps0 += s[nt][0];
            s[nt][1] = __expf(s[nt][1] - nm0); ps0 += s[nt][1];
            s[nt][2] = __expf(s[nt][2] - nm1); ps1 += s[nt][2];
            s[nt][3] = __expf(s[nt][3] - nm1); ps1 += s[nt][3];
        }
        ps0 += __shfl_xor_sync(0xFFFFFFFF, ps0, 1);
        ps0 += __shfl_xor_sync(0xFFFFFFFF, ps0, 2);
        ps1 += __shfl_xor_sync(0xFFFFFFFF, ps1, 1);
        ps1 += __shfl_xor_sync(0xFFFFFFFF, ps1, 2);
        l0 = l0 * rs0 + ps0;
        l1 = l1 * rs1 + ps1;

#pragma unroll
        for (int nt = 0; nt < 8; nt++) {
            o[nt][0] *= rs0; o[nt][1] *= rs0;
            o[nt][2] *= rs1; o[nt][3] *= rs1;
        }

        // ---- O += P V (P 2-term fp16; V single) ----
#pragma unroll
        for (int kt = 0; kt < 8; kt++) {
            uint32_t phi[4], plo[4];
            packhl_h(s[2 * kt][0],     s[2 * kt][1],     phi[0], plo[0]);
            packhl_h(s[2 * kt][2],     s[2 * kt][3],     phi[1], plo[1]);
            packhl_h(s[2 * kt + 1][0], s[2 * kt + 1][1], phi[2], plo[2]);
            packhl_h(s[2 * kt + 1][2], s[2 * kt + 1][3], phi[3], plo[3]);
#pragma unroll
            for (int nt2 = 0; nt2 < 4; nt2++) {
                uint32_t vh[4];
                uint32_t va = sbase + ATT_VH + (kt * 16 + (lane & 15)) * 144
                            + (nt2 * 16 + (lane >> 4) * 8) * 2;
                ldsm4t(vh, va);
                mma_f16(o[2 * nt2],     phi, vh[0], vh[1]);
                mma_f16(o[2 * nt2],     plo, vh[0], vh[1]);
                mma_f16(o[2 * nt2 + 1], phi, vh[2], vh[3]);
                mma_f16(o[2 * nt2 + 1], plo, vh[2], vh[3]);
            }
        }
    }

    // ---- epilogue: write ctx as fp16 hi/lo directly ----
    float inv0 = 1.0f / l0, inv1 = 1.0f / l1;
    size_t co0 = ((size_t)(b * SS + sq0)) * DD + h * DKK;
    size_t co1 = ((size_t)(b * SS + sq0 + 8)) * DD + h * DKK;
#pragma unroll
    for (int nt = 0; nt < 8; nt++) {
        int cc = 8 * nt + 2 * q4;
        uint32_t hp, lp;
        packhl_h(o[nt][0] * inv0, o[nt][1] * inv0, hp, lp);
        *(uint32_t*)(g_ctx_hi + co0 + cc) = hp;
        *(uint32_t*)(g_ctx_lo + co0 + cc) = lp;
        packhl_h(o[nt][2] * inv1, o[nt][3] * inv1, hp, lp);
        *(uint32_t*)(g_ctx_hi + co1 + cc) = hp;
        *(uint32_t*)(g_ctx_lo + co1 + cc) = lp;
    }
}

// ---------------- launch ----------------
extern "C" void kernel_launch(void* const* d_in, const int* in_sizes, int n_in,
                              void* d_out, int out_size) {
    const float* hs   = (const float*)d_in[0];
    const float* Wq   = (const float*)d_in[1];
    const float* Wk   = (const float*)d_in[2];
    const float* Wv   = (const float*)d_in[3];
    const float* Wo   = (const float*)d_in[4];
    const float* relb = (const float*)d_in[5];
    const float* grel = (const float*)d_in[6];
    const float* gln  = (const float*)d_in[7];
    const int*   mask = (const int*)d_in[8];
    float* out = (float*)d_out;

    float *p_qkv, *p_skv, *p_gi;
    cudaGetSymbolAddress((void**)&p_qkv, g_qkv);
    cudaGetSymbolAddress((void**)&p_skv, g_skv);
    cudaGetSymbolAddress((void**)&p_gi,  g_gi);

    __half *hs_hi, *hs_lo, *ctx_hi, *ctx_lo, *gi_hi, *gi_lo, *wqkv, *wo;
    cudaGetSymbolAddress((void**)&hs_hi,  g_hs_hi);
    cudaGetSymbolAddress((void**)&hs_lo,  g_hs_lo);
    cudaGetSymbolAddress((void**)&ctx_hi, g_ctx_hi);
    cudaGetSymbolAddress((void**)&ctx_lo, g_ctx_lo);
    cudaGetSymbolAddress((void**)&gi_hi,  g_gi_hi);
    cudaGetSymbolAddress((void**)&gi_lo,  g_gi_lo);
    cudaGetSymbolAddress((void**)&wqkv,   g_wqkv);
    cudaGetSymbolAddress((void**)&wo,     g_wo);

    cudaFuncSetAttribute(bgemm, cudaFuncAttributeMaxDynamicSharedMemorySize, BGE_SMEM_BYTES);
    cudaFuncSetAttribute(k_attn, cudaFuncAttributeMaxDynamicSharedMemorySize, ATT_SMEM);

    const int NHS4 = BB * SS * DD / 4;
    const int NW4  = DD * DD / 4;
    const int NGI4 = BB * GLL * DD / 4;

    // #1..#3: prerequisites for the big QKV GEMM
    k_cvt_qkvw<<<(3 * NW4 + 255) / 256, 256>>>((const float4*)Wq, (const float4*)Wk,
                                               (const float4*)Wv, (uint2*)wqkv);
    k_split<<<(NHS4 + 255) / 256, 256>>>((const float4*)hs, (uint2*)hs_hi, (uint2*)hs_lo, NHS4);
    k_block_ids<<<BB, 256>>>(mask);

    // #4: fused QKV GEMM (profiled slot)
    bgemm<<<dim3(3 * DD / 128, (BB * SS) / 128), 256, BGE_SMEM_BYTES>>>(
        hs_hi, hs_lo, DD, wqkv, 3 * DD, p_qkv, 3 * DD, DD);

    // global path
    k_global_agg<<<dim3(GLL, BB), 256>>>(hs, gln);
    k_split<<<(NGI4 + 255) / 256, 256>>>((const float4*)p_gi, (uint2*)gi_hi, (uint2*)gi_lo, NGI4);
    bgemm<<<dim3(2 * DD / 128, (BB * GLL) / 128), 256, BGE_SMEM_BYTES>>>(
        gi_hi, gi_lo, DD, wqkv + DD, 3 * DD, p_skv, 2 * DD, DD);

    // bias tables + Wo convert
    k_pgtab<<<(HH * 512 + 255) / 256, 256>>>(relb, grel);
    k_cvt_w<<<(NW4 + 255) / 256, 256>>>((const float4*)Wo, (uint2*)wo, NW4);

    // attention (tensor-core, fp16 2-term)
    k_attn<<<dim3(HH, SS / BLL, BB), 256, ATT_SMEM>>>(mask);

    // output projection (reads ctx hi/lo written by attention)
    bgemm<<<dim3(DD / 128, (BB * SS) / 128), 256, BGE_SMEM_BYTES>>>(
        ctx_hi, ctx_lo, DD, wo, DD, out, DD, DD);
}

// round 11
// speedup vs baseline: 1.4519x; 1.0332x over previous
#include <cuda_runtime.h>
#include <cuda_bf16.h>
#include <cuda_fp16.h>
#include <cstdint>
#include <math.h>

#define BB   2
#define SS   4096
#define DD   1024
#define HH   16
#define DKK  64
#define BLL  128
#define GG   16
#define GLL  256
#define NBUCK 32
#define NEGV (-1e10f)

// ---------------- scratch (device globals: allocation-free) ----------------
__device__ float g_qkv[BB*SS*3*DD];    // [row][q|k|v]
__device__ float g_skv[BB*GLL*2*DD];   // [row][sk|sv]
__device__ float g_gi [BB*GLL*DD];
__device__ float g_pb [HH*512];
__device__ float g_gb [HH*512];
__device__ int   g_bid [BB*SS];
__device__ int   g_gseg[BB*GLL];
__device__ int   g_full[BB];

// fp16 split buffers: activations hi/lo, weights single
__device__ __half g_hs_hi  [BB*SS*DD];
__device__ __half g_hs_lo  [BB*SS*DD];
__device__ __half g_ctx_hi [BB*SS*DD];
__device__ __half g_ctx_lo [BB*SS*DD];
__device__ __half g_gi_hi  [BB*GLL*DD];
__device__ __half g_gi_lo  [BB*GLL*DD];
__device__ __half g_wqkv   [DD*3*DD];   // [k][3*DD] interleaved q|k|v cols
__device__ __half g_wo     [DD*DD];

// ---------------- helpers ----------------
__device__ __forceinline__ uint32_t smem_u32(const void* p) {
    uint32_t a;
    asm("{ .reg .u64 t; cvta.to.shared.u64 t, %1; cvt.u32.u64 %0, t; }" : "=r"(a) : "l"(p));
    return a;
}

#define CP16(dst, src) asm volatile("cp.async.cg.shared.global [%0], [%1], 16;" :: "r"(dst), "l"(src) : "memory")
#define CP_COMMIT()    asm volatile("cp.async.commit_group;" ::: "memory")
#define CP_WAIT0()     asm volatile("cp.async.wait_group 0;" ::: "memory")

__device__ __forceinline__ void ldsm4(uint32_t* r, uint32_t a) {
    asm volatile("ldmatrix.sync.aligned.m8n8.x4.shared.b16 {%0,%1,%2,%3}, [%4];"
        : "=r"(r[0]), "=r"(r[1]), "=r"(r[2]), "=r"(r[3]) : "r"(a));
}
__device__ __forceinline__ void ldsm4t(uint32_t* r, uint32_t a) {
    asm volatile("ldmatrix.sync.aligned.m8n8.x4.trans.shared.b16 {%0,%1,%2,%3}, [%4];"
        : "=r"(r[0]), "=r"(r[1]), "=r"(r[2]), "=r"(r[3]) : "r"(a));
}
__device__ __forceinline__ void mma_f16(float* d, const uint32_t* a, uint32_t b0, uint32_t b1) {
    asm volatile("mma.sync.aligned.m16n8k16.row.col.f32.f16.f16.f32 "
        "{%0,%1,%2,%3}, {%4,%5,%6,%7}, {%8,%9}, {%0,%1,%2,%3};"
        : "+f"(d[0]), "+f"(d[1]), "+f"(d[2]), "+f"(d[3])
        : "r"(a[0]), "r"(a[1]), "r"(a[2]), "r"(a[3]), "r"(b0), "r"(b1));
}

// fp32x4 -> fp16 hi (uint2 = 4 halves) + fp16 lo
__device__ __forceinline__ void split4h(float4 a, uint2& h, uint2& l) {
    __half2 h01 = __floats2half2_rn(a.x, a.y);
    __half2 h23 = __floats2half2_rn(a.z, a.w);
    float l0 = a.x - __half2float(__low2half(h01));
    float l1 = a.y - __half2float(__high2half(h01));
    float l2 = a.z - __half2float(__low2half(h23));
    float l3 = a.w - __half2float(__high2half(h23));
    __half2 q01 = __floats2half2_rn(l0, l1);
    __half2 q23 = __floats2half2_rn(l2, l3);
    h = make_uint2(*(uint32_t*)&h01, *(uint32_t*)&h23);
    l = make_uint2(*(uint32_t*)&q01, *(uint32_t*)&q23);
}

// fp32x4 -> fp16 single
__device__ __forceinline__ uint2 cvt4h(float4 a) {
    __half2 h01 = __floats2half2_rn(a.x, a.y);
    __half2 h23 = __floats2half2_rn(a.z, a.w);
    return make_uint2(*(uint32_t*)&h01, *(uint32_t*)&h23);
}

__device__ __forceinline__ void packhl_h(float a, float b, uint32_t& hp, uint32_t& lp) {
    __half2 hv = __floats2half2_rn(a, b);
    __half2 lv = __floats2half2_rn(a - __half2float(__low2half(hv)),
                                   b - __half2float(__high2half(hv)));
    hp = *(uint32_t*)&hv;
    lp = *(uint32_t*)&lv;
}

// ---------------- fp32 -> fp16 hi/lo split (activations) ----------------
__global__ void k_split(const float4* __restrict__ src,
                        uint2* __restrict__ hi, uint2* __restrict__ lo, int n4) {
    int i = blockIdx.x * 256 + threadIdx.x;
    if (i >= n4) return;
    uint2 h, l;
    split4h(src[i], h, l);
    hi[i] = h; lo[i] = l;
}

// ---- weight conversions (single fp16) ----
__global__ void k_cvt_w(const float4* __restrict__ src, uint2* __restrict__ dst, int n4) {
    int i = blockIdx.x * 256 + threadIdx.x;
    if (i >= n4) return;
    dst[i] = cvt4h(src[i]);
}

__global__ void k_cvt_qkvw(const float4* __restrict__ Wq, const float4* __restrict__ Wk,
                           const float4* __restrict__ Wv, uint2* __restrict__ dst) {
    const int NW4 = DD * DD / 4;
    int idx = blockIdx.x * 256 + threadIdx.x;
    if (idx >= 3 * NW4) return;
    int i = idx / NW4;
    int r = idx % NW4;
    int k  = r >> 8;
    int n4 = r & 255;
    const float4* src = (i == 0) ? Wq : (i == 1) ? Wk : Wv;
    dst[k * (3 * DD / 4) + i * (DD / 4) + n4] = cvt4h(src[r]);
}

// ============ fp16 2-term GEMM, BK=64, 2-stage, 1 barrier/chunk ============
// per-stage halves: Ahi[128*72] Alo[128*72] B[64*136]
#define SH_A0   0
#define SH_A1   9216
#define SH_B0   18432
#define SH_STG  27136
#define BGE_SMEM_BYTES (2 * SH_STG * 2)   // 108544 B

__global__ __launch_bounds__(256, 2)
void bgemm(const __half* __restrict__ Ahi, const __half* __restrict__ Alo, int lda,
           const __half* __restrict__ Bh, int ldb,
           float* __restrict__ C, int ldc, int K) {
    extern __shared__ __half sh[];
    uint32_t sbase = smem_u32(sh);

    int tid = threadIdx.x;
    int wid = tid >> 5, lane = tid & 31;
    int wm = wid & 3, wn = wid >> 2;
    int bx = blockIdx.x, by = blockIdx.y;

    float acc[2][8][4];
#pragma unroll
    for (int mt = 0; mt < 2; mt++)
#pragma unroll
        for (int nt = 0; nt < 8; nt++)
#pragma unroll
            for (int j = 0; j < 4; j++) acc[mt][nt][j] = 0.f;

    auto load_stage = [&](int c, int stage) {
        int k0 = c * 64;
        uint32_t s0 = sbase + (uint32_t)(stage * SH_STG) * 2;
        // A: 128 rows x 64 cols (8 f8-chunks per row) -> 1024 cp per matrix
#pragma unroll
        for (int i = 0; i < 4; i++) {
            int idx = i * 256 + tid;          // 0..1023
            int row = idx >> 3;
            int c8  = (idx & 7) * 8;
            size_t ga = (size_t)(by * 128 + row) * lda + k0 + c8;
            uint32_t d = s0 + (uint32_t)(row * 72 + c8) * 2;
            CP16(d, Ahi + ga);
            CP16(d + SH_A1 * 2, Alo + ga);
        }
        // B: 64 rows x 128 cols (16 f8 per row) -> 1024 cp
#pragma unroll
        for (int i = 0; i < 4; i++) {
            int idx = i * 256 + tid;
            int row = idx >> 4;
            int c8  = (idx & 15) * 8;
            size_t gb = (size_t)(k0 + row) * ldb + bx * 128 + c8;
            CP16(s0 + (uint32_t)(SH_B0 + row * 136 + c8) * 2, Bh + gb);
        }
        CP_COMMIT();
    };

    int nch = K >> 6;   // chunks of 64
    load_stage(0, 0);
    for (int c = 0; c < nch; c++) {
        CP_WAIT0();
        __syncthreads();           // chunk c visible; chunk c-1 compute retired
        if (c + 1 < nch) load_stage(c + 1, (c + 1) & 1);
        uint32_t s0 = sbase + (uint32_t)((c & 1) * SH_STG) * 2;
#pragma unroll
        for (int ks = 0; ks < 4; ks++) {
            uint32_t ah[2][4], al[2][4];
#pragma unroll
            for (int mt = 0; mt < 2; mt++) {
                int row = wm * 32 + mt * 16 + (lane & 15);
                int col = ks * 16 + (lane >> 4) * 8;
                uint32_t a = s0 + (uint32_t)(row * 72 + col) * 2;
                ldsm4(ah[mt], a);
                ldsm4(al[mt], a + SH_A1 * 2);
            }
#pragma unroll
            for (int nt2 = 0; nt2 < 4; nt2++) {
                uint32_t bh[4];
                int krow = ks * 16 + (lane & 15);
                int ncol = wn * 64 + nt2 * 16 + (lane >> 4) * 8;
                ldsm4t(bh, s0 + (uint32_t)(SH_B0 + krow * 136 + ncol) * 2);
#pragma unroll
                for (int p = 0; p < 2; p++) {
                    int nt = nt2 * 2 + p;
#pragma unroll
                    for (int mt = 0; mt < 2; mt++) {
                        mma_f16(acc[mt][nt], ah[mt], bh[2 * p], bh[2 * p + 1]);
                        mma_f16(acc[mt][nt], al[mt], bh[2 * p], bh[2 * p + 1]);
                    }
                }
            }
        }
    }
    __syncthreads();

#pragma unroll
    for (int mt = 0; mt < 2; mt++) {
#pragma unroll
        for (int nt = 0; nt < 8; nt++) {
            int r  = by * 128 + wm * 32 + mt * 16 + (lane >> 2);
            int cc = bx * 128 + wn * 64 + nt * 8 + (lane & 3) * 2;
            *(float2*)&C[(size_t)r * ldc + cc] =
                make_float2(acc[mt][nt][0], acc[mt][nt][1]);
            *(float2*)&C[(size_t)(r + 8) * ldc + cc] =
                make_float2(acc[mt][nt][2], acc[mt][nt][3]);
        }
    }
}

// ---------------- T5 bidirectional relative bucket ----------------
__device__ __forceinline__ int rel_bucket(int rp) {
    int rb = (rp > 0) ? (NBUCK / 2) : 0;
    int a  = rp < 0 ? -rp : rp;
    if (a < 8) return rb + a;
    float rf = (float)a;
    int large = 8 + (int)(logf(rf * 0.125f) * (8.0f / 2.772588722239781f));
    if (large > 15) large = 15;
    return rb + large;
}

// ---------------- 1D bias tables ----------------
__global__ void k_pgtab(const float* __restrict__ relb, const float* __restrict__ grel) {
    int idx = blockIdx.x * 256 + threadIdx.x;
    if (idx >= HH * 512) return;
    int h = idx >> 9;
    int i = idx & 511;
    int rel = i - 255;
    int bk = rel_bucket(rel);
    g_pb[idx] = relb[bk * HH + h];
    g_gb[idx] = grel[bk * HH + h];
}

// ---------------- block ids / global segments ----------------
__global__ void k_block_ids(const int* __restrict__ mask) {
    int b = blockIdx.x;
    __shared__ int s_cnt, s_max;
    if (threadIdx.x == 0) { s_cnt = 0; s_max = -1; }
    __syncthreads();
    int lc = 0;
    for (int i = threadIdx.x; i < SS; i += blockDim.x)
        if (((i & (GG - 1)) == GG - 1) && mask[b * SS + i] != 0) lc++;
    atomicAdd(&s_cnt, lc);
    __syncthreads();
    int full = s_cnt - 1;
    int lm = -1;
    for (int i = threadIdx.x; i < SS; i += blockDim.x) {
        int id;
        if (mask[b * SS + i] != 0) { id = i / GG; if (id > full) id = full; }
        else id = -1;
        g_bid[b * SS + i] = id;
        if (id > lm) lm = id;
    }
    atomicMax(&s_max, lm);
    __syncthreads();
    for (int g = threadIdx.x; g < GLL; g += blockDim.x)
        g_gseg[b * GLL + g] = (g <= s_max) ? 1 : 0;
    if (threadIdx.x == 0) g_full[b] = full;
}

// ---------------- global aggregates + RMSNorm ----------------
__global__ void k_global_agg(const float* __restrict__ hs, const float* __restrict__ gln_w) {
    int g = blockIdx.x, b = blockIdx.y;
    int t = threadIdx.x;
    int full = g_full[b];
    float acc0 = 0.f, acc1 = 0.f, acc2 = 0.f, acc3 = 0.f;
    if (g <= full) {
        int s_begin = g * GG;
        int s_end   = (g == full) ? SS : (g + 1) * GG;
#pragma unroll 1
        for (int s = s_begin; s < s_end; s++) {
            if (g_bid[b * SS + s] == g) {
                const float* row = hs + ((size_t)(b * SS + s)) * DD;
                acc0 += row[t];
                acc1 += row[t + 256];
                acc2 += row[t + 512];
                acc3 += row[t + 768];
            }
        }
    }
    __shared__ float red[256];
    red[t] = acc0 * acc0 + acc1 * acc1 + acc2 * acc2 + acc3 * acc3;
    __syncthreads();
    for (int off = 128; off > 0; off >>= 1) {
        if (t < off) red[t] += red[t + off];
        __syncthreads();
    }
    float var = red[0] * (1.0f / (float)DD);
    float sc = rsqrtf(var + 1e-6f);
    float* out = g_gi + ((size_t)(b * GLL + g)) * DD;
    out[t]       = acc0 * sc * gln_w[t];
    out[t + 256] = acc1 * sc * gln_w[t + 256];
    out[t + 512] = acc2 * sc * gln_w[t + 512];
    out[t + 768] = acc3 * sc * gln_w[t + 768];
}

// ================= tensor-core attention (fp16 2-term, CHUNK=64, occ 2) =====
// Q in registers (fragments); K/V staged per 64-key chunk.
#define ATT_KH   0          // K: 64 rows x 72 halves = 9216 B
#define ATT_VH   9216       // V: same
#define ATT_PB   36864      // (Q staging transiently uses [0,36864))
#define ATT_GB   38912
#define ATT_KVAL 40960      // 64 ints
#define ATT_GSEG 41216      // 256 ints
#define ATT_SMEM 42240

__global__ __launch_bounds__(256, 2)
void k_attn(const int* __restrict__ mask) {
    extern __shared__ char sm[];
    uint32_t sbase = smem_u32(sm);
    int h = blockIdx.x, n = blockIdx.y, b = blockIdx.z;
    int tid = threadIdx.x;
    int w = tid >> 5, lane = tid & 31;
    int g4 = lane >> 2, q4 = lane & 3;

    // ---- stage Q (fp16 hi/lo) transiently into [0,36864) ----
#pragma unroll
    for (int i = 0; i < 8; i++) {
        int f4 = i * 256 + tid;
        int row = f4 >> 4;
        int c4 = (f4 & 15) * 4;
        const float* qp = g_qkv + ((size_t)(b * SS + n * BLL + row)) * (3 * DD) + h * DKK + c4;
        uint2 qh, ql;
        split4h(*(const float4*)qp, qh, ql);
        uint32_t off = row * 144 + c4 * 2;
        *(uint2*)(sm + off)         = qh;
        *(uint2*)(sm + 18432 + off) = ql;
    }
    ((float*)(sm + ATT_PB))[tid]       = g_pb[h * 512 + tid];
    ((float*)(sm + ATT_PB))[tid + 256] = g_pb[h * 512 + tid + 256];
    ((float*)(sm + ATT_GB))[tid]       = g_gb[h * 512 + tid];
    ((float*)(sm + ATT_GB))[tid + 256] = g_gb[h * 512 + tid + 256];
    ((int*)(sm + ATT_GSEG))[tid]       = g_gseg[b * GLL + tid];
    __syncthreads();

    // ---- Q fragments into registers (live whole kernel) ----
    uint32_t qfh[4][4], qfl[4][4];
#pragma unroll
    for (int kt = 0; kt < 4; kt++) {
        uint32_t qa = sbase + (w * 16 + (lane & 15)) * 144 + (kt * 16 + (lane >> 4) * 8) * 2;
        ldsm4(qfh[kt], qa);
        ldsm4(qfl[kt], qa + 18432);
    }

    int r0  = w * 16 + g4;
    int sq0 = n * BLL + r0;
    int mq0 = mask[b * SS + sq0], mq1 = mask[b * SS + sq0 + 8];
    int bid0 = g_bid[b * SS + sq0], bid1 = g_bid[b * SS + sq0 + 8];

    const float* pb_s   = (const float*)(sm + ATT_PB);
    const float* gb_s   = (const float*)(sm + ATT_GB);
    const int*   kval_s = (const int*)(sm + ATT_KVAL);
    const int*   gseg_s = (const int*)(sm + ATT_GSEG);

    float o[8][4];
#pragma unroll
    for (int nt = 0; nt < 8; nt++)
#pragma unroll
        for (int j = 0; j < 4; j++) o[nt][j] = 0.f;
    float m0 = -1e30f, m1 = -1e30f, l0 = 0.f, l1 = 0.f;

    // 10 chunks of 64 keys: 0..5 local (384), 6..9 side (256)
    for (int c = 0; c < 10; c++) {
        __syncthreads();   // prior compute (or Q-frag reads) done before overwrite
        // ---- stage K/V chunk (64 keys) as single fp16 ----
#pragma unroll
        for (int i = 0; i < 8; i++) {
            int idx = i * 256 + tid;          // 0..2047
            int isV = idx >> 10;
            int r   = (idx & 1023) >> 4;      // row 0..63
            int c4  = (idx & 15) * 4;
            const float* p;
            if (c < 6) {
                int t = (n - 1) * BLL + c * 64 + r;
                int tc = min(max(t, 0), SS - 1);
                p = g_qkv + ((size_t)(b * SS + tc)) * (3 * DD) + h * DKK + c4
                  + (isV ? 2 * DD : DD);
            } else {
                int gI = (c - 6) * 64 + r;
                p = g_skv + ((size_t)(b * GLL + gI)) * (2 * DD) + h * DKK + c4
                  + (isV ? DD : 0);
            }
            *(uint2*)(sm + (isV ? ATT_VH : ATT_KH) + r * 144 + c4 * 2) =
                cvt4h(*(const float4*)p);
        }
        if (c < 6 && tid < 64) {
            int t = (n - 1) * BLL + c * 64 + tid;
            ((int*)(sm + ATT_KVAL))[tid] = (t >= 0 && t < SS) ? mask[b * SS + t] : 0;
        }
        __syncthreads();

        // ---- S = Q K^T (2-term fp16), 16 rows x 64 keys per warp ----
        float s[8][4];
#pragma unroll
        for (int nt = 0; nt < 8; nt++)
#pragma unroll
            for (int j = 0; j < 4; j++) s[nt][j] = 0.f;

#pragma unroll
        for (int kt = 0; kt < 4; kt++) {
#pragma unroll
            for (int nt2 = 0; nt2 < 4; nt2++) {
                uint32_t kh[4];
                uint32_t ka = sbase + ATT_KH + (nt2 * 16 + (lane & 15)) * 144
                            + (kt * 16 + (lane >> 4) * 8) * 2;
                ldsm4(kh, ka);
                mma_f16(s[2 * nt2],     qfh[kt], kh[0], kh[2]);
                mma_f16(s[2 * nt2],     qfl[kt], kh[0], kh[2]);
                mma_f16(s[2 * nt2 + 1], qfh[kt], kh[1], kh[3]);
                mma_f16(s[2 * nt2 + 1], qfl[kt], kh[1], kh[3]);
            }
        }

        // ---- bias + mask ----
#pragma unroll
        for (int nt = 0; nt < 8; nt++) {
            int cn = 8 * nt + 2 * q4;            // chunk-local key 0..63
            if (c < 6) {
                int kv0 = kval_s[cn], kv1 = kval_s[cn + 1];
                int rel0 = c * 64 + cn - BLL - r0;
                int rel1 = rel0 - 8;
                s[nt][0] += pb_s[rel0 + 255] +
                    ((mq0 && kv0 && rel0 > -BLL && rel0 < BLL) ? 0.f : NEGV);
                s[nt][1] += pb_s[rel0 + 256] +
                    ((mq0 && kv1 && rel0 + 1 > -BLL && rel0 + 1 < BLL) ? 0.f : NEGV);
                s[nt][2] += pb_s[rel1 + 255] +
                    ((mq1 && kv0 && rel1 > -BLL && rel1 < BLL) ? 0.f : NEGV);
                s[nt][3] += pb_s[rel1 + 256] +
                    ((mq1 && kv1 && rel1 + 1 > -BLL && rel1 + 1 < BLL) ? 0.f : NEGV);
            } else {
                int g0 = (c - 6) * 64 + cn;
                int gs0 = gseg_s[g0], gs1 = gseg_s[g0 + 1];
                int sp0 = g0 - bid0, sp1 = g0 - bid1;
                s[nt][0] += gb_s[sp0 + 255] + ((mq0 == gs0) ? 0.f : NEGV);
                s[nt][1] += gb_s[sp0 + 256] + ((mq0 == gs1) ? 0.f : NEGV);
                s[nt][2] += gb_s[sp1 + 255] + ((mq1 == gs0) ? 0.f : NEGV);
                s[nt][3] += gb_s[sp1 + 256] + ((mq1 == gs1) ? 0.f : NEGV);
            }
        }

        // ---- online softmax ----
        float mx0 = -1e30f, mx1 = -1e30f;
#pragma unroll
        for (int nt = 0; nt < 8; nt++) {
            mx0 = fmaxf(mx0, fmaxf(s[nt][0], s[nt][1]));
            mx1 = fmaxf(mx1, fmaxf(s[nt][2], s[nt][3]));
        }
        mx0 = fmaxf(mx0, __shfl_xor_sync(0xFFFFFFFF, mx0, 1));
        mx0 = fmaxf(mx0, __shfl_xor_sync(0xFFFFFFFF, mx0, 2));
        mx1 = fmaxf(mx1, __shfl_xor_sync(0xFFFFFFFF, mx1, 1));
        mx1 = fmaxf(mx1, __shfl_xor_sync(0xFFFFFFFF, mx1, 2));
        float nm0 = fmaxf(m0, mx0), nm1 = fmaxf(m1, mx1);
        float rs0 = __expf(m0 - nm0), rs1 = __expf(m1 - nm1);
        m0 = nm0; m1 = nm1;

        float ps0 = 0.f, ps1 = 0.f;
#pragma unroll
        for (int nt = 0; nt < 8; nt++) {
            s[nt][0] = __expf(s[nt][0] - nm0); ps0 += s[nt][0];
            s[nt][1] = __expf(s[nt][1] - nm0); ps0 += s[nt][1];
            s[nt][2] = __expf(s[nt][2] - nm1); ps1 += s[nt][2];
            s[nt][3] = __expf(s[nt][3] - nm1); ps1 += s[nt][3];
        }
        ps0 += __shfl_xor_sync(0xFFFFFFFF, ps0, 1);
        ps0 += __shfl_xor_sync(0xFFFFFFFF, ps0, 2);
        ps1 += __shfl_xor_sync(0xFFFFFFFF, ps1, 1);
        ps1 += __shfl_xor_sync(0xFFFFFFFF, ps1, 2);
        l0 = l0 * rs0 + ps0;
        l1 = l1 * rs1 + ps1;

#pragma unroll
        for (int nt = 0; nt < 8; nt++) {
            o[nt][0] *= rs0; o[nt][1] *= rs0;
            o[nt][2] *= rs1; o[nt][3] *= rs1;
        }

        // ---- O += P V (P 2-term fp16; V single) ----
#pragma unroll
        for (int kt = 0; kt < 4; kt++) {
            uint32_t phi[4], plo[4];
            packhl_h(s[2 * kt][0],     s[2 * kt][1],     phi[0], plo[0]);
            packhl_h(s[2 * kt][2],     s[2 * kt][3],     phi[1], plo[1]);
            packhl_h(s[2 * kt + 1][0], s[2 * kt + 1][1], phi[2], plo[2]);
            packhl_h(s[2 * kt + 1][2], s[2 * kt + 1][3], phi[3], plo[3]);
#pragma unroll
            for (int nt2 = 0; nt2 < 4; nt2++) {
                uint32_t vh[4];
                uint32_t va = sbase + ATT_VH + (kt * 16 + (lane & 15)) * 144
                            + (nt2 * 16 + (lane >> 4) * 8) * 2;
                ldsm4t(vh, va);
                mma_f16(o[2 * nt2],     phi, vh[0], vh[1]);
                mma_f16(o[2 * nt2],     plo, vh[0], vh[1]);
                mma_f16(o[2 * nt2 + 1], phi, vh[2], vh[3]);
                mma_f16(o[2 * nt2 + 1], plo, vh[2], vh[3]);
            }
        }
    }

    // ---- epilogue: write ctx as fp16 hi/lo directly ----
    float inv0 = 1.0f / l0, inv1 = 1.0f / l1;
    size_t co0 = ((size_t)(b * SS + sq0)) * DD + h * DKK;
    size_t co1 = ((size_t)(b * SS + sq0 + 8)) * DD + h * DKK;
#pragma unroll
    for (int nt = 0; nt < 8; nt++) {
        int cc = 8 * nt + 2 * q4;
        uint32_t hp, lp;
        packhl_h(o[nt][0] * inv0, o[nt][1] * inv0, hp, lp);
        *(uint32_t*)(g_ctx_hi + co0 + cc) = hp;
        *(uint32_t*)(g_ctx_lo + co0 + cc) = lp;
        packhl_h(o[nt][2] * inv1, o[nt][3] * inv1, hp, lp);
        *(uint32_t*)(g_ctx_hi + co1 + cc) = hp;
        *(uint32_t*)(g_ctx_lo + co1 + cc) = lp;
    }
}

// ---------------- launch ----------------
extern "C" void kernel_launch(void* const* d_in, const int* in_sizes, int n_in,
                              void* d_out, int out_size) {
    const float* hs   = (const float*)d_in[0];
    const float* Wq   = (const float*)d_in[1];
    const float* Wk   = (const float*)d_in[2];
    const float* Wv   = (const float*)d_in[3];
    const float* Wo   = (const float*)d_in[4];
    const float* relb = (const float*)d_in[5];
    const float* grel = (const float*)d_in[6];
    const float* gln  = (const float*)d_in[7];
    const int*   mask = (const int*)d_in[8];
    float* out = (float*)d_out;

    float *p_qkv, *p_skv, *p_gi;
    cudaGetSymbolAddress((void**)&p_qkv, g_qkv);
    cudaGetSymbolAddress((void**)&p_skv, g_skv);
    cudaGetSymbolAddress((void**)&p_gi,  g_gi);

    __half *hs_hi, *hs_lo, *ctx_hi, *ctx_lo, *gi_hi, *gi_lo, *wqkv, *wo;
    cudaGetSymbolAddress((void**)&hs_hi,  g_hs_hi);
    cudaGetSymbolAddress((void**)&hs_lo,  g_hs_lo);
    cudaGetSymbolAddress((void**)&ctx_hi, g_ctx_hi);
    cudaGetSymbolAddress((void**)&ctx_lo, g_ctx_lo);
    cudaGetSymbolAddress((void**)&gi_hi,  g_gi_hi);
    cudaGetSymbolAddress((void**)&gi_lo,  g_gi_lo);
    cudaGetSymbolAddress((void**)&wqkv,   g_wqkv);
    cudaGetSymbolAddress((void**)&wo,     g_wo);

    cudaFuncSetAttribute(bgemm, cudaFuncAttributeMaxDynamicSharedMemorySize, BGE_SMEM_BYTES);
    cudaFuncSetAttribute(k_attn, cudaFuncAttributeMaxDynamicSharedMemorySize, ATT_SMEM);

    const int NHS4 = BB * SS * DD / 4;
    const int NW4  = DD * DD / 4;
    const int NGI4 = BB * GLL * DD / 4;

    // #1..#3: prerequisites for the big QKV GEMM
    k_cvt_qkvw<<<(3 * NW4 + 255) / 256, 256>>>((const float4*)Wq, (const float4*)Wk,
                                               (const float4*)Wv, (uint2*)wqkv);
    k_split<<<(NHS4 + 255) / 256, 256>>>((const float4*)hs, (uint2*)hs_hi, (uint2*)hs_lo, NHS4);
    k_block_ids<<<BB, 256>>>(mask);

    // #4: fused QKV GEMM (profiled slot)
    bgemm<<<dim3(3 * DD / 128, (BB * SS) / 128), 256, BGE_SMEM_BYTES>>>(
        hs_hi, hs_lo, DD, wqkv, 3 * DD, p_qkv, 3 * DD, DD);

    // global path
    k_global_agg<<<dim3(GLL, BB), 256>>>(hs, gln);
    k_split<<<(NGI4 + 255) / 256, 256>>>((const float4*)p_gi, (uint2*)gi_hi, (uint2*)gi_lo, NGI4);
    bgemm<<<dim3(2 * DD / 128, (BB * GLL) / 128), 256, BGE_SMEM_BYTES>>>(
        gi_hi, gi_lo, DD, wqkv + DD, 3 * DD, p_skv, 2 * DD, DD);

    // bias tables + Wo convert
    k_pgtab<<<(HH * 512 + 255) / 256, 256>>>(relb, grel);
    k_cvt_w<<<(NW4 + 255) / 256, 256>>>((const float4*)Wo, (uint2*)wo, NW4);

    // attention (tensor-core, fp16 2-term, occ 2)
    k_attn<<<dim3(HH, SS / BLL, BB), 256, ATT_SMEM>>>(mask);

    // output projection (reads ctx hi/lo written by attention)
    bgemm<<<dim3(DD / 128, (BB * SS) / 128), 256, BGE_SMEM_BYTES>>>(
        ctx_hi, ctx_lo, DD, wo, DD, out, DD, DD);
}

// round 12
// speedup vs baseline: 1.4571x; 1.0036x over previous
#include <cuda_runtime.h>
#include <cuda_bf16.h>
#include <cuda_fp16.h>
#include <cstdint>
#include <math.h>

#define BB   2
#define SS   4096
#define DD   1024
#define HH   16
#define DKK  64
#define BLL  128
#define GG   16
#define GLL  256
#define NBUCK 32
#define NEGV (-1e10f)

// ---------------- scratch (device globals: allocation-free) ----------------
__device__ float g_qkv[BB*SS*3*DD];    // [row][q|k|v]
__device__ float g_skv[BB*GLL*2*DD];   // [row][sk|sv]
__device__ float g_gi [BB*GLL*DD];
__device__ float g_pb [HH*512];
__device__ float g_gb [HH*512];
__device__ int   g_bid [BB*SS];
__device__ int   g_gseg[BB*GLL];
__device__ int   g_full[BB];

// fp16 split buffers: activations hi/lo, weights single
__device__ __half g_hs_hi  [BB*SS*DD];
__device__ __half g_hs_lo  [BB*SS*DD];
__device__ __half g_ctx_hi [BB*SS*DD];
__device__ __half g_ctx_lo [BB*SS*DD];
__device__ __half g_gi_hi  [BB*GLL*DD];
__device__ __half g_gi_lo  [BB*GLL*DD];
__device__ __half g_wqkv   [DD*3*DD];   // [k][3*DD] interleaved q|k|v cols
__device__ __half g_wo     [DD*DD];

// ---------------- helpers ----------------
__device__ __forceinline__ uint32_t smem_u32(const void* p) {
    uint32_t a;
    asm("{ .reg .u64 t; cvta.to.shared.u64 t, %1; cvt.u32.u64 %0, t; }" : "=r"(a) : "l"(p));
    return a;
}

#define CP16(dst, src) asm volatile("cp.async.cg.shared.global [%0], [%1], 16;" :: "r"(dst), "l"(src) : "memory")
#define CP_COMMIT()    asm volatile("cp.async.commit_group;" ::: "memory")
#define CP_WAIT0()     asm volatile("cp.async.wait_group 0;" ::: "memory")

__device__ __forceinline__ void ldsm4(uint32_t* r, uint32_t a) {
    asm volatile("ldmatrix.sync.aligned.m8n8.x4.shared.b16 {%0,%1,%2,%3}, [%4];"
        : "=r"(r[0]), "=r"(r[1]), "=r"(r[2]), "=r"(r[3]) : "r"(a));
}
__device__ __forceinline__ void ldsm4t(uint32_t* r, uint32_t a) {
    asm volatile("ldmatrix.sync.aligned.m8n8.x4.trans.shared.b16 {%0,%1,%2,%3}, [%4];"
        : "=r"(r[0]), "=r"(r[1]), "=r"(r[2]), "=r"(r[3]) : "r"(a));
}
__device__ __forceinline__ void mma_f16(float* d, const uint32_t* a, uint32_t b0, uint32_t b1) {
    asm volatile("mma.sync.aligned.m16n8k16.row.col.f32.f16.f16.f32 "
        "{%0,%1,%2,%3}, {%4,%5,%6,%7}, {%8,%9}, {%0,%1,%2,%3};"
        : "+f"(d[0]), "+f"(d[1]), "+f"(d[2]), "+f"(d[3])
        : "r"(a[0]), "r"(a[1]), "r"(a[2]), "r"(a[3]), "r"(b0), "r"(b1));
}

// fp32x4 -> fp16 hi (uint2 = 4 halves) + fp16 lo
__device__ __forceinline__ void split4h(float4 a, uint2& h, uint2& l) {
    __half2 h01 = __floats2half2_rn(a.x, a.y);
    __half2 h23 = __floats2half2_rn(a.z, a.w);
    float l0 = a.x - __half2float(__low2half(h01));
    float l1 = a.y - __half2float(__high2half(h01));
    float l2 = a.z - __half2float(__low2half(h23));
    float l3 = a.w - __half2float(__high2half(h23));
    __half2 q01 = __floats2half2_rn(l0, l1);
    __half2 q23 = __floats2half2_rn(l2, l3);
    h = make_uint2(*(uint32_t*)&h01, *(uint32_t*)&h23);
    l = make_uint2(*(uint32_t*)&q01, *(uint32_t*)&q23);
}

// fp32x4 -> fp16 single
__device__ __forceinline__ uint2 cvt4h(float4 a) {
    __half2 h01 = __floats2half2_rn(a.x, a.y);
    __half2 h23 = __floats2half2_rn(a.z, a.w);
    return make_uint2(*(uint32_t*)&h01, *(uint32_t*)&h23);
}

__device__ __forceinline__ void packhl_h(float a, float b, uint32_t& hp, uint32_t& lp) {
    __half2 hv = __floats2half2_rn(a, b);
    __half2 lv = __floats2half2_rn(a - __half2float(__low2half(hv)),
                                   b - __half2float(__high2half(hv)));
    hp = *(uint32_t*)&hv;
    lp = *(uint32_t*)&lv;
}

// ---------------- fp32 -> fp16 hi/lo split (activations) ----------------
__global__ void k_split(const float4* __restrict__ src,
                        uint2* __restrict__ hi, uint2* __restrict__ lo, int n4) {
    int i = blockIdx.x * 256 + threadIdx.x;
    if (i >= n4) return;
    uint2 h, l;
    split4h(src[i], h, l);
    hi[i] = h; lo[i] = l;
}

// ---- weight conversions (single fp16) ----
__global__ void k_cvt_w(const float4* __restrict__ src, uint2* __restrict__ dst, int n4) {
    int i = blockIdx.x * 256 + threadIdx.x;
    if (i >= n4) return;
    dst[i] = cvt4h(src[i]);
}

__global__ void k_cvt_qkvw(const float4* __restrict__ Wq, const float4* __restrict__ Wk,
                           const float4* __restrict__ Wv, uint2* __restrict__ dst) {
    const int NW4 = DD * DD / 4;
    int idx = blockIdx.x * 256 + threadIdx.x;
    if (idx >= 3 * NW4) return;
    int i = idx / NW4;
    int r = idx % NW4;
    int k  = r >> 8;
    int n4 = r & 255;
    const float4* src = (i == 0) ? Wq : (i == 1) ? Wk : Wv;
    dst[k * (3 * DD / 4) + i * (DD / 4) + n4] = cvt4h(src[r]);
}

// ============ fp16 2-term GEMM, BK=64, 2-stage, hi/lo de-interleaved ========
// per-stage halves: Ahi[128*72] Alo[128*72] B[64*136]
#define SH_A0   0
#define SH_A1   9216
#define SH_B0   18432
#define SH_STG  27136
#define BGE_SMEM_BYTES (2 * SH_STG * 2)   // 108544 B

__global__ __launch_bounds__(256, 2)
void bgemm(const __half* __restrict__ Ahi, const __half* __restrict__ Alo, int lda,
           const __half* __restrict__ Bh, int ldb,
           float* __restrict__ C, int ldc, int K) {
    extern __shared__ __half sh[];
    uint32_t sbase = smem_u32(sh);

    int tid = threadIdx.x;
    int wid = tid >> 5, lane = tid & 31;
    int wm = wid & 3, wn = wid >> 2;
    int bx = blockIdx.x, by = blockIdx.y;

    float acc[2][8][4];
#pragma unroll
    for (int mt = 0; mt < 2; mt++)
#pragma unroll
        for (int nt = 0; nt < 8; nt++)
#pragma unroll
            for (int j = 0; j < 4; j++) acc[mt][nt][j] = 0.f;

    auto load_stage = [&](int c, int stage) {
        int k0 = c * 64;
        uint32_t s0 = sbase + (uint32_t)(stage * SH_STG) * 2;
#pragma unroll
        for (int i = 0; i < 4; i++) {
            int idx = i * 256 + tid;          // 0..1023
            int row = idx >> 3;
            int c8  = (idx & 7) * 8;
            size_t ga = (size_t)(by * 128 + row) * lda + k0 + c8;
            uint32_t d = s0 + (uint32_t)(row * 72 + c8) * 2;
            CP16(d, Ahi + ga);
            CP16(d + SH_A1 * 2, Alo + ga);
        }
#pragma unroll
        for (int i = 0; i < 4; i++) {
            int idx = i * 256 + tid;
            int row = idx >> 4;
            int c8  = (idx & 15) * 8;
            size_t gb = (size_t)(k0 + row) * ldb + bx * 128 + c8;
            CP16(s0 + (uint32_t)(SH_B0 + row * 136 + c8) * 2, Bh + gb);
        }
        CP_COMMIT();
    };

    int nch = K >> 6;   // chunks of 64
    load_stage(0, 0);
    for (int c = 0; c < nch; c++) {
        CP_WAIT0();
        __syncthreads();
        if (c + 1 < nch) load_stage(c + 1, (c + 1) & 1);
        uint32_t s0 = sbase + (uint32_t)((c & 1) * SH_STG) * 2;
#pragma unroll
        for (int ks = 0; ks < 4; ks++) {
            uint32_t ah[2][4], al[2][4], bh4[4][4];
#pragma unroll
            for (int mt = 0; mt < 2; mt++) {
                int row = wm * 32 + mt * 16 + (lane & 15);
                int col = ks * 16 + (lane >> 4) * 8;
                uint32_t a = s0 + (uint32_t)(row * 72 + col) * 2;
                ldsm4(ah[mt], a);
                ldsm4(al[mt], a + SH_A1 * 2);
            }
#pragma unroll
            for (int nt2 = 0; nt2 < 4; nt2++) {
                int krow = ks * 16 + (lane & 15);
                int ncol = wn * 64 + nt2 * 16 + (lane >> 4) * 8;
                ldsm4t(bh4[nt2], s0 + (uint32_t)(SH_B0 + krow * 136 + ncol) * 2);
            }
            // hi sweep (16 independent accumulators)
#pragma unroll
            for (int nt2 = 0; nt2 < 4; nt2++)
#pragma unroll
                for (int p = 0; p < 2; p++)
#pragma unroll
                    for (int mt = 0; mt < 2; mt++)
                        mma_f16(acc[mt][nt2 * 2 + p], ah[mt],
                                bh4[nt2][2 * p], bh4[nt2][2 * p + 1]);
            // lo sweep
#pragma unroll
            for (int nt2 = 0; nt2 < 4; nt2++)
#pragma unroll
                for (int p = 0; p < 2; p++)
#pragma unroll
                    for (int mt = 0; mt < 2; mt++)
                        mma_f16(acc[mt][nt2 * 2 + p], al[mt],
                                bh4[nt2][2 * p], bh4[nt2][2 * p + 1]);
        }
    }
    __syncthreads();

#pragma unroll
    for (int mt = 0; mt < 2; mt++) {
#pragma unroll
        for (int nt = 0; nt < 8; nt++) {
            int r  = by * 128 + wm * 32 + mt * 16 + (lane >> 2);
            int cc = bx * 128 + wn * 64 + nt * 8 + (lane & 3) * 2;
            *(float2*)&C[(size_t)r * ldc + cc] =
                make_float2(acc[mt][nt][0], acc[mt][nt][1]);
            *(float2*)&C[(size_t)(r + 8) * ldc + cc] =
                make_float2(acc[mt][nt][2], acc[mt][nt][3]);
        }
    }
}

// ---------------- T5 bidirectional relative bucket ----------------
__device__ __forceinline__ int rel_bucket(int rp) {
    int rb = (rp > 0) ? (NBUCK / 2) : 0;
    int a  = rp < 0 ? -rp : rp;
    if (a < 8) return rb + a;
    float rf = (float)a;
    int large = 8 + (int)(logf(rf * 0.125f) * (8.0f / 2.772588722239781f));
    if (large > 15) large = 15;
    return rb + large;
}

// ---------------- 1D bias tables ----------------
__global__ void k_pgtab(const float* __restrict__ relb, const float* __restrict__ grel) {
    int idx = blockIdx.x * 256 + threadIdx.x;
    if (idx >= HH * 512) return;
    int h = idx >> 9;
    int i = idx & 511;
    int rel = i - 255;
    int bk = rel_bucket(rel);
    g_pb[idx] = relb[bk * HH + h];
    g_gb[idx] = grel[bk * HH + h];
}

// ---------------- block ids / global segments ----------------
__global__ void k_block_ids(const int* __restrict__ mask) {
    int b = blockIdx.x;
    __shared__ int s_cnt, s_max;
    if (threadIdx.x == 0) { s_cnt = 0; s_max = -1; }
    __syncthreads();
    int lc = 0;
    for (int i = threadIdx.x; i < SS; i += blockDim.x)
        if (((i & (GG - 1)) == GG - 1) && mask[b * SS + i] != 0) lc++;
    atomicAdd(&s_cnt, lc);
    __syncthreads();
    int full = s_cnt - 1;
    int lm = -1;
    for (int i = threadIdx.x; i < SS; i += blockDim.x) {
        int id;
        if (mask[b * SS + i] != 0) { id = i / GG; if (id > full) id = full; }
        else id = -1;
        g_bid[b * SS + i] = id;
        if (id > lm) lm = id;
    }
    atomicMax(&s_max, lm);
    __syncthreads();
    for (int g = threadIdx.x; g < GLL; g += blockDim.x)
        g_gseg[b * GLL + g] = (g <= s_max) ? 1 : 0;
    if (threadIdx.x == 0) g_full[b] = full;
}

// ---------------- global aggregates + RMSNorm ----------------
__global__ void k_global_agg(const float* __restrict__ hs, const float* __restrict__ gln_w) {
    int g = blockIdx.x, b = blockIdx.y;
    int t = threadIdx.x;
    int full = g_full[b];
    float acc0 = 0.f, acc1 = 0.f, acc2 = 0.f, acc3 = 0.f;
    if (g <= full) {
        int s_begin = g * GG;
        int s_end   = (g == full) ? SS : (g + 1) * GG;
#pragma unroll 1
        for (int s = s_begin; s < s_end; s++) {
            if (g_bid[b * SS + s] == g) {
                const float* row = hs + ((size_t)(b * SS + s)) * DD;
                acc0 += row[t];
                acc1 += row[t + 256];
                acc2 += row[t + 512];
                acc3 += row[t + 768];
            }
        }
    }
    __shared__ float red[256];
    red[t] = acc0 * acc0 + acc1 * acc1 + acc2 * acc2 + acc3 * acc3;
    __syncthreads();
    for (int off = 128; off > 0; off >>= 1) {
        if (t < off) red[t] += red[t + off];
        __syncthreads();
    }
    float var = red[0] * (1.0f / (float)DD);
    float sc = rsqrtf(var + 1e-6f);
    float* out = g_gi + ((size_t)(b * GLL + g)) * DD;
    out[t]       = acc0 * sc * gln_w[t];
    out[t + 256] = acc1 * sc * gln_w[t + 256];
    out[t + 512] = acc2 * sc * gln_w[t + 512];
    out[t + 768] = acc3 * sc * gln_w[t + 768];
}

// ================= tensor-core attention (fp16 2-term, CHUNK=64, occ 2) =====
#define ATT_KH   0          // K: 64 rows x 72 halves = 9216 B
#define ATT_VH   9216
#define ATT_PB   36864      // (Q staging transiently uses [0,36864))
#define ATT_GB   38912
#define ATT_KVAL 40960
#define ATT_GSEG 41216
#define ATT_SMEM 42240

__global__ __launch_bounds__(256, 2)
void k_attn(const int* __restrict__ mask) {
    extern __shared__ char sm[];
    uint32_t sbase = smem_u32(sm);
    int h = blockIdx.x, n = blockIdx.y, b = blockIdx.z;
    int tid = threadIdx.x;
    int w = tid >> 5, lane = tid & 31;
    int g4 = lane >> 2, q4 = lane & 3;

    // ---- stage Q (fp16 hi/lo) transiently into [0,36864) ----
#pragma unroll
    for (int i = 0; i < 8; i++) {
        int f4 = i * 256 + tid;
        int row = f4 >> 4;
        int c4 = (f4 & 15) * 4;
        const float* qp = g_qkv + ((size_t)(b * SS + n * BLL + row)) * (3 * DD) + h * DKK + c4;
        uint2 qh, ql;
        split4h(*(const float4*)qp, qh, ql);
        uint32_t off = row * 144 + c4 * 2;
        *(uint2*)(sm + off)         = qh;
        *(uint2*)(sm + 18432 + off) = ql;
    }
    ((float*)(sm + ATT_PB))[tid]       = g_pb[h * 512 + tid];
    ((float*)(sm + ATT_PB))[tid + 256] = g_pb[h * 512 + tid + 256];
    ((float*)(sm + ATT_GB))[tid]       = g_gb[h * 512 + tid];
    ((float*)(sm + ATT_GB))[tid + 256] = g_gb[h * 512 + tid + 256];
    ((int*)(sm + ATT_GSEG))[tid]       = g_gseg[b * GLL + tid];
    __syncthreads();

    // ---- Q fragments into registers ----
    uint32_t qfh[4][4], qfl[4][4];
#pragma unroll
    for (int kt = 0; kt < 4; kt++) {
        uint32_t qa = sbase + (w * 16 + (lane & 15)) * 144 + (kt * 16 + (lane >> 4) * 8) * 2;
        ldsm4(qfh[kt], qa);
        ldsm4(qfl[kt], qa + 18432);
    }

    int r0  = w * 16 + g4;
    int sq0 = n * BLL + r0;
    int mq0 = mask[b * SS + sq0], mq1 = mask[b * SS + sq0 + 8];
    int bid0 = g_bid[b * SS + sq0], bid1 = g_bid[b * SS + sq0 + 8];

    const float* pb_s   = (const float*)(sm + ATT_PB);
    const float* gb_s   = (const float*)(sm + ATT_GB);
    const int*   kval_s = (const int*)(sm + ATT_KVAL);
    const int*   gseg_s = (const int*)(sm + ATT_GSEG);

    float o[8][4];
#pragma unroll
    for (int nt = 0; nt < 8; nt++)
#pragma unroll
        for (int j = 0; j < 4; j++) o[nt][j] = 0.f;
    float m0 = -1e30f, m1 = -1e30f, l0 = 0.f, l1 = 0.f;

    for (int c = 0; c < 10; c++) {
        __syncthreads();
        // ---- stage K/V chunk (64 keys) as single fp16 ----
#pragma unroll
        for (int i = 0; i < 8; i++) {
            int idx = i * 256 + tid;
            int isV = idx >> 10;
            int r   = (idx & 1023) >> 4;
            int c4  = (idx & 15) * 4;
            const float* p;
            if (c < 6) {
                int t = (n - 1) * BLL + c * 64 + r;
                int tc = min(max(t, 0), SS - 1);
                p = g_qkv + ((size_t)(b * SS + tc)) * (3 * DD) + h * DKK + c4
                  + (isV ? 2 * DD : DD);
            } else {
                int gI = (c - 6) * 64 + r;
                p = g_skv + ((size_t)(b * GLL + gI)) * (2 * DD) + h * DKK + c4
                  + (isV ? DD : 0);
            }
            *(uint2*)(sm + (isV ? ATT_VH : ATT_KH) + r * 144 + c4 * 2) =
                cvt4h(*(const float4*)p);
        }
        if (c < 6 && tid < 64) {
            int t = (n - 1) * BLL + c * 64 + tid;
            ((int*)(sm + ATT_KVAL))[tid] = (t >= 0 && t < SS) ? mask[b * SS + t] : 0;
        }
        __syncthreads();

        // ---- S = Q K^T (2-term fp16, hi/lo de-interleaved) ----
        float s[8][4];
#pragma unroll
        for (int nt = 0; nt < 8; nt++)
#pragma unroll
            for (int j = 0; j < 4; j++) s[nt][j] = 0.f;

#pragma unroll
        for (int kt = 0; kt < 4; kt++) {
            uint32_t kh4[4][4];
#pragma unroll
            for (int nt2 = 0; nt2 < 4; nt2++) {
                uint32_t ka = sbase + ATT_KH + (nt2 * 16 + (lane & 15)) * 144
                            + (kt * 16 + (lane >> 4) * 8) * 2;
                ldsm4(kh4[nt2], ka);
            }
            // hi sweep
#pragma unroll
            for (int nt2 = 0; nt2 < 4; nt2++) {
                mma_f16(s[2 * nt2],     qfh[kt], kh4[nt2][0], kh4[nt2][2]);
                mma_f16(s[2 * nt2 + 1], qfh[kt], kh4[nt2][1], kh4[nt2][3]);
            }
            // lo sweep
#pragma unroll
            for (int nt2 = 0; nt2 < 4; nt2++) {
                mma_f16(s[2 * nt2],     qfl[kt], kh4[nt2][0], kh4[nt2][2]);
                mma_f16(s[2 * nt2 + 1], qfl[kt], kh4[nt2][1], kh4[nt2][3]);
            }
        }

        // ---- bias + mask ----
#pragma unroll
        for (int nt = 0; nt < 8; nt++) {
            int cn = 8 * nt + 2 * q4;
            if (c < 6) {
                int kv0 = kval_s[cn], kv1 = kval_s[cn + 1];
                int rel0 = c * 64 + cn - BLL - r0;
                int rel1 = rel0 - 8;
                s[nt][0] += pb_s[rel0 + 255] +
                    ((mq0 && kv0 && rel0 > -BLL && rel0 < BLL) ? 0.f : NEGV);
                s[nt][1] += pb_s[rel0 + 256] +
                    ((mq0 && kv1 && rel0 + 1 > -BLL && rel0 + 1 < BLL) ? 0.f : NEGV);
                s[nt][2] += pb_s[rel1 + 255] +
                    ((mq1 && kv0 && rel1 > -BLL && rel1 < BLL) ? 0.f : NEGV);
                s[nt][3] += pb_s[rel1 + 256] +
                    ((mq1 && kv1 && rel1 + 1 > -BLL && rel1 + 1 < BLL) ? 0.f : NEGV);
            } else {
                int g0 = (c - 6) * 64 + cn;
                int gs0 = gseg_s[g0], gs1 = gseg_s[g0 + 1];
                int sp0 = g0 - bid0, sp1 = g0 - bid1;
                s[nt][0] += gb_s[sp0 + 255] + ((mq0 == gs0) ? 0.f : NEGV);
                s[nt][1] += gb_s[sp0 + 256] + ((mq0 == gs1) ? 0.f : NEGV);
                s[nt][2] += gb_s[sp1 + 255] + ((mq1 == gs0) ? 0.f : NEGV);
                s[nt][3] += gb_s[sp1 + 256] + ((mq1 == gs1) ? 0.f : NEGV);
            }
        }

        // ---- online softmax ----
        float mx0 = -1e30f, mx1 = -1e30f;
#pragma unroll
        for (int nt = 0; nt < 8; nt++) {
            mx0 = fmaxf(mx0, fmaxf(s[nt][0], s[nt][1]));
            mx1 = fmaxf(mx1, fmaxf(s[nt][2], s[nt][3]));
        }
        mx0 = fmaxf(mx0, __shfl_xor_sync(0xFFFFFFFF, mx0, 1));
        mx0 = fmaxf(mx0, __shfl_xor_sync(0xFFFFFFFF, mx0, 2));
        mx1 = fmaxf(mx1, __shfl_xor_sync(0xFFFFFFFF, mx1, 1));
        mx1 = fmaxf(mx1, __shfl_xor_sync(0xFFFFFFFF, mx1, 2));
        float nm0 = fmaxf(m0, mx0), nm1 = fmaxf(m1, mx1);
        float rs0 = __expf(m0 - nm0), rs1 = __expf(m1 - nm1);
        m0 = nm0; m1 = nm1;

        float ps0 = 0.f, ps1 = 0.f;
#pragma unroll
        for (int nt = 0; nt < 8; nt++) {
            s[nt][0] = __expf(s[nt][0] - nm0); ps0 += s[nt][0];
            s[nt][1] = __expf(s[nt][1] - nm0); ps0 += s[nt][1];
            s[nt][2] = __expf(s[nt][2] - nm1); ps1 += s[nt][2];
            s[nt][3] = __expf(s[nt][3] - nm1); ps1 += s[nt][3];
        }
        ps0 += __shfl_xor_sync(0xFFFFFFFF, ps0, 1);
        ps0 += __shfl_xor_sync(0xFFFFFFFF, ps0, 2);
        ps1 += __shfl_xor_sync(0xFFFFFFFF, ps1, 1);
        ps1 += __shfl_xor_sync(0xFFFFFFFF, ps1, 2);
        l0 = l0 * rs0 + ps0;
        l1 = l1 * rs1 + ps1;

#pragma unroll
        for (int nt = 0; nt < 8; nt++) {
            o[nt][0] *= rs0; o[nt][1] *= rs0;
            o[nt][2] *= rs1; o[nt][3] *= rs1;
        }

        // ---- O += P V (hi/lo de-interleaved) ----
#pragma unroll
        for (int kt = 0; kt < 4; kt++) {
            uint32_t phi[4], plo[4], vh4[4][4];
            packhl_h(s[2 * kt][0],     s[2 * kt][1],     phi[0], plo[0]);
            packhl_h(s[2 * kt][2],     s[2 * kt][3],     phi[1], plo[1]);
            packhl_h(s[2 * kt + 1][0], s[2 * kt + 1][1], phi[2], plo[2]);
            packhl_h(s[2 * kt + 1][2], s[2 * kt + 1][3], phi[3], plo[3]);
#pragma unroll
            for (int nt2 = 0; nt2 < 4; nt2++) {
                uint32_t va = sbase + ATT_VH + (kt * 16 + (lane & 15)) * 144
                            + (nt2 * 16 + (lane >> 4) * 8) * 2;
                ldsm4t(vh4[nt2], va);
            }
            // hi sweep
#pragma unroll
            for (int nt2 = 0; nt2 < 4; nt2++) {
                mma_f16(o[2 * nt2],     phi, vh4[nt2][0], vh4[nt2][1]);
                mma_f16(o[2 * nt2 + 1], phi, vh4[nt2][2], vh4[nt2][3]);
            }
            // lo sweep
#pragma unroll
            for (int nt2 = 0; nt2 < 4; nt2++) {
                mma_f16(o[2 * nt2],     plo, vh4[nt2][0], vh4[nt2][1]);
                mma_f16(o[2 * nt2 + 1], plo, vh4[nt2][2], vh4[nt2][3]);
            }
        }
    }

    // ---- epilogue: write ctx as fp16 hi/lo directly ----
    float inv0 = 1.0f / l0, inv1 = 1.0f / l1;
    size_t co0 = ((size_t)(b * SS + sq0)) * DD + h * DKK;
    size_t co1 = ((size_t)(b * SS + sq0 + 8)) * DD + h * DKK;
#pragma unroll
    for (int nt = 0; nt < 8; nt++) {
        int cc = 8 * nt + 2 * q4;
        uint32_t hp, lp;
        packhl_h(o[nt][0] * inv0, o[nt][1] * inv0, hp, lp);
        *(uint32_t*)(g_ctx_hi + co0 + cc) = hp;
        *(uint32_t*)(g_ctx_lo + co0 + cc) = lp;
        packhl_h(o[nt][2] * inv1, o[nt][3] * inv1, hp, lp);
        *(uint32_t*)(g_ctx_hi + co1 + cc) = hp;
        *(uint32_t*)(g_ctx_lo + co1 + cc) = lp;
    }
}

// ---------------- launch ----------------
extern "C" void kernel_launch(void* const* d_in, const int* in_sizes, int n_in,
                              void* d_out, int out_size) {
    const float* hs   = (const float*)d_in[0];
    const float* Wq   = (const float*)d_in[1];
    const float* Wk   = (const float*)d_in[2];
    const float* Wv   = (const float*)d_in[3];
    const float* Wo   = (const float*)d_in[4];
    const float* relb = (const float*)d_in[5];
    const float* grel = (const float*)d_in[6];
    const float* gln  = (const float*)d_in[7];
    const int*   mask = (const int*)d_in[8];
    float* out = (float*)d_out;

    float *p_qkv, *p_skv, *p_gi;
    cudaGetSymbolAddress((void**)&p_qkv, g_qkv);
    cudaGetSymbolAddress((void**)&p_skv, g_skv);
    cudaGetSymbolAddress((void**)&p_gi,  g_gi);

    __half *hs_hi, *hs_lo, *ctx_hi, *ctx_lo, *gi_hi, *gi_lo, *wqkv, *wo;
    cudaGetSymbolAddress((void**)&hs_hi,  g_hs_hi);
    cudaGetSymbolAddress((void**)&hs_lo,  g_hs_lo);
    cudaGetSymbolAddress((void**)&ctx_hi, g_ctx_hi);
    cudaGetSymbolAddress((void**)&ctx_lo, g_ctx_lo);
    cudaGetSymbolAddress((void**)&gi_hi,  g_gi_hi);
    cudaGetSymbolAddress((void**)&gi_lo,  g_gi_lo);
    cudaGetSymbolAddress((void**)&wqkv,   g_wqkv);
    cudaGetSymbolAddress((void**)&wo,     g_wo);

    cudaFuncSetAttribute(bgemm, cudaFuncAttributeMaxDynamicSharedMemorySize, BGE_SMEM_BYTES);
    cudaFuncSetAttribute(k_attn, cudaFuncAttributeMaxDynamicSharedMemorySize, ATT_SMEM);

    const int NHS4 = BB * SS * DD / 4;
    const int NW4  = DD * DD / 4;
    const int NGI4 = BB * GLL * DD / 4;

    // #1..#3: prerequisites for the big QKV GEMM
    k_cvt_qkvw<<<(3 * NW4 + 255) / 256, 256>>>((const float4*)Wq, (const float4*)Wk,
                                               (const float4*)Wv, (uint2*)wqkv);
    k_split<<<(NHS4 + 255) / 256, 256>>>((const float4*)hs, (uint2*)hs_hi, (uint2*)hs_lo, NHS4);
    k_block_ids<<<BB, 256>>>(mask);

    // #4: fused QKV GEMM (profiled slot)
    bgemm<<<dim3(3 * DD / 128, (BB * SS) / 128), 256, BGE_SMEM_BYTES>>>(
        hs_hi, hs_lo, DD, wqkv, 3 * DD, p_qkv, 3 * DD, DD);

    // global path
    k_global_agg<<<dim3(GLL, BB), 256>>>(hs, gln);
    k_split<<<(NGI4 + 255) / 256, 256>>>((const float4*)p_gi, (uint2*)gi_hi, (uint2*)gi_lo, NGI4);
    bgemm<<<dim3(2 * DD / 128, (BB * GLL) / 128), 256, BGE_SMEM_BYTES>>>(
        gi_hi, gi_lo, DD, wqkv + DD, 3 * DD, p_skv, 2 * DD, DD);

    // bias tables + Wo convert
    k_pgtab<<<(HH * 512 + 255) / 256, 256>>>(relb, grel);
    k_cvt_w<<<(NW4 + 255) / 256, 256>>>((const float4*)Wo, (uint2*)wo, NW4);

    // attention (tensor-core, fp16 2-term, occ 2, de-interleaved)
    k_attn<<<dim3(HH, SS / BLL, BB), 256, ATT_SMEM>>>(mask);

    // output projection (reads ctx hi/lo written by attention)
    bgemm<<<dim3(DD / 128, (BB * SS) / 128), 256, BGE_SMEM_BYTES>>>(
        ctx_hi, ctx_lo, DD, wo, DD, out, DD, DD);
}

// round 13
// speedup vs baseline: 1.4685x; 1.0078x over previous
#include <cuda_runtime.h>
#include <cuda_bf16.h>
#include <cuda_fp16.h>
#include <cstdint>
#include <math.h>

#define BB   2
#define SS   4096
#define DD   1024
#define HH   16
#define DKK  64
#define BLL  128
#define GG   16
#define GLL  256
#define NBUCK 32
#define NEGV (-1e10f)
#define SROW (SS + GLL)

// ---------------- scratch (device globals: allocation-free) ----------------
__device__ float g_qkv[BB*SS*3*DD];    // [row][q|k|v]
__device__ float g_skv[BB*GLL*2*DD];   // [row][sk|sv]
__device__ float g_gi [BB*GLL*DD];
__device__ float g_pb [HH*512];
__device__ float g_gb [HH*512];
__device__ int   g_bid [BB*SS];
__device__ int   g_gseg[BB*GLL];
__device__ int   g_full[BB];

// fp16 split buffers: activations hi/lo, weights single
__device__ __half g_hs_hi  [BB*SS*DD];
__device__ __half g_hs_lo  [BB*SS*DD];
__device__ __half g_ctx_hi [BB*SS*DD];
__device__ __half g_ctx_lo [BB*SS*DD];
__device__ __half g_gi_hi  [BB*GLL*DD];
__device__ __half g_gi_lo  [BB*GLL*DD];
__device__ __half g_wqkv   [DD*3*DD];
__device__ __half g_wo     [DD*DD];
// pre-split attention K/V (single fp16): rows [0,SS) local, [SS,SS+GLL) side
__device__ __half g_kat    [BB*SROW*DD];
__device__ __half g_vat    [BB*SROW*DD];

// ---------------- helpers ----------------
__device__ __forceinline__ uint32_t smem_u32(const void* p) {
    uint32_t a;
    asm("{ .reg .u64 t; cvta.to.shared.u64 t, %1; cvt.u32.u64 %0, t; }" : "=r"(a) : "l"(p));
    return a;
}

#define CP16(dst, src) asm volatile("cp.async.cg.shared.global [%0], [%1], 16;" :: "r"(dst), "l"(src) : "memory")
#define CP_COMMIT()    asm volatile("cp.async.commit_group;" ::: "memory")
#define CP_WAIT0()     asm volatile("cp.async.wait_group 0;" ::: "memory")

__device__ __forceinline__ void ldsm4(uint32_t* r, uint32_t a) {
    asm volatile("ldmatrix.sync.aligned.m8n8.x4.shared.b16 {%0,%1,%2,%3}, [%4];"
        : "=r"(r[0]), "=r"(r[1]), "=r"(r[2]), "=r"(r[3]) : "r"(a));
}
__device__ __forceinline__ void ldsm4t(uint32_t* r, uint32_t a) {
    asm volatile("ldmatrix.sync.aligned.m8n8.x4.trans.shared.b16 {%0,%1,%2,%3}, [%4];"
        : "=r"(r[0]), "=r"(r[1]), "=r"(r[2]), "=r"(r[3]) : "r"(a));
}
__device__ __forceinline__ void mma_f16(float* d, const uint32_t* a, uint32_t b0, uint32_t b1) {
    asm volatile("mma.sync.aligned.m16n8k16.row.col.f32.f16.f16.f32 "
        "{%0,%1,%2,%3}, {%4,%5,%6,%7}, {%8,%9}, {%0,%1,%2,%3};"
        : "+f"(d[0]), "+f"(d[1]), "+f"(d[2]), "+f"(d[3])
        : "r"(a[0]), "r"(a[1]), "r"(a[2]), "r"(a[3]), "r"(b0), "r"(b1));
}

__device__ __forceinline__ void split4h(float4 a, uint2& h, uint2& l) {
    __half2 h01 = __floats2half2_rn(a.x, a.y);
    __half2 h23 = __floats2half2_rn(a.z, a.w);
    float l0 = a.x - __half2float(__low2half(h01));
    float l1 = a.y - __half2float(__high2half(h01));
    float l2 = a.z - __half2float(__low2half(h23));
    float l3 = a.w - __half2float(__high2half(h23));
    __half2 q01 = __floats2half2_rn(l0, l1);
    __half2 q23 = __floats2half2_rn(l2, l3);
    h = make_uint2(*(uint32_t*)&h01, *(uint32_t*)&h23);
    l = make_uint2(*(uint32_t*)&q01, *(uint32_t*)&q23);
}

__device__ __forceinline__ uint2 cvt4h(float4 a) {
    __half2 h01 = __floats2half2_rn(a.x, a.y);
    __half2 h23 = __floats2half2_rn(a.z, a.w);
    return make_uint2(*(uint32_t*)&h01, *(uint32_t*)&h23);
}

__device__ __forceinline__ void packhl_h(float a, float b, uint32_t& hp, uint32_t& lp) {
    __half2 hv = __floats2half2_rn(a, b);
    __half2 lv = __floats2half2_rn(a - __half2float(__low2half(hv)),
                                   b - __half2float(__high2half(hv)));
    hp = *(uint32_t*)&hv;
    lp = *(uint32_t*)&lv;
}

// ---------------- fp32 -> fp16 hi/lo split (activations) ----------------
__global__ void k_split(const float4* __restrict__ src,
                        uint2* __restrict__ hi, uint2* __restrict__ lo, int n4) {
    int i = blockIdx.x * 256 + threadIdx.x;
    if (i >= n4) return;
    uint2 h, l;
    split4h(src[i], h, l);
    hi[i] = h; lo[i] = l;
}

// ---- weight conversions (single fp16) ----
__global__ void k_cvt_w(const float4* __restrict__ src, uint2* __restrict__ dst, int n4) {
    int i = blockIdx.x * 256 + threadIdx.x;
    if (i >= n4) return;
    dst[i] = cvt4h(src[i]);
}

__global__ void k_cvt_qkvw(const float4* __restrict__ Wq, const float4* __restrict__ Wk,
                           const float4* __restrict__ Wv, uint2* __restrict__ dst) {
    const int NW4 = DD * DD / 4;
    int idx = blockIdx.x * 256 + threadIdx.x;
    if (idx >= 3 * NW4) return;
    int i = idx / NW4;
    int r = idx % NW4;
    int k  = r >> 8;
    int n4 = r & 255;
    const float4* src = (i == 0) ? Wq : (i == 1) ? Wk : Wv;
    dst[k * (3 * DD / 4) + i * (DD / 4) + n4] = cvt4h(src[r]);
}

// ---- attention K/V pre-split (single fp16, unified rows) ----
__global__ void k_split_kv() {
    const int N4 = BB * SROW * DD / 4;
    int i4 = blockIdx.x * 256 + threadIdx.x;
    if (i4 >= N4) return;
    int c4  = (i4 & (DD / 4 - 1)) * 4;
    int row = i4 / (DD / 4);
    int b = row / SROW;
    int r = row % SROW;
    const float *kp, *vp;
    if (r < SS) {
        const float* base = g_qkv + ((size_t)(b * SS + r)) * (3 * DD) + c4;
        kp = base + DD; vp = base + 2 * DD;
    } else {
        const float* base = g_skv + ((size_t)(b * GLL + (r - SS))) * (2 * DD) + c4;
        kp = base; vp = base + DD;
    }
    size_t d = (size_t)row * DD + c4;
    *(uint2*)(g_kat + d) = cvt4h(*(const float4*)kp);
    *(uint2*)(g_vat + d) = cvt4h(*(const float4*)vp);
}

// ============ fp16 2-term GEMM, BK=64, 2-stage (unchanged from R12) ========
#define SH_A0   0
#define SH_A1   9216
#define SH_B0   18432
#define SH_STG  27136
#define BGE_SMEM_BYTES (2 * SH_STG * 2)

__global__ __launch_bounds__(256, 2)
void bgemm(const __half* __restrict__ Ahi, const __half* __restrict__ Alo, int lda,
           const __half* __restrict__ Bh, int ldb,
           float* __restrict__ C, int ldc, int K) {
    extern __shared__ __half sh[];
    uint32_t sbase = smem_u32(sh);

    int tid = threadIdx.x;
    int wid = tid >> 5, lane = tid & 31;
    int wm = wid & 3, wn = wid >> 2;
    int bx = blockIdx.x, by = blockIdx.y;

    float acc[2][8][4];
#pragma unroll
    for (int mt = 0; mt < 2; mt++)
#pragma unroll
        for (int nt = 0; nt < 8; nt++)
#pragma unroll
            for (int j = 0; j < 4; j++) acc[mt][nt][j] = 0.f;

    auto load_stage = [&](int c, int stage) {
        int k0 = c * 64;
        uint32_t s0 = sbase + (uint32_t)(stage * SH_STG) * 2;
#pragma unroll
        for (int i = 0; i < 4; i++) {
            int idx = i * 256 + tid;
            int row = idx >> 3;
            int c8  = (idx & 7) * 8;
            size_t ga = (size_t)(by * 128 + row) * lda + k0 + c8;
            uint32_t d = s0 + (uint32_t)(row * 72 + c8) * 2;
            CP16(d, Ahi + ga);
            CP16(d + SH_A1 * 2, Alo + ga);
        }
#pragma unroll
        for (int i = 0; i < 4; i++) {
            int idx = i * 256 + tid;
            int row = idx >> 4;
            int c8  = (idx & 15) * 8;
            size_t gb = (size_t)(k0 + row) * ldb + bx * 128 + c8;
            CP16(s0 + (uint32_t)(SH_B0 + row * 136 + c8) * 2, Bh + gb);
        }
        CP_COMMIT();
    };

    int nch = K >> 6;
    load_stage(0, 0);
    for (int c = 0; c < nch; c++) {
        CP_WAIT0();
        __syncthreads();
        if (c + 1 < nch) load_stage(c + 1, (c + 1) & 1);
        uint32_t s0 = sbase + (uint32_t)((c & 1) * SH_STG) * 2;
#pragma unroll
        for (int ks = 0; ks < 4; ks++) {
            uint32_t ah[2][4], al[2][4], bh4[4][4];
#pragma unroll
            for (int mt = 0; mt < 2; mt++) {
                int row = wm * 32 + mt * 16 + (lane & 15);
                int col = ks * 16 + (lane >> 4) * 8;
                uint32_t a = s0 + (uint32_t)(row * 72 + col) * 2;
                ldsm4(ah[mt], a);
                ldsm4(al[mt], a + SH_A1 * 2);
            }
#pragma unroll
            for (int nt2 = 0; nt2 < 4; nt2++) {
                int krow = ks * 16 + (lane & 15);
                int ncol = wn * 64 + nt2 * 16 + (lane >> 4) * 8;
                ldsm4t(bh4[nt2], s0 + (uint32_t)(SH_B0 + krow * 136 + ncol) * 2);
            }
#pragma unroll
            for (int nt2 = 0; nt2 < 4; nt2++)
#pragma unroll
                for (int p = 0; p < 2; p++)
#pragma unroll
                    for (int mt = 0; mt < 2; mt++)
                        mma_f16(acc[mt][nt2 * 2 + p], ah[mt],
                                bh4[nt2][2 * p], bh4[nt2][2 * p + 1]);
#pragma unroll
            for (int nt2 = 0; nt2 < 4; nt2++)
#pragma unroll
                for (int p = 0; p < 2; p++)
#pragma unroll
                    for (int mt = 0; mt < 2; mt++)
                        mma_f16(acc[mt][nt2 * 2 + p], al[mt],
                                bh4[nt2][2 * p], bh4[nt2][2 * p + 1]);
        }
    }
    __syncthreads();

#pragma unroll
    for (int mt = 0; mt < 2; mt++) {
#pragma unroll
        for (int nt = 0; nt < 8; nt++) {
            int r  = by * 128 + wm * 32 + mt * 16 + (lane >> 2);
            int cc = bx * 128 + wn * 64 + nt * 8 + (lane & 3) * 2;
            *(float2*)&C[(size_t)r * ldc + cc] =
                make_float2(acc[mt][nt][0], acc[mt][nt][1]);
            *(float2*)&C[(size_t)(r + 8) * ldc + cc] =
                make_float2(acc[mt][nt][2], acc[mt][nt][3]);
        }
    }
}

// ---------------- T5 bidirectional relative bucket ----------------
__device__ __forceinline__ int rel_bucket(int rp) {
    int rb = (rp > 0) ? (NBUCK / 2) : 0;
    int a  = rp < 0 ? -rp : rp;
    if (a < 8) return rb + a;
    float rf = (float)a;
    int large = 8 + (int)(logf(rf * 0.125f) * (8.0f / 2.772588722239781f));
    if (large > 15) large = 15;
    return rb + large;
}

// ---------------- 1D bias tables ----------------
__global__ void k_pgtab(const float* __restrict__ relb, const float* __restrict__ grel) {
    int idx = blockIdx.x * 256 + threadIdx.x;
    if (idx >= HH * 512) return;
    int h = idx >> 9;
    int i = idx & 511;
    int rel = i - 255;
    int bk = rel_bucket(rel);
    g_pb[idx] = relb[bk * HH + h];
    g_gb[idx] = grel[bk * HH + h];
}

// ---------------- block ids / global segments ----------------
__global__ void k_block_ids(const int* __restrict__ mask) {
    int b = blockIdx.x;
    __shared__ int s_cnt, s_max;
    if (threadIdx.x == 0) { s_cnt = 0; s_max = -1; }
    __syncthreads();
    int lc = 0;
    for (int i = threadIdx.x; i < SS; i += blockDim.x)
        if (((i & (GG - 1)) == GG - 1) && mask[b * SS + i] != 0) lc++;
    atomicAdd(&s_cnt, lc);
    __syncthreads();
    int full = s_cnt - 1;
    int lm = -1;
    for (int i = threadIdx.x; i < SS; i += blockDim.x) {
        int id;
        if (mask[b * SS + i] != 0) { id = i / GG; if (id > full) id = full; }
        else id = -1;
        g_bid[b * SS + i] = id;
        if (id > lm) lm = id;
    }
    atomicMax(&s_max, lm);
    __syncthreads();
    for (int g = threadIdx.x; g < GLL; g += blockDim.x)
        g_gseg[b * GLL + g] = (g <= s_max) ? 1 : 0;
    if (threadIdx.x == 0) g_full[b] = full;
}

// ---------------- global aggregates + RMSNorm ----------------
__global__ void k_global_agg(const float* __restrict__ hs, const float* __restrict__ gln_w) {
    int g = blockIdx.x, b = blockIdx.y;
    int t = threadIdx.x;
    int full = g_full[b];
    float acc0 = 0.f, acc1 = 0.f, acc2 = 0.f, acc3 = 0.f;
    if (g <= full) {
        int s_begin = g * GG;
        int s_end   = (g == full) ? SS : (g + 1) * GG;
#pragma unroll 1
        for (int s = s_begin; s < s_end; s++) {
            if (g_bid[b * SS + s] == g) {
                const float* row = hs + ((size_t)(b * SS + s)) * DD;
                acc0 += row[t];
                acc1 += row[t + 256];
                acc2 += row[t + 512];
                acc3 += row[t + 768];
            }
        }
    }
    __shared__ float red[256];
    red[t] = acc0 * acc0 + acc1 * acc1 + acc2 * acc2 + acc3 * acc3;
    __syncthreads();
    for (int off = 128; off > 0; off >>= 1) {
        if (t < off) red[t] += red[t + off];
        __syncthreads();
    }
    float var = red[0] * (1.0f / (float)DD);
    float sc = rsqrtf(var + 1e-6f);
    float* out = g_gi + ((size_t)(b * GLL + g)) * DD;
    out[t]       = acc0 * sc * gln_w[t];
    out[t + 256] = acc1 * sc * gln_w[t + 256];
    out[t + 512] = acc2 * sc * gln_w[t + 512];
    out[t + 768] = acc3 * sc * gln_w[t + 768];
}

// ================= tensor-core attention =================
// fp16 2-term Q (regs) x single-fp16 K/V (cp.async double-buffered), 1 sync/chunk
#define ATT_ST0  0          // stage s at s*18432: K[64x72h] then V[64x72h]
#define ATT_PB   36864
#define ATT_GB   38912
#define ATT_KVAL 40960      // 2 x 64 ints
#define ATT_GSEG 41472
#define ATT_SMEM 42496

__global__ __launch_bounds__(256, 2)
void k_attn(const int* __restrict__ mask) {
    extern __shared__ char sm[];
    uint32_t sbase = smem_u32(sm);
    int h = blockIdx.x, n = blockIdx.y, b = blockIdx.z;
    int tid = threadIdx.x;
    int w = tid >> 5, lane = tid & 31;
    int g4 = lane >> 2, q4 = lane & 3;

    // ---- stage Q (fp16 hi/lo) transiently into [0,36864) ----
#pragma unroll
    for (int i = 0; i < 8; i++) {
        int f4 = i * 256 + tid;
        int row = f4 >> 4;
        int c4 = (f4 & 15) * 4;
        const float* qp = g_qkv + ((size_t)(b * SS + n * BLL + row)) * (3 * DD) + h * DKK + c4;
        uint2 qh, ql;
        split4h(*(const float4*)qp, qh, ql);
        uint32_t off = row * 144 + c4 * 2;
        *(uint2*)(sm + off)         = qh;
        *(uint2*)(sm + 18432 + off) = ql;
    }
    ((float*)(sm + ATT_PB))[tid]       = g_pb[h * 512 + tid];
    ((float*)(sm + ATT_PB))[tid + 256] = g_pb[h * 512 + tid + 256];
    ((float*)(sm + ATT_GB))[tid]       = g_gb[h * 512 + tid];
    ((float*)(sm + ATT_GB))[tid + 256] = g_gb[h * 512 + tid + 256];
    ((int*)(sm + ATT_GSEG))[tid]       = g_gseg[b * GLL + tid];
    __syncthreads();

    // ---- Q fragments into registers ----
    uint32_t qfh[4][4], qfl[4][4];
#pragma unroll
    for (int kt = 0; kt < 4; kt++) {
        uint32_t qa = sbase + (w * 16 + (lane & 15)) * 144 + (kt * 16 + (lane >> 4) * 8) * 2;
        ldsm4(qfh[kt], qa);
        ldsm4(qfl[kt], qa + 18432);
    }
    __syncthreads();   // all warps done reading transient Q before K/V cp.async lands there

    int r0  = w * 16 + g4;
    int sq0 = n * BLL + r0;
    int mq0 = mask[b * SS + sq0], mq1 = mask[b * SS + sq0 + 8];
    int bid0 = g_bid[b * SS + sq0], bid1 = g_bid[b * SS + sq0 + 8];

    const float* pb_s   = (const float*)(sm + ATT_PB);
    const float* gb_s   = (const float*)(sm + ATT_GB);
    const int*   kval_s = (const int*)(sm + ATT_KVAL);
    const int*   gseg_s = (const int*)(sm + ATT_GSEG);

    // cp.async staging of pre-split K/V (64 keys): 1024 CP16 per chunk
    auto stage = [&](int c, int buf) {
        uint32_t sb = sbase + (uint32_t)buf * 18432;
#pragma unroll
        for (int i = 0; i < 4; i++) {
            int idx = i * 256 + tid;          // 0..1023
            int isV = idx >> 9;               // first 512: K, next 512: V
            int r   = (idx >> 3) & 63;
            int c8  = (idx & 7) * 8;
            int srcrow;
            if (c < 6) {
                int t = (n - 1) * BLL + c * 64 + r;
                srcrow = min(max(t, 0), SS - 1);
            } else {
                srcrow = SS + (c - 6) * 64 + r;
            }
            size_t goff = ((size_t)(b * SROW + srcrow)) * DD + h * DKK + c8;
            uint32_t dst = sb + (uint32_t)(isV * 9216 + r * 144 + c8 * 2);
            CP16(dst, (isV ? g_vat : g_kat) + goff);
        }
        CP_COMMIT();
        if (c < 6 && tid < 64) {
            int t = (n - 1) * BLL + c * 64 + tid;
            ((int*)(sm + ATT_KVAL))[buf * 64 + tid] = (t >= 0 && t < SS) ? mask[b * SS + t] : 0;
        }
    };

    float o[8][4];
#pragma unroll
    for (int nt = 0; nt < 8; nt++)
#pragma unroll
        for (int j = 0; j < 4; j++) o[nt][j] = 0.f;
    float m0 = -1e30f, m1 = -1e30f, l0 = 0.f, l1 = 0.f;

    stage(0, 0);
    for (int c = 0; c < 10; c++) {
        int buf = c & 1;
        CP_WAIT0();
        __syncthreads();   // stage(c)+kval(c) visible; compute(c-1) retired
        if (c + 1 < 10) stage(c + 1, (c + 1) & 1);

        uint32_t kb = sbase + (uint32_t)buf * 18432;

        // ---- S = Q K^T ----
        float s[8][4];
#pragma unroll
        for (int nt = 0; nt < 8; nt++)
#pragma unroll
            for (int j = 0; j < 4; j++) s[nt][j] = 0.f;

#pragma unroll
        for (int kt = 0; kt < 4; kt++) {
            uint32_t kh4[4][4];
#pragma unroll
            for (int nt2 = 0; nt2 < 4; nt2++) {
                uint32_t ka = kb + (nt2 * 16 + (lane & 15)) * 144
                            + (kt * 16 + (lane >> 4) * 8) * 2;
                ldsm4(kh4[nt2], ka);
            }
#pragma unroll
            for (int nt2 = 0; nt2 < 4; nt2++) {
                mma_f16(s[2 * nt2],     qfh[kt], kh4[nt2][0], kh4[nt2][2]);
                mma_f16(s[2 * nt2 + 1], qfh[kt], kh4[nt2][1], kh4[nt2][3]);
            }
#pragma unroll
            for (int nt2 = 0; nt2 < 4; nt2++) {
                mma_f16(s[2 * nt2],     qfl[kt], kh4[nt2][0], kh4[nt2][2]);
                mma_f16(s[2 * nt2 + 1], qfl[kt], kh4[nt2][1], kh4[nt2][3]);
            }
        }

        // ---- bias + mask ----
#pragma unroll
        for (int nt = 0; nt < 8; nt++) {
            int cn = 8 * nt + 2 * q4;
            if (c < 6) {
                int kv0 = kval_s[buf * 64 + cn], kv1 = kval_s[buf * 64 + cn + 1];
                int rel0 = c * 64 + cn - BLL - r0;
                int rel1 = rel0 - 8;
                s[nt][0] += pb_s[rel0 + 255] +
                    ((mq0 && kv0 && rel0 > -BLL && rel0 < BLL) ? 0.f : NEGV);
                s[nt][1] += pb_s[rel0 + 256] +
                    ((mq0 && kv1 && rel0 + 1 > -BLL && rel0 + 1 < BLL) ? 0.f : NEGV);
                s[nt][2] += pb_s[rel1 + 255] +
                    ((mq1 && kv0 && rel1 > -BLL && rel1 < BLL) ? 0.f : NEGV);
                s[nt][3] += pb_s[rel1 + 256] +
                    ((mq1 && kv1 && rel1 + 1 > -BLL && rel1 + 1 < BLL) ? 0.f : NEGV);
            } else {
                int g0 = (c - 6) * 64 + cn;
                int gs0 = gseg_s[g0], gs1 = gseg_s[g0 + 1];
                int sp0 = g0 - bid0, sp1 = g0 - bid1;
                s[nt][0] += gb_s[sp0 + 255] + ((mq0 == gs0) ? 0.f : NEGV);
                s[nt][1] += gb_s[sp0 + 256] + ((mq0 == gs1) ? 0.f : NEGV);
                s[nt][2] += gb_s[sp1 + 255] + ((mq1 == gs0) ? 0.f : NEGV);
                s[nt][3] += gb_s[sp1 + 256] + ((mq1 == gs1) ? 0.f : NEGV);
            }
        }

        // ---- online softmax ----
        float mx0 = -1e30f, mx1 = -1e30f;
#pragma unroll
        for (int nt = 0; nt < 8; nt++) {
            mx0 = fmaxf(mx0, fmaxf(s[nt][0], s[nt][1]));
            mx1 = fmaxf(mx1, fmaxf(s[nt][2], s[nt][3]));
        }
        mx0 = fmaxf(mx0, __shfl_xor_sync(0xFFFFFFFF, mx0, 1));
        mx0 = fmaxf(mx0, __shfl_xor_sync(0xFFFFFFFF, mx0, 2));
        mx1 = fmaxf(mx1, __shfl_xor_sync(0xFFFFFFFF, mx1, 1));
        mx1 = fmaxf(mx1, __shfl_xor_sync(0xFFFFFFFF, mx1, 2));
        float nm0 = fmaxf(m0, mx0), nm1 = fmaxf(m1, mx1);
        float rs0 = __expf(m0 - nm0), rs1 = __expf(m1 - nm1);
        m0 = nm0; m1 = nm1;

        float ps0 = 0.f, ps1 = 0.f;
#pragma unroll
        for (int nt = 0; nt < 8; nt++) {
            s[nt][0] = __expf(s[nt][0] - nm0); ps0 += s[nt][0];
            s[nt][1] = __expf(s[nt][1] - nm0); ps0 += s[nt][1];
            s[nt][2] = __expf(s[nt][2] - nm1); ps1 += s[nt][2];
            s[nt][3] = __expf(s[nt][3] - nm1); ps1 += s[nt][3];
        }
        ps0 += __shfl_xor_sync(0xFFFFFFFF, ps0, 1);
        ps0 += __shfl_xor_sync(0xFFFFFFFF, ps0, 2);
        ps1 += __shfl_xor_sync(0xFFFFFFFF, ps1, 1);
        ps1 += __shfl_xor_sync(0xFFFFFFFF, ps1, 2);
        l0 = l0 * rs0 + ps0;
        l1 = l1 * rs1 + ps1;

#pragma unroll
        for (int nt = 0; nt < 8; nt++) {
            o[nt][0] *= rs0; o[nt][1] *= rs0;
            o[nt][2] *= rs1; o[nt][3] *= rs1;
        }

        // ---- O += P V ----
#pragma unroll
        for (int kt = 0; kt < 4; kt++) {
            uint32_t phi[4], plo[4], vh4[4][4];
            packhl_h(s[2 * kt][0],     s[2 * kt][1],     phi[0], plo[0]);
            packhl_h(s[2 * kt][2],     s[2 * kt][3],     phi[1], plo[1]);
            packhl_h(s[2 * kt + 1][0], s[2 * kt + 1][1], phi[2], plo[2]);
            packhl_h(s[2 * kt + 1][2], s[2 * kt + 1][3], phi[3], plo[3]);
#pragma unroll
            for (int nt2 = 0; nt2 < 4; nt2++) {
                uint32_t va = kb + 9216 + (kt * 16 + (lane & 15)) * 144
                            + (nt2 * 16 + (lane >> 4) * 8) * 2;
                ldsm4t(vh4[nt2], va);
            }
#pragma unroll
            for (int nt2 = 0; nt2 < 4; nt2++) {
                mma_f16(o[2 * nt2],     phi, vh4[nt2][0], vh4[nt2][1]);
                mma_f16(o[2 * nt2 + 1], phi, vh4[nt2][2], vh4[nt2][3]);
            }
#pragma unroll
            for (int nt2 = 0; nt2 < 4; nt2++) {
                mma_f16(o[2 * nt2],     plo, vh4[nt2][0], vh4[nt2][1]);
                mma_f16(o[2 * nt2 + 1], plo, vh4[nt2][2], vh4[nt2][3]);
            }
        }
    }

    // ---- epilogue: write ctx as fp16 hi/lo directly ----
    float inv0 = 1.0f / l0, inv1 = 1.0f / l1;
    size_t co0 = ((size_t)(b * SS + sq0)) * DD + h * DKK;
    size_t co1 = ((size_t)(b * SS + sq0 + 8)) * DD + h * DKK;
#pragma unroll
    for (int nt = 0; nt < 8; nt++) {
        int cc = 8 * nt + 2 * q4;
        uint32_t hp, lp;
        packhl_h(o[nt][0] * inv0, o[nt][1] * inv0, hp, lp);
        *(uint32_t*)(g_ctx_hi + co0 + cc) = hp;
        *(uint32_t*)(g_ctx_lo + co0 + cc) = lp;
        packhl_h(o[nt][2] * inv1, o[nt][3] * inv1, hp, lp);
        *(uint32_t*)(g_ctx_hi + co1 + cc) = hp;
        *(uint32_t*)(g_ctx_lo + co1 + cc) = lp;
    }
}

// ---------------- launch ----------------
extern "C" void kernel_launch(void* const* d_in, const int* in_sizes, int n_in,
                              void* d_out, int out_size) {
    const float* hs   = (const float*)d_in[0];
    const float* Wq   = (const float*)d_in[1];
    const float* Wk   = (const float*)d_in[2];
    const float* Wv   = (const float*)d_in[3];
    const float* Wo   = (const float*)d_in[4];
    const float* relb = (const float*)d_in[5];
    const float* grel = (const float*)d_in[6];
    const float* gln  = (const float*)d_in[7];
    const int*   mask = (const int*)d_in[8];
    float* out = (float*)d_out;

    float *p_qkv, *p_skv, *p_gi;
    cudaGetSymbolAddress((void**)&p_qkv, g_qkv);
    cudaGetSymbolAddress((void**)&p_skv, g_skv);
    cudaGetSymbolAddress((void**)&p_gi,  g_gi);

    __half *hs_hi, *hs_lo, *ctx_hi, *ctx_lo, *gi_hi, *gi_lo, *wqkv, *wo;
    cudaGetSymbolAddress((void**)&hs_hi,  g_hs_hi);
    cudaGetSymbolAddress((void**)&hs_lo,  g_hs_lo);
    cudaGetSymbolAddress((void**)&ctx_hi, g_ctx_hi);
    cudaGetSymbolAddress((void**)&ctx_lo, g_ctx_lo);
    cudaGetSymbolAddress((void**)&gi_hi,  g_gi_hi);
    cudaGetSymbolAddress((void**)&gi_lo,  g_gi_lo);
    cudaGetSymbolAddress((void**)&wqkv,   g_wqkv);
    cudaGetSymbolAddress((void**)&wo,     g_wo);

    cudaFuncSetAttribute(bgemm, cudaFuncAttributeMaxDynamicSharedMemorySize, BGE_SMEM_BYTES);
    cudaFuncSetAttribute(k_attn, cudaFuncAttributeMaxDynamicSharedMemorySize, ATT_SMEM);

    const int NHS4 = BB * SS * DD / 4;
    const int NW4  = DD * DD / 4;
    const int NGI4 = BB * GLL * DD / 4;
    const int NKV4 = BB * SROW * DD / 4;

    // #1..#3: prerequisites for the big QKV GEMM
    k_cvt_qkvw<<<(3 * NW4 + 255) / 256, 256>>>((const float4*)Wq, (const float4*)Wk,
                                               (const float4*)Wv, (uint2*)wqkv);
    k_split<<<(NHS4 + 255) / 256, 256>>>((const float4*)hs, (uint2*)hs_hi, (uint2*)hs_lo, NHS4);
    k_block_ids<<<BB, 256>>>(mask);

    // #4: fused QKV GEMM (profiled slot)
    bgemm<<<dim3(3 * DD / 128, (BB * SS) / 128), 256, BGE_SMEM_BYTES>>>(
        hs_hi, hs_lo, DD, wqkv, 3 * DD, p_qkv, 3 * DD, DD);

    // global path
    k_global_agg<<<dim3(GLL, BB), 256>>>(hs, gln);
    k_split<<<(NGI4 + 255) / 256, 256>>>((const float4*)p_gi, (uint2*)gi_hi, (uint2*)gi_lo, NGI4);
    bgemm<<<dim3(2 * DD / 128, (BB * GLL) / 128), 256, BGE_SMEM_BYTES>>>(
        gi_hi, gi_lo, DD, wqkv + DD, 3 * DD, p_skv, 2 * DD, DD);

    // pre-split K/V for attention
    k_split_kv<<<(NKV4 + 255) / 256, 256>>>();

    // bias tables + Wo convert
    k_pgtab<<<(HH * 512 + 255) / 256, 256>>>(relb, grel);
    k_cvt_w<<<(NW4 + 255) / 256, 256>>>((const float4*)Wo, (uint2*)wo, NW4);

    // attention (tensor-core, cp.async double-buffered, 1 sync/chunk)
    k_attn<<<dim3(HH, SS / BLL, BB), 256, ATT_SMEM>>>(mask);

    // output projection (reads ctx hi/lo written by attention)
    bgemm<<<dim3(DD / 128, (BB * SS) / 128), 256, BGE_SMEM_BYTES>>>(
        ctx_hi, ctx_lo, DD, wo, DD, out, DD, DD);
}

// round 14
// speedup vs baseline: 1.6059x; 1.0936x over previous
#include <cuda_runtime.h>
#include <cuda_bf16.h>
#include <cuda_fp16.h>
#include <cstdint>
#include <math.h>

#define BB   2
#define SS   4096
#define DD   1024
#define HH   16
#define DKK  64
#define BLL  128
#define GG   16
#define GLL  256
#define NBUCK 32
#define NEGV (-1e10f)
#define SROW (SS + GLL)

// ---------------- scratch (device globals: allocation-free) ----------------
__device__ float g_pb [HH*512];
__device__ float g_gb [HH*512];
__device__ int   g_bid [BB*SS];
__device__ int   g_gseg[BB*GLL];
__device__ int   g_full[BB];

// fp16 buffers
__device__ __half g_hs_hi  [BB*SS*DD];
__device__ __half g_hs_lo  [BB*SS*DD];
__device__ __half g_q_hi   [BB*SS*DD];
__device__ __half g_q_lo   [BB*SS*DD];
__device__ __half g_ctx_hi [BB*SS*DD];
__device__ __half g_ctx_lo [BB*SS*DD];
__device__ __half g_gi_hi  [BB*GLL*DD];
__device__ __half g_gi_lo  [BB*GLL*DD];
__device__ __half g_wqkv   [DD*3*DD];
__device__ __half g_wo     [DD*DD];
// attention K/V (single fp16): rows [0,SS) local, [SS,SS+GLL) side
__device__ __half g_kat    [BB*SROW*DD];
__device__ __half g_vat    [BB*SROW*DD];

// ---------------- helpers ----------------
__device__ __forceinline__ uint32_t smem_u32(const void* p) {
    uint32_t a;
    asm("{ .reg .u64 t; cvta.to.shared.u64 t, %1; cvt.u32.u64 %0, t; }" : "=r"(a) : "l"(p));
    return a;
}

#define CP16(dst, src) asm volatile("cp.async.cg.shared.global [%0], [%1], 16;" :: "r"(dst), "l"(src) : "memory")
#define CP_COMMIT()    asm volatile("cp.async.commit_group;" ::: "memory")
#define CP_WAIT0()     asm volatile("cp.async.wait_group 0;" ::: "memory")

__device__ __forceinline__ void ldsm4(uint32_t* r, uint32_t a) {
    asm volatile("ldmatrix.sync.aligned.m8n8.x4.shared.b16 {%0,%1,%2,%3}, [%4];"
        : "=r"(r[0]), "=r"(r[1]), "=r"(r[2]), "=r"(r[3]) : "r"(a));
}
__device__ __forceinline__ void ldsm4t(uint32_t* r, uint32_t a) {
    asm volatile("ldmatrix.sync.aligned.m8n8.x4.trans.shared.b16 {%0,%1,%2,%3}, [%4];"
        : "=r"(r[0]), "=r"(r[1]), "=r"(r[2]), "=r"(r[3]) : "r"(a));
}
__device__ __forceinline__ void mma_f16(float* d, const uint32_t* a, uint32_t b0, uint32_t b1) {
    asm volatile("mma.sync.aligned.m16n8k16.row.col.f32.f16.f16.f32 "
        "{%0,%1,%2,%3}, {%4,%5,%6,%7}, {%8,%9}, {%0,%1,%2,%3};"
        : "+f"(d[0]), "+f"(d[1]), "+f"(d[2]), "+f"(d[3])
        : "r"(a[0]), "r"(a[1]), "r"(a[2]), "r"(a[3]), "r"(b0), "r"(b1));
}

__device__ __forceinline__ void split4h(float4 a, uint2& h, uint2& l) {
    __half2 h01 = __floats2half2_rn(a.x, a.y);
    __half2 h23 = __floats2half2_rn(a.z, a.w);
    float l0 = a.x - __half2float(__low2half(h01));
    float l1 = a.y - __half2float(__high2half(h01));
    float l2 = a.z - __half2float(__low2half(h23));
    float l3 = a.w - __half2float(__high2half(h23));
    __half2 q01 = __floats2half2_rn(l0, l1);
    __half2 q23 = __floats2half2_rn(l2, l3);
    h = make_uint2(*(uint32_t*)&h01, *(uint32_t*)&h23);
    l = make_uint2(*(uint32_t*)&q01, *(uint32_t*)&q23);
}

__device__ __forceinline__ uint2 cvt4h(float4 a) {
    __half2 h01 = __floats2half2_rn(a.x, a.y);
    __half2 h23 = __floats2half2_rn(a.z, a.w);
    return make_uint2(*(uint32_t*)&h01, *(uint32_t*)&h23);
}

__device__ __forceinline__ void packhl_h(float a, float b, uint32_t& hp, uint32_t& lp) {
    __half2 hv = __floats2half2_rn(a, b);
    __half2 lv = __floats2half2_rn(a - __half2float(__low2half(hv)),
                                   b - __half2float(__high2half(hv)));
    hp = *(uint32_t*)&hv;
    lp = *(uint32_t*)&lv;
}
__device__ __forceinline__ uint32_t pack2h(float a, float b) {
    __half2 hv = __floats2half2_rn(a, b);
    return *(uint32_t*)&hv;
}

// ---------------- fp32 -> fp16 hi/lo split (hs) ----------------
__global__ void k_split(const float4* __restrict__ src,
                        uint2* __restrict__ hi, uint2* __restrict__ lo, int n4) {
    int i = blockIdx.x * 256 + threadIdx.x;
    if (i >= n4) return;
    uint2 h, l;
    split4h(src[i], h, l);
    hi[i] = h; lo[i] = l;
}

// ---- weight conversions (single fp16) ----
__global__ void k_cvt_w(const float4* __restrict__ src, uint2* __restrict__ dst, int n4) {
    int i = blockIdx.x * 256 + threadIdx.x;
    if (i >= n4) return;
    dst[i] = cvt4h(src[i]);
}

__global__ void k_cvt_qkvw(const float4* __restrict__ Wq, const float4* __restrict__ Wk,
                           const float4* __restrict__ Wv, uint2* __restrict__ dst) {
    const int NW4 = DD * DD / 4;
    int idx = blockIdx.x * 256 + threadIdx.x;
    if (idx >= 3 * NW4) return;
    int i = idx / NW4;
    int r = idx % NW4;
    int k  = r >> 8;
    int n4 = r & 255;
    const float4* src = (i == 0) ? Wq : (i == 1) ? Wk : Wv;
    dst[k * (3 * DD / 4) + i * (DD / 4) + n4] = cvt4h(src[r]);
}

// ============ fp16 2-term GEMM, BK=64, 2-stage, fused-output epilogues ======
// mode 0: C fp32.  mode 1: QKV (Q->q_hi/lo, K->g_kat, V->g_vat).
// mode 2: skv (sk->g_kat rows SS+, sv->g_vat rows SS+).
#define SH_A0   0
#define SH_A1   9216
#define SH_B0   18432
#define SH_STG  27136
#define BGE_SMEM_BYTES (2 * SH_STG * 2)

__global__ __launch_bounds__(256, 2)
void bgemm(const __half* __restrict__ Ahi, const __half* __restrict__ Alo, int lda,
           const __half* __restrict__ Bh, int ldb,
           float* __restrict__ C, int ldc, int K, int mode) {
    extern __shared__ __half sh[];
    uint32_t sbase = smem_u32(sh);

    int tid = threadIdx.x;
    int wid = tid >> 5, lane = tid & 31;
    int wm = wid & 3, wn = wid >> 2;
    int bx = blockIdx.x, by = blockIdx.y;

    float acc[2][8][4];
#pragma unroll
    for (int mt = 0; mt < 2; mt++)
#pragma unroll
        for (int nt = 0; nt < 8; nt++)
#pragma unroll
            for (int j = 0; j < 4; j++) acc[mt][nt][j] = 0.f;

    auto load_stage = [&](int c, int stage) {
        int k0 = c * 64;
        uint32_t s0 = sbase + (uint32_t)(stage * SH_STG) * 2;
#pragma unroll
        for (int i = 0; i < 4; i++) {
            int idx = i * 256 + tid;
            int row = idx >> 3;
            int c8  = (idx & 7) * 8;
            size_t ga = (size_t)(by * 128 + row) * lda + k0 + c8;
            uint32_t d = s0 + (uint32_t)(row * 72 + c8) * 2;
            CP16(d, Ahi + ga);
            CP16(d + SH_A1 * 2, Alo + ga);
        }
#pragma unroll
        for (int i = 0; i < 4; i++) {
            int idx = i * 256 + tid;
            int row = idx >> 4;
            int c8  = (idx & 15) * 8;
            size_t gb = (size_t)(k0 + row) * ldb + bx * 128 + c8;
            CP16(s0 + (uint32_t)(SH_B0 + row * 136 + c8) * 2, Bh + gb);
        }
        CP_COMMIT();
    };

    int nch = K >> 6;
    load_stage(0, 0);
    for (int c = 0; c < nch; c++) {
        CP_WAIT0();
        __syncthreads();
        if (c + 1 < nch) load_stage(c + 1, (c + 1) & 1);
        uint32_t s0 = sbase + (uint32_t)((c & 1) * SH_STG) * 2;
#pragma unroll
        for (int ks = 0; ks < 4; ks++) {
            uint32_t ah[2][4], al[2][4], bh4[4][4];
#pragma unroll
            for (int mt = 0; mt < 2; mt++) {
                int row = wm * 32 + mt * 16 + (lane & 15);
                int col = ks * 16 + (lane >> 4) * 8;
                uint32_t a = s0 + (uint32_t)(row * 72 + col) * 2;
                ldsm4(ah[mt], a);
                ldsm4(al[mt], a + SH_A1 * 2);
            }
#pragma unroll
            for (int nt2 = 0; nt2 < 4; nt2++) {
                int krow = ks * 16 + (lane & 15);
                int ncol = wn * 64 + nt2 * 16 + (lane >> 4) * 8;
                ldsm4t(bh4[nt2], s0 + (uint32_t)(SH_B0 + krow * 136 + ncol) * 2);
            }
#pragma unroll
            for (int nt2 = 0; nt2 < 4; nt2++)
#pragma unroll
                for (int p = 0; p < 2; p++)
#pragma unroll
                    for (int mt = 0; mt < 2; mt++)
                        mma_f16(acc[mt][nt2 * 2 + p], ah[mt],
                                bh4[nt2][2 * p], bh4[nt2][2 * p + 1]);
#pragma unroll
            for (int nt2 = 0; nt2 < 4; nt2++)
#pragma unroll
                for (int p = 0; p < 2; p++)
#pragma unroll
                    for (int mt = 0; mt < 2; mt++)
                        mma_f16(acc[mt][nt2 * 2 + p], al[mt],
                                bh4[nt2][2 * p], bh4[nt2][2 * p + 1]);
        }
    }
    __syncthreads();

    if (mode == 0) {
#pragma unroll
        for (int mt = 0; mt < 2; mt++) {
#pragma unroll
            for (int nt = 0; nt < 8; nt++) {
                int r  = by * 128 + wm * 32 + mt * 16 + (lane >> 2);
                int cc = bx * 128 + wn * 64 + nt * 8 + (lane & 3) * 2;
                *(float2*)&C[(size_t)r * ldc + cc] =
                    make_float2(acc[mt][nt][0], acc[mt][nt][1]);
                *(float2*)&C[(size_t)(r + 8) * ldc + cc] =
                    make_float2(acc[mt][nt][2], acc[mt][nt][3]);
            }
        }
    } else if (mode == 1) {
        int seg = bx >> 3;            // 0 Q, 1 K, 2 V
#pragma unroll
        for (int mt = 0; mt < 2; mt++) {
            int r  = by * 128 + wm * 32 + mt * 16 + (lane >> 2);
            int b  = r / SS, s2 = r % SS;        // rows r, r+8 share b (128 | SS)
#pragma unroll
            for (int nt = 0; nt < 8; nt++) {
                int cg  = bx * 128 + wn * 64 + nt * 8 + (lane & 3) * 2;
                int col = cg - seg * 1024;
                if (seg == 0) {
                    uint32_t hp, lp;
                    packhl_h(acc[mt][nt][0], acc[mt][nt][1], hp, lp);
                    *(uint32_t*)(g_q_hi + (size_t)r * DD + col) = hp;
                    *(uint32_t*)(g_q_lo + (size_t)r * DD + col) = lp;
                    packhl_h(acc[mt][nt][2], acc[mt][nt][3], hp, lp);
                    *(uint32_t*)(g_q_hi + (size_t)(r + 8) * DD + col) = hp;
                    *(uint32_t*)(g_q_lo + (size_t)(r + 8) * DD + col) = lp;
                } else {
                    __half* dst = (seg == 1) ? g_kat : g_vat;
                    size_t o0 = ((size_t)(b * SROW + s2)) * DD + col;
                    *(uint32_t*)(dst + o0) = pack2h(acc[mt][nt][0], acc[mt][nt][1]);
                    *(uint32_t*)(dst + o0 + 8 * DD) = pack2h(acc[mt][nt][2], acc[mt][nt][3]);
                }
            }
        }
    } else {   // mode 2: skv
        int seg = bx >> 3;            // 0 sk, 1 sv
        __half* dst = (seg == 0) ? g_kat : g_vat;
#pragma unroll
        for (int mt = 0; mt < 2; mt++) {
            int r  = by * 128 + wm * 32 + mt * 16 + (lane >> 2);
            int b  = r / GLL, gI = r % GLL;      // rows r, r+8: GLL=256, 128-blocks stay in b
#pragma unroll
            for (int nt = 0; nt < 8; nt++) {
                int cg  = bx * 128 + wn * 64 + nt * 8 + (lane & 3) * 2;
                int col = cg - seg * 1024;
                size_t o0 = ((size_t)(b * SROW + SS + gI)) * DD + col;
                *(uint32_t*)(dst + o0) = pack2h(acc[mt][nt][0], acc[mt][nt][1]);
                *(uint32_t*)(dst + o0 + 8 * DD) = pack2h(acc[mt][nt][2], acc[mt][nt][3]);
            }
        }
    }
}

// ---------------- T5 bidirectional relative bucket ----------------
__device__ __forceinline__ int rel_bucket(int rp) {
    int rb = (rp > 0) ? (NBUCK / 2) : 0;
    int a  = rp < 0 ? -rp : rp;
    if (a < 8) return rb + a;
    float rf = (float)a;
    int large = 8 + (int)(logf(rf * 0.125f) * (8.0f / 2.772588722239781f));
    if (large > 15) large = 15;
    return rb + large;
}

// ---------------- 1D bias tables ----------------
__global__ void k_pgtab(const float* __restrict__ relb, const float* __restrict__ grel) {
    int idx = blockIdx.x * 256 + threadIdx.x;
    if (idx >= HH * 512) return;
    int h = idx >> 9;
    int i = idx & 511;
    int rel = i - 255;
    int bk = rel_bucket(rel);
    g_pb[idx] = relb[bk * HH + h];
    g_gb[idx] = grel[bk * HH + h];
}

// ---------------- block ids / global segments ----------------
__global__ void k_block_ids(const int* __restrict__ mask) {
    int b = blockIdx.x;
    __shared__ int s_cnt, s_max;
    if (threadIdx.x == 0) { s_cnt = 0; s_max = -1; }
    __syncthreads();
    int lc = 0;
    for (int i = threadIdx.x; i < SS; i += blockDim.x)
        if (((i & (GG - 1)) == GG - 1) && mask[b * SS + i] != 0) lc++;
    atomicAdd(&s_cnt, lc);
    __syncthreads();
    int full = s_cnt - 1;
    int lm = -1;
    for (int i = threadIdx.x; i < SS; i += blockDim.x) {
        int id;
        if (mask[b * SS + i] != 0) { id = i / GG; if (id > full) id = full; }
        else id = -1;
        g_bid[b * SS + i] = id;
        if (id > lm) lm = id;
    }
    atomicMax(&s_max, lm);
    __syncthreads();
    for (int g = threadIdx.x; g < GLL; g += blockDim.x)
        g_gseg[b * GLL + g] = (g <= s_max) ? 1 : 0;
    if (threadIdx.x == 0) g_full[b] = full;
}

// ---------------- global aggregates + RMSNorm -> gi hi/lo directly ---------
__global__ void k_global_agg(const float* __restrict__ hs, const float* __restrict__ gln_w) {
    int g = blockIdx.x, b = blockIdx.y;
    int t = threadIdx.x;
    int full = g_full[b];
    float acc0 = 0.f, acc1 = 0.f, acc2 = 0.f, acc3 = 0.f;
    if (g <= full) {
        int s_begin = g * GG;
        int s_end   = (g == full) ? SS : (g + 1) * GG;
#pragma unroll 1
        for (int s = s_begin; s < s_end; s++) {
            if (g_bid[b * SS + s] == g) {
                const float* row = hs + ((size_t)(b * SS + s)) * DD;
                acc0 += row[t];
                acc1 += row[t + 256];
                acc2 += row[t + 512];
                acc3 += row[t + 768];
            }
        }
    }
    __shared__ float red[256];
    red[t] = acc0 * acc0 + acc1 * acc1 + acc2 * acc2 + acc3 * acc3;
    __syncthreads();
    for (int off = 128; off > 0; off >>= 1) {
        if (t < off) red[t] += red[t + off];
        __syncthreads();
    }
    float var = red[0] * (1.0f / (float)DD);
    float sc = rsqrtf(var + 1e-6f);
    size_t base = ((size_t)(b * GLL + g)) * DD;
    float vals[4] = {acc0 * sc * gln_w[t], acc1 * sc * gln_w[t + 256],
                     acc2 * sc * gln_w[t + 512], acc3 * sc * gln_w[t + 768]};
#pragma unroll
    for (int j = 0; j < 4; j++) {
        float v = vals[j];
        __half hv = __float2half_rn(v);
        g_gi_hi[base + t + j * 256] = hv;
        g_gi_lo[base + t + j * 256] = __float2half_rn(v - __half2float(hv));
    }
}

// ================= tensor-core attention =================
// Q 2-term (regs) x K single; P single x V single. cp.async double-buffered.
#define ATT_PB   36864
#define ATT_GB   38912
#define ATT_KVAL 40960      // 2 x 64 ints
#define ATT_GSEG 41472
#define ATT_SMEM 42496

__global__ __launch_bounds__(256, 2)
void k_attn(const int* __restrict__ mask) {
    extern __shared__ char sm[];
    uint32_t sbase = smem_u32(sm);
    int h = blockIdx.x, n = blockIdx.y, b = blockIdx.z;
    int tid = threadIdx.x;
    int w = tid >> 5, lane = tid & 31;
    int g4 = lane >> 2, q4 = lane & 3;

    // ---- stage Q (pre-split hi/lo) transiently into [0,36864) via cp.async
#pragma unroll
    for (int i = 0; i < 4; i++) {
        int idx = i * 256 + tid;          // 0..1023
        int row = idx >> 3;
        int c8  = (idx & 7) * 8;
        size_t goff = ((size_t)(b * SS + n * BLL + row)) * DD + h * DKK + c8;
        uint32_t d = sbase + (uint32_t)(row * 144 + c8 * 2);
        CP16(d, g_q_hi + goff);
        CP16(d + 18432, g_q_lo + goff);
    }
    CP_COMMIT();
    ((float*)(sm + ATT_PB))[tid]       = g_pb[h * 512 + tid];
    ((float*)(sm + ATT_PB))[tid + 256] = g_pb[h * 512 + tid + 256];
    ((float*)(sm + ATT_GB))[tid]       = g_gb[h * 512 + tid];
    ((float*)(sm + ATT_GB))[tid + 256] = g_gb[h * 512 + tid + 256];
    ((int*)(sm + ATT_GSEG))[tid]       = g_gseg[b * GLL + tid];
    CP_WAIT0();
    __syncthreads();

    // ---- Q fragments into registers ----
    uint32_t qfh[4][4], qfl[4][4];
#pragma unroll
    for (int kt = 0; kt < 4; kt++) {
        uint32_t qa = sbase + (w * 16 + (lane & 15)) * 144 + (kt * 16 + (lane >> 4) * 8) * 2;
        ldsm4(qfh[kt], qa);
        ldsm4(qfl[kt], qa + 18432);
    }
    __syncthreads();   // all warps done reading transient Q before K/V lands there

    int r0  = w * 16 + g4;
    int sq0 = n * BLL + r0;
    int mq0 = mask[b * SS + sq0], mq1 = mask[b * SS + sq0 + 8];
    int bid0 = g_bid[b * SS + sq0], bid1 = g_bid[b * SS + sq0 + 8];

    const float* pb_s   = (const float*)(sm + ATT_PB);
    const float* gb_s   = (const float*)(sm + ATT_GB);
    const int*   kval_s = (const int*)(sm + ATT_KVAL);
    const int*   gseg_s = (const int*)(sm + ATT_GSEG);

    auto stage = [&](int c, int buf) {
        uint32_t sb = sbase + (uint32_t)buf * 18432;
#pragma unroll
        for (int i = 0; i < 4; i++) {
            int idx = i * 256 + tid;
            int isV = idx >> 9;
            int r   = (idx >> 3) & 63;
            int c8  = (idx & 7) * 8;
            int srcrow;
            if (c < 6) {
                int t = (n - 1) * BLL + c * 64 + r;
                srcrow = min(max(t, 0), SS - 1);
            } else {
                srcrow = SS + (c - 6) * 64 + r;
            }
            size_t goff = ((size_t)(b * SROW + srcrow)) * DD + h * DKK + c8;
            uint32_t dst = sb + (uint32_t)(isV * 9216 + r * 144 + c8 * 2);
            CP16(dst, (isV ? g_vat : g_kat) + goff);
        }
        CP_COMMIT();
        if (c < 6 && tid < 64) {
            int t = (n - 1) * BLL + c * 64 + tid;
            ((int*)(sm + ATT_KVAL))[buf * 64 + tid] = (t >= 0 && t < SS) ? mask[b * SS + t] : 0;
        }
    };

    float o[8][4];
#pragma unroll
    for (int nt = 0; nt < 8; nt++)
#pragma unroll
        for (int j = 0; j < 4; j++) o[nt][j] = 0.f;
    float m0 = -1e30f, m1 = -1e30f, l0 = 0.f, l1 = 0.f;

    stage(0, 0);
    for (int c = 0; c < 10; c++) {
        int buf = c & 1;
        CP_WAIT0();
        __syncthreads();
        if (c + 1 < 10) stage(c + 1, (c + 1) & 1);

        uint32_t kb = sbase + (uint32_t)buf * 18432;

        // ---- S = Q K^T (Q 2-term) ----
        float s[8][4];
#pragma unroll
        for (int nt = 0; nt < 8; nt++)
#pragma unroll
            for (int j = 0; j < 4; j++) s[nt][j] = 0.f;

#pragma unroll
        for (int kt = 0; kt < 4; kt++) {
            uint32_t kh4[4][4];
#pragma unroll
            for (int nt2 = 0; nt2 < 4; nt2++) {
                uint32_t ka = kb + (nt2 * 16 + (lane & 15)) * 144
                            + (kt * 16 + (lane >> 4) * 8) * 2;
                ldsm4(kh4[nt2], ka);
            }
#pragma unroll
            for (int nt2 = 0; nt2 < 4; nt2++) {
                mma_f16(s[2 * nt2],     qfh[kt], kh4[nt2][0], kh4[nt2][2]);
                mma_f16(s[2 * nt2 + 1], qfh[kt], kh4[nt2][1], kh4[nt2][3]);
            }
#pragma unroll
            for (int nt2 = 0; nt2 < 4; nt2++) {
                mma_f16(s[2 * nt2],     qfl[kt], kh4[nt2][0], kh4[nt2][2]);
                mma_f16(s[2 * nt2 + 1], qfl[kt], kh4[nt2][1], kh4[nt2][3]);
            }
        }

        // ---- bias + mask ----
#pragma unroll
        for (int nt = 0; nt < 8; nt++) {
            int cn = 8 * nt + 2 * q4;
            if (c < 6) {
                int kv0 = kval_s[buf * 64 + cn], kv1 = kval_s[buf * 64 + cn + 1];
                int rel0 = c * 64 + cn - BLL - r0;
                int rel1 = rel0 - 8;
                s[nt][0] += pb_s[rel0 + 255] +
                    ((mq0 && kv0 && rel0 > -BLL && rel0 < BLL) ? 0.f : NEGV);
                s[nt][1] += pb_s[rel0 + 256] +
                    ((mq0 && kv1 && rel0 + 1 > -BLL && rel0 + 1 < BLL) ? 0.f : NEGV);
                s[nt][2] += pb_s[rel1 + 255] +
                    ((mq1 && kv0 && rel1 > -BLL && rel1 < BLL) ? 0.f : NEGV);
                s[nt][3] += pb_s[rel1 + 256] +
                    ((mq1 && kv1 && rel1 + 1 > -BLL && rel1 + 1 < BLL) ? 0.f : NEGV);
            } else {
                int g0 = (c - 6) * 64 + cn;
                int gs0 = gseg_s[g0], gs1 = gseg_s[g0 + 1];
                int sp0 = g0 - bid0, sp1 = g0 - bid1;
                s[nt][0] += gb_s[sp0 + 255] + ((mq0 == gs0) ? 0.f : NEGV);
                s[nt][1] += gb_s[sp0 + 256] + ((mq0 == gs1) ? 0.f : NEGV);
                s[nt][2] += gb_s[sp1 + 255] + ((mq1 == gs0) ? 0.f : NEGV);
                s[nt][3] += gb_s[sp1 + 256] + ((mq1 == gs1) ? 0.f : NEGV);
            }
        }

        // ---- online softmax ----
        float mx0 = -1e30f, mx1 = -1e30f;
#pragma unroll
        for (int nt = 0; nt < 8; nt++) {
            mx0 = fmaxf(mx0, fmaxf(s[nt][0], s[nt][1]));
            mx1 = fmaxf(mx1, fmaxf(s[nt][2], s[nt][3]));
        }
        mx0 = fmaxf(mx0, __shfl_xor_sync(0xFFFFFFFF, mx0, 1));
        mx0 = fmaxf(mx0, __shfl_xor_sync(0xFFFFFFFF, mx0, 2));
        mx1 = fmaxf(mx1, __shfl_xor_sync(0xFFFFFFFF, mx1, 1));
        mx1 = fmaxf(mx1, __shfl_xor_sync(0xFFFFFFFF, mx1, 2));
        float nm0 = fmaxf(m0, mx0), nm1 = fmaxf(m1, mx1);
        float rs0 = __expf(m0 - nm0), rs1 = __expf(m1 - nm1);
        m0 = nm0; m1 = nm1;

        float ps0 = 0.f, ps1 = 0.f;
#pragma unroll
        for (int nt = 0; nt < 8; nt++) {
            s[nt][0] = __expf(s[nt][0] - nm0); ps0 += s[nt][0];
            s[nt][1] = __expf(s[nt][1] - nm0); ps0 += s[nt][1];
            s[nt][2] = __expf(s[nt][2] - nm1); ps1 += s[nt][2];
            s[nt][3] = __expf(s[nt][3] - nm1); ps1 += s[nt][3];
        }
        ps0 += __shfl_xor_sync(0xFFFFFFFF, ps0, 1);
        ps0 += __shfl_xor_sync(0xFFFFFFFF, ps0, 2);
        ps1 += __shfl_xor_sync(0xFFFFFFFF, ps1, 1);
        ps1 += __shfl_xor_sync(0xFFFFFFFF, ps1, 2);
        l0 = l0 * rs0 + ps0;
        l1 = l1 * rs1 + ps1;

#pragma unroll
        for (int nt = 0; nt < 8; nt++) {
            o[nt][0] *= rs0; o[nt][1] *= rs0;
            o[nt][2] *= rs1; o[nt][3] *= rs1;
        }

        // ---- O += P V (P single fp16) ----
#pragma unroll
        for (int kt = 0; kt < 4; kt++) {
            uint32_t phi[4], vh4[4][4];
            phi[0] = pack2h(s[2 * kt][0],     s[2 * kt][1]);
            phi[1] = pack2h(s[2 * kt][2],     s[2 * kt][3]);
            phi[2] = pack2h(s[2 * kt + 1][0], s[2 * kt + 1][1]);
            phi[3] = pack2h(s[2 * kt + 1][2], s[2 * kt + 1][3]);
#pragma unroll
            for (int nt2 = 0; nt2 < 4; nt2++) {
                uint32_t va = kb + 9216 + (kt * 16 + (lane & 15)) * 144
                            + (nt2 * 16 + (lane >> 4) * 8) * 2;
                ldsm4t(vh4[nt2], va);
            }
#pragma unroll
            for (int nt2 = 0; nt2 < 4; nt2++) {
                mma_f16(o[2 * nt2],     phi, vh4[nt2][0], vh4[nt2][1]);
                mma_f16(o[2 * nt2 + 1], phi, vh4[nt2][2], vh4[nt2][3]);
            }
        }
    }

    // ---- epilogue: write ctx as fp16 hi/lo directly ----
    float inv0 = 1.0f / l0, inv1 = 1.0f / l1;
    size_t co0 = ((size_t)(b * SS + sq0)) * DD + h * DKK;
    size_t co1 = ((size_t)(b * SS + sq0 + 8)) * DD + h * DKK;
#pragma unroll
    for (int nt = 0; nt < 8; nt++) {
        int cc = 8 * nt + 2 * q4;
        uint32_t hp, lp;
        packhl_h(o[nt][0] * inv0, o[nt][1] * inv0, hp, lp);
        *(uint32_t*)(g_ctx_hi + co0 + cc) = hp;
        *(uint32_t*)(g_ctx_lo + co0 + cc) = lp;
        packhl_h(o[nt][2] * inv1, o[nt][3] * inv1, hp, lp);
        *(uint32_t*)(g_ctx_hi + co1 + cc) = hp;
        *(uint32_t*)(g_ctx_lo + co1 + cc) = lp;
    }
}

// ---------------- launch ----------------
extern "C" void kernel_launch(void* const* d_in, const int* in_sizes, int n_in,
                              void* d_out, int out_size) {
    const float* hs   = (const float*)d_in[0];
    const float* Wq   = (const float*)d_in[1];
    const float* Wk   = (const float*)d_in[2];
    const float* Wv   = (const float*)d_in[3];
    const float* Wo   = (const float*)d_in[4];
    const float* relb = (const float*)d_in[5];
    const float* grel = (const float*)d_in[6];
    const float* gln  = (const float*)d_in[7];
    const int*   mask = (const int*)d_in[8];
    float* out = (float*)d_out;

    __half *hs_hi, *hs_lo, *ctx_hi, *ctx_lo, *gi_hi, *gi_lo, *wqkv, *wo;
    cudaGetSymbolAddress((void**)&hs_hi,  g_hs_hi);
    cudaGetSymbolAddress((void**)&hs_lo,  g_hs_lo);
    cudaGetSymbolAddress((void**)&ctx_hi, g_ctx_hi);
    cudaGetSymbolAddress((void**)&ctx_lo, g_ctx_lo);
    cudaGetSymbolAddress((void**)&gi_hi,  g_gi_hi);
    cudaGetSymbolAddress((void**)&gi_lo,  g_gi_lo);
    cudaGetSymbolAddress((void**)&wqkv,   g_wqkv);
    cudaGetSymbolAddress((void**)&wo,     g_wo);

    cudaFuncSetAttribute(bgemm, cudaFuncAttributeMaxDynamicSharedMemorySize, BGE_SMEM_BYTES);
    cudaFuncSetAttribute(k_attn, cudaFuncAttributeMaxDynamicSharedMemorySize, ATT_SMEM);

    const int NHS4 = BB * SS * DD / 4;
    const int NW4  = DD * DD / 4;

    // #1..#3: prerequisites for the big QKV GEMM
    k_cvt_qkvw<<<(3 * NW4 + 255) / 256, 256>>>((const float4*)Wq, (const float4*)Wk,
                                               (const float4*)Wv, (uint2*)wqkv);
    k_split<<<(NHS4 + 255) / 256, 256>>>((const float4*)hs, (uint2*)hs_hi, (uint2*)hs_lo, NHS4);
    k_block_ids<<<BB, 256>>>(mask);

    // #4: fused QKV GEMM (mode 1: Q->hi/lo, K/V->kat/vat)
    bgemm<<<dim3(3 * DD / 128, (BB * SS) / 128), 256, BGE_SMEM_BYTES>>>(
        hs_hi, hs_lo, DD, wqkv, 3 * DD, out /*unused*/, 0, DD, 1);

    // global path (agg writes gi hi/lo directly)
    k_global_agg<<<dim3(GLL, BB), 256>>>(hs, gln);
    bgemm<<<dim3(2 * DD / 128, (BB * GLL) / 128), 256, BGE_SMEM_BYTES>>>(
        gi_hi, gi_lo, DD, wqkv + DD, 3 * DD, out /*unused*/, 0, DD, 2);

    // bias tables + Wo convert
    k_pgtab<<<(HH * 512 + 255) / 256, 256>>>(relb, grel);
    k_cvt_w<<<(NW4 + 255) / 256, 256>>>((const float4*)Wo, (uint2*)wo, NW4);

    // attention
    k_attn<<<dim3(HH, SS / BLL, BB), 256, ATT_SMEM>>>(mask);

    // output projection (mode 0: fp32 out)
    bgemm<<<dim3(DD / 128, (BB * SS) / 128), 256, BGE_SMEM_BYTES>>>(
        ctx_hi, ctx_lo, DD, wo, DD, out, DD, DD, 0);
}

// round 16
// speedup vs baseline: 1.6923x; 1.0538x over previous
#include <cuda_runtime.h>
#include <cuda_bf16.h>
#include <cuda_fp16.h>
#include <cstdint>
#include <math.h>

#define BB   2
#define SS   4096
#define DD   1024
#define HH   16
#define DKK  64
#define BLL  128
#define GG   16
#define GLL  256
#define NBUCK 32
#define NEGV (-1e10f)
#define SROW (SS + GLL)

// ---------------- scratch ----------------
__device__ float g_pb [HH*512];
__device__ float g_gb [HH*512];
__device__ int   g_bid [BB*SS];
__device__ int   g_gseg[BB*GLL];
__device__ int   g_full[BB];

__device__ __half g_hs_hi  [BB*SS*DD];
__device__ __half g_hs_lo  [BB*SS*DD];
__device__ __half g_q      [BB*SS*DD];    // Q single fp16
__device__ __half g_ctx_hi [BB*SS*DD];
__device__ __half g_ctx_lo [BB*SS*DD];
__device__ __half g_gi_hi  [BB*GLL*DD];
__device__ __half g_gi_lo  [BB*GLL*DD];
__device__ __half g_wqkv   [DD*3*DD];
__device__ __half g_wo     [DD*DD];
__device__ __half g_kat    [BB*SROW*DD];
__device__ __half g_vat    [BB*SROW*DD];

// ---------------- helpers ----------------
__device__ __forceinline__ uint32_t smem_u32(const void* p) {
    uint32_t a;
    asm("{ .reg .u64 t; cvta.to.shared.u64 t, %1; cvt.u32.u64 %0, t; }" : "=r"(a) : "l"(p));
    return a;
}

#define CP16(dst, src) asm volatile("cp.async.cg.shared.global [%0], [%1], 16;" :: "r"(dst), "l"(src) : "memory")
#define CP_COMMIT()    asm volatile("cp.async.commit_group;" ::: "memory")
#define CP_WAIT0()     asm volatile("cp.async.wait_group 0;" ::: "memory")

__device__ __forceinline__ void ldsm4(uint32_t* r, uint32_t a) {
    asm volatile("ldmatrix.sync.aligned.m8n8.x4.shared.b16 {%0,%1,%2,%3}, [%4];"
        : "=r"(r[0]), "=r"(r[1]), "=r"(r[2]), "=r"(r[3]) : "r"(a));
}
__device__ __forceinline__ void ldsm4t(uint32_t* r, uint32_t a) {
    asm volatile("ldmatrix.sync.aligned.m8n8.x4.trans.shared.b16 {%0,%1,%2,%3}, [%4];"
        : "=r"(r[0]), "=r"(r[1]), "=r"(r[2]), "=r"(r[3]) : "r"(a));
}
__device__ __forceinline__ void mma_f16(float* d, const uint32_t* a, uint32_t b0, uint32_t b1) {
    asm volatile("mma.sync.aligned.m16n8k16.row.col.f32.f16.f16.f32 "
        "{%0,%1,%2,%3}, {%4,%5,%6,%7}, {%8,%9}, {%0,%1,%2,%3};"
        : "+f"(d[0]), "+f"(d[1]), "+f"(d[2]), "+f"(d[3])
        : "r"(a[0]), "r"(a[1]), "r"(a[2]), "r"(a[3]), "r"(b0), "r"(b1));
}

__device__ __forceinline__ void split4h(float4 a, uint2& h, uint2& l) {
    __half2 h01 = __floats2half2_rn(a.x, a.y);
    __half2 h23 = __floats2half2_rn(a.z, a.w);
    float l0 = a.x - __half2float(__low2half(h01));
    float l1 = a.y - __half2float(__high2half(h01));
    float l2 = a.z - __half2float(__low2half(h23));
    float l3 = a.w - __half2float(__high2half(h23));
    __half2 q01 = __floats2half2_rn(l0, l1);
    __half2 q23 = __floats2half2_rn(l2, l3);
    h = make_uint2(*(uint32_t*)&h01, *(uint32_t*)&h23);
    l = make_uint2(*(uint32_t*)&q01, *(uint32_t*)&q23);
}

__device__ __forceinline__ uint2 cvt4h(float4 a) {
    __half2 h01 = __floats2half2_rn(a.x, a.y);
    __half2 h23 = __floats2half2_rn(a.z, a.w);
    return make_uint2(*(uint32_t*)&h01, *(uint32_t*)&h23);
}

__device__ __forceinline__ void packhl_h(float a, float b, uint32_t& hp, uint32_t& lp) {
    __half2 hv = __floats2half2_rn(a, b);
    __half2 lv = __floats2half2_rn(a - __half2float(__low2half(hv)),
                                   b - __half2float(__high2half(hv)));
    hp = *(uint32_t*)&hv;
    lp = *(uint32_t*)&lv;
}
__device__ __forceinline__ uint32_t pack2h(float a, float b) {
    __half2 hv = __floats2half2_rn(a, b);
    return *(uint32_t*)&hv;
}

// ---------------- conversions ----------------
__global__ void k_split(const float4* __restrict__ src,
                        uint2* __restrict__ hi, uint2* __restrict__ lo, int n4) {
    int i = blockIdx.x * 256 + threadIdx.x;
    if (i >= n4) return;
    uint2 h, l;
    split4h(src[i], h, l);
    hi[i] = h; lo[i] = l;
}

__global__ void k_cvt(const float4* __restrict__ src, uint2* __restrict__ dst, int n4) {
    int i = blockIdx.x * 256 + threadIdx.x;
    if (i >= n4) return;
    dst[i] = cvt4h(src[i]);
}

__global__ void k_cvt_qkvw(const float4* __restrict__ Wq, const float4* __restrict__ Wk,
                           const float4* __restrict__ Wv, uint2* __restrict__ dst) {
    const int NW4 = DD * DD / 4;
    int idx = blockIdx.x * 256 + threadIdx.x;
    if (idx >= 3 * NW4) return;
    int i = idx / NW4;
    int r = idx % NW4;
    int k  = r >> 8;
    int n4 = r & 255;
    const float4* src = (i == 0) ? Wq : (i == 1) ? Wk : Wv;
    dst[k * (3 * DD / 4) + i * (DD / 4) + n4] = cvt4h(src[r]);
}

// ============ fp16 GEMM, BK=64, 2-stage; nsweep = 1 or 2 A-terms ============
// mode 0: C fp32 store.  mode 1: QKV (Q->g_q single, K->g_kat, V->g_vat).
// mode 2: skv.
#define SH_A0   0
#define SH_A1   9216
#define SH_B0   18432
#define SH_STG  27136
#define BGE_SMEM_BYTES (2 * SH_STG * 2)

__global__ __launch_bounds__(256, 2)
void bgemm(const __half* __restrict__ Ahi, const __half* __restrict__ Alo, int lda,
           const __half* __restrict__ Bh, int ldb,
           float* __restrict__ C, int ldc, int K, int mode, int nsweep) {
    extern __shared__ __half sh[];
    uint32_t sbase = smem_u32(sh);

    int tid = threadIdx.x;
    int wid = tid >> 5, lane = tid & 31;
    int wm = wid & 3, wn = wid >> 2;
    int bx = blockIdx.x, by = blockIdx.y;

    float acc[2][8][4];
#pragma unroll
    for (int mt = 0; mt < 2; mt++)
#pragma unroll
        for (int nt = 0; nt < 8; nt++)
#pragma unroll
            for (int j = 0; j < 4; j++) acc[mt][nt][j] = 0.f;

    auto load_stage = [&](int c, int stage) {
        int k0 = c * 64;
        uint32_t s0 = sbase + (uint32_t)(stage * SH_STG) * 2;
#pragma unroll
        for (int i = 0; i < 4; i++) {
            int idx = i * 256 + tid;
            int row = idx >> 3;
            int c8  = (idx & 7) * 8;
            size_t ga = (size_t)(by * 128 + row) * lda + k0 + c8;
            uint32_t d = s0 + (uint32_t)(row * 72 + c8) * 2;
            CP16(d, Ahi + ga);
            if (nsweep == 2) CP16(d + SH_A1 * 2, Alo + ga);
        }
#pragma unroll
        for (int i = 0; i < 4; i++) {
            int idx = i * 256 + tid;
            int row = idx >> 4;
            int c8  = (idx & 15) * 8;
            size_t gb = (size_t)(k0 + row) * ldb + bx * 128 + c8;
            CP16(s0 + (uint32_t)(SH_B0 + row * 136 + c8) * 2, Bh + gb);
        }
        CP_COMMIT();
    };

    int nch = K >> 6;
    load_stage(0, 0);
    for (int c = 0; c < nch; c++) {
        CP_WAIT0();
        __syncthreads();
        if (c + 1 < nch) load_stage(c + 1, (c + 1) & 1);
        uint32_t s0 = sbase + (uint32_t)((c & 1) * SH_STG) * 2;
#pragma unroll
        for (int ks = 0; ks < 4; ks++) {
            uint32_t ah[2][4], al[2][4], bh4[4][4];
#pragma unroll
            for (int mt = 0; mt < 2; mt++) {
                int row = wm * 32 + mt * 16 + (lane & 15);
                int col = ks * 16 + (lane >> 4) * 8;
                uint32_t a = s0 + (uint32_t)(row * 72 + col) * 2;
                ldsm4(ah[mt], a);
                if (nsweep == 2) ldsm4(al[mt], a + SH_A1 * 2);
            }
#pragma unroll
            for (int nt2 = 0; nt2 < 4; nt2++) {
                int krow = ks * 16 + (lane & 15);
                int ncol = wn * 64 + nt2 * 16 + (lane >> 4) * 8;
                ldsm4t(bh4[nt2], s0 + (uint32_t)(SH_B0 + krow * 136 + ncol) * 2);
            }
#pragma unroll
            for (int nt2 = 0; nt2 < 4; nt2++)
#pragma unroll
                for (int p = 0; p < 2; p++)
#pragma unroll
                    for (int mt = 0; mt < 2; mt++)
                        mma_f16(acc[mt][nt2 * 2 + p], ah[mt],
                                bh4[nt2][2 * p], bh4[nt2][2 * p + 1]);
            if (nsweep == 2) {
#pragma unroll
                for (int nt2 = 0; nt2 < 4; nt2++)
#pragma unroll
                    for (int p = 0; p < 2; p++)
#pragma unroll
                        for (int mt = 0; mt < 2; mt++)
                            mma_f16(acc[mt][nt2 * 2 + p], al[mt],
                                    bh4[nt2][2 * p], bh4[nt2][2 * p + 1]);
            }
        }
    }
    __syncthreads();

    if (mode == 0) {
#pragma unroll
        for (int mt = 0; mt < 2; mt++) {
#pragma unroll
            for (int nt = 0; nt < 8; nt++) {
                int r  = by * 128 + wm * 32 + mt * 16 + (lane >> 2);
                int cc = bx * 128 + wn * 64 + nt * 8 + (lane & 3) * 2;
                *(float2*)&C[(size_t)r * ldc + cc] =
                    make_float2(acc[mt][nt][0], acc[mt][nt][1]);
                *(float2*)&C[(size_t)(r + 8) * ldc + cc] =
                    make_float2(acc[mt][nt][2], acc[mt][nt][3]);
            }
        }
    } else if (mode == 1) {
        int seg = bx >> 3;            // 0 Q, 1 K, 2 V
#pragma unroll
        for (int mt = 0; mt < 2; mt++) {
            int r  = by * 128 + wm * 32 + mt * 16 + (lane >> 2);
            int b  = r / SS, s2 = r % SS;
#pragma unroll
            for (int nt = 0; nt < 8; nt++) {
                int cg  = bx * 128 + wn * 64 + nt * 8 + (lane & 3) * 2;
                int col = cg - seg * 1024;
                if (seg == 0) {
                    *(uint32_t*)(g_q + (size_t)r * DD + col) =
                        pack2h(acc[mt][nt][0], acc[mt][nt][1]);
                    *(uint32_t*)(g_q + (size_t)(r + 8) * DD + col) =
                        pack2h(acc[mt][nt][2], acc[mt][nt][3]);
                } else {
                    __half* dst = (seg == 1) ? g_kat : g_vat;
                    size_t o0 = ((size_t)(b * SROW + s2)) * DD + col;
                    *(uint32_t*)(dst + o0) = pack2h(acc[mt][nt][0], acc[mt][nt][1]);
                    *(uint32_t*)(dst + o0 + 8 * DD) = pack2h(acc[mt][nt][2], acc[mt][nt][3]);
                }
            }
        }
    } else {   // mode 2: skv
        int seg = bx >> 3;
        __half* dst = (seg == 0) ? g_kat : g_vat;
#pragma unroll
        for (int mt = 0; mt < 2; mt++) {
            int r  = by * 128 + wm * 32 + mt * 16 + (lane >> 2);
            int b  = r / GLL, gI = r % GLL;
#pragma unroll
            for (int nt = 0; nt < 8; nt++) {
                int cg  = bx * 128 + wn * 64 + nt * 8 + (lane & 3) * 2;
                int col = cg - seg * 1024;
                size_t o0 = ((size_t)(b * SROW + SS + gI)) * DD + col;
                *(uint32_t*)(dst + o0) = pack2h(acc[mt][nt][0], acc[mt][nt][1]);
                *(uint32_t*)(dst + o0 + 8 * DD) = pack2h(acc[mt][nt][2], acc[mt][nt][3]);
            }
        }
    }
}

// ---------------- T5 bidirectional relative bucket ----------------
__device__ __forceinline__ int rel_bucket(int rp) {
    int rb = (rp > 0) ? (NBUCK / 2) : 0;
    int a  = rp < 0 ? -rp : rp;
    if (a < 8) return rb + a;
    float rf = (float)a;
    int large = 8 + (int)(logf(rf * 0.125f) * (8.0f / 2.772588722239781f));
    if (large > 15) large = 15;
    return rb + large;
}

__global__ void k_pgtab(const float* __restrict__ relb, const float* __restrict__ grel) {
    int idx = blockIdx.x * 256 + threadIdx.x;
    if (idx >= HH * 512) return;
    int h = idx >> 9;
    int i = idx & 511;
    int rel = i - 255;
    int bk = rel_bucket(rel);
    g_pb[idx] = relb[bk * HH + h];
    g_gb[idx] = grel[bk * HH + h];
}

// ---------------- block ids / global segments ----------------
__global__ void k_block_ids(const int* __restrict__ mask) {
    int b = blockIdx.x;
    __shared__ int s_cnt, s_max;
    if (threadIdx.x == 0) { s_cnt = 0; s_max = -1; }
    __syncthreads();
    int lc = 0;
    for (int i = threadIdx.x; i < SS; i += blockDim.x)
        if (((i & (GG - 1)) == GG - 1) && mask[b * SS + i] != 0) lc++;
    atomicAdd(&s_cnt, lc);
    __syncthreads();
    int full = s_cnt - 1;
    int lm = -1;
    for (int i = threadIdx.x; i < SS; i += blockDim.x) {
        int id;
        if (mask[b * SS + i] != 0) { id = i / GG; if (id > full) id = full; }
        else id = -1;
        g_bid[b * SS + i] = id;
        if (id > lm) lm = id;
    }
    atomicMax(&s_max, lm);
    __syncthreads();
    for (int g = threadIdx.x; g < GLL; g += blockDim.x)
        g_gseg[b * GLL + g] = (g <= s_max) ? 1 : 0;
    if (threadIdx.x == 0) g_full[b] = full;
}

// ---------------- global aggregates + RMSNorm -> gi hi/lo ----------------
__global__ void k_global_agg(const float* __restrict__ hs, const float* __restrict__ gln_w) {
    int g = blockIdx.x, b = blockIdx.y;
    int t = threadIdx.x;
    int full = g_full[b];
    float acc0 = 0.f, acc1 = 0.f, acc2 = 0.f, acc3 = 0.f;
    if (g <= full) {
        int s_begin = g * GG;
        int s_end   = (g == full) ? SS : (g + 1) * GG;
#pragma unroll 1
        for (int s = s_begin; s < s_end; s++) {
            if (g_bid[b * SS + s] == g) {
                const float* row = hs + ((size_t)(b * SS + s)) * DD;
                acc0 += row[t];
                acc1 += row[t + 256];
                acc2 += row[t + 512];
                acc3 += row[t + 768];
            }
        }
    }
    __shared__ float red[256];
    red[t] = acc0 * acc0 + acc1 * acc1 + acc2 * acc2 + acc3 * acc3;
    __syncthreads();
    for (int off = 128; off > 0; off >>= 1) {
        if (t < off) red[t] += red[t + off];
        __syncthreads();
    }
    float var = red[0] * (1.0f / (float)DD);
    float sc = rsqrtf(var + 1e-6f);
    size_t base = ((size_t)(b * GLL + g)) * DD;
    float vals[4] = {acc0 * sc * gln_w[t], acc1 * sc * gln_w[t + 256],
                     acc2 * sc * gln_w[t + 512], acc3 * sc * gln_w[t + 768]};
#pragma unroll
    for (int j = 0; j < 4; j++) {
        float v = vals[j];
        __half hv = __float2half_rn(v);
        g_gi_hi[base + t + j * 256] = hv;
        g_gi_lo[base + t + j * 256] = __float2half_rn(v - __half2float(hv));
    }
}

// ================= tensor-core attention (Q single, K/V single) =============
#define ATT_PB   36864
#define ATT_GB   38912
#define ATT_KVAL 40960
#define ATT_GSEG 41472
#define ATT_SMEM 42496

__global__ __launch_bounds__(256, 2)
void k_attn(const int* __restrict__ mask) {
    extern __shared__ char sm[];
    uint32_t sbase = smem_u32(sm);
    int h = blockIdx.x, n = blockIdx.y, b = blockIdx.z;
    int tid = threadIdx.x;
    int w = tid >> 5, lane = tid & 31;
    int g4 = lane >> 2, q4 = lane & 3;

    // ---- stage Q (single fp16) transiently via cp.async ----
#pragma unroll
    for (int i = 0; i < 4; i++) {
        int idx = i * 256 + tid;
        int row = idx >> 3;
        int c8  = (idx & 7) * 8;
        size_t goff = ((size_t)(b * SS + n * BLL + row)) * DD + h * DKK + c8;
        CP16(sbase + (uint32_t)(row * 144 + c8 * 2), g_q + goff);
    }
    CP_COMMIT();
    ((float*)(sm + ATT_PB))[tid]       = g_pb[h * 512 + tid];
    ((float*)(sm + ATT_PB))[tid + 256] = g_pb[h * 512 + tid + 256];
    ((float*)(sm + ATT_GB))[tid]       = g_gb[h * 512 + tid];
    ((float*)(sm + ATT_GB))[tid + 256] = g_gb[h * 512 + tid + 256];
    ((int*)(sm + ATT_GSEG))[tid]       = g_gseg[b * GLL + tid];
    CP_WAIT0();
    __syncthreads();

    uint32_t qfh[4][4];
#pragma unroll
    for (int kt = 0; kt < 4; kt++) {
        uint32_t qa = sbase + (w * 16 + (lane & 15)) * 144 + (kt * 16 + (lane >> 4) * 8) * 2;
        ldsm4(qfh[kt], qa);
    }
    __syncthreads();

    int r0  = w * 16 + g4;
    int sq0 = n * BLL + r0;
    int mq0 = mask[b * SS + sq0], mq1 = mask[b * SS + sq0 + 8];
    int bid0 = g_bid[b * SS + sq0], bid1 = g_bid[b * SS + sq0 + 8];

    const float* pb_s   = (const float*)(sm + ATT_PB);
    const float* gb_s   = (const float*)(sm + ATT_GB);
    const int*   kval_s = (const int*)(sm + ATT_KVAL);
    const int*   gseg_s = (const int*)(sm + ATT_GSEG);

    auto stage = [&](int c, int buf) {
        uint32_t sb = sbase + (uint32_t)buf * 18432;
#pragma unroll
        for (int i = 0; i < 4; i++) {
            int idx = i * 256 + tid;
            int isV = idx >> 9;
            int r   = (idx >> 3) & 63;
            int c8  = (idx & 7) * 8;
            int srcrow;
            if (c < 6) {
                int t = (n - 1) * BLL + c * 64 + r;
                srcrow = min(max(t, 0), SS - 1);
            } else {
                srcrow = SS + (c - 6) * 64 + r;
            }
            size_t goff = ((size_t)(b * SROW + srcrow)) * DD + h * DKK + c8;
            uint32_t dst = sb + (uint32_t)(isV * 9216 + r * 144 + c8 * 2);
            CP16(dst, (isV ? g_vat : g_kat) + goff);
        }
        CP_COMMIT();
        if (c < 6 && tid < 64) {
            int t = (n - 1) * BLL + c * 64 + tid;
            ((int*)(sm + ATT_KVAL))[buf * 64 + tid] = (t >= 0 && t < SS) ? mask[b * SS + t] : 0;
        }
    };

    float o[8][4];
#pragma unroll
    for (int nt = 0; nt < 8; nt++)
#pragma unroll
        for (int j = 0; j < 4; j++) o[nt][j] = 0.f;
    float m0 = -1e30f, m1 = -1e30f, l0 = 0.f, l1 = 0.f;

    stage(0, 0);
    for (int c = 0; c < 10; c++) {
        int buf = c & 1;
        CP_WAIT0();
        __syncthreads();
        if (c + 1 < 10) stage(c + 1, (c + 1) & 1);

        uint32_t kb = sbase + (uint32_t)buf * 18432;

        // ---- S = Q K^T (single term) ----
        float s[8][4];
#pragma unroll
        for (int nt = 0; nt < 8; nt++)
#pragma unroll
            for (int j = 0; j < 4; j++) s[nt][j] = 0.f;

#pragma unroll
        for (int kt = 0; kt < 4; kt++) {
            uint32_t kh4[4][4];
#pragma unroll
            for (int nt2 = 0; nt2 < 4; nt2++) {
                uint32_t ka = kb + (nt2 * 16 + (lane & 15)) * 144
                            + (kt * 16 + (lane >> 4) * 8) * 2;
                ldsm4(kh4[nt2], ka);
            }
#pragma unroll
            for (int nt2 = 0; nt2 < 4; nt2++) {
                mma_f16(s[2 * nt2],     qfh[kt], kh4[nt2][0], kh4[nt2][2]);
                mma_f16(s[2 * nt2 + 1], qfh[kt], kh4[nt2][1], kh4[nt2][3]);
            }
        }

        // ---- bias + mask ----
#pragma unroll
        for (int nt = 0; nt < 8; nt++) {
            int cn = 8 * nt + 2 * q4;
            if (c < 6) {
                int kv0 = kval_s[buf * 64 + cn], kv1 = kval_s[buf * 64 + cn + 1];
                int rel0 = c * 64 + cn - BLL - r0;
                int rel1 = rel0 - 8;
                s[nt][0] += pb_s[rel0 + 255] +
                    ((mq0 && kv0 && rel0 > -BLL && rel0 < BLL) ? 0.f : NEGV);
                s[nt][1] += pb_s[rel0 + 256] +
                    ((mq0 && kv1 && rel0 + 1 > -BLL && rel0 + 1 < BLL) ? 0.f : NEGV);
                s[nt][2] += pb_s[rel1 + 255] +
                    ((mq1 && kv0 && rel1 > -BLL && rel1 < BLL) ? 0.f : NEGV);
                s[nt][3] += pb_s[rel1 + 256] +
                    ((mq1 && kv1 && rel1 + 1 > -BLL && rel1 + 1 < BLL) ? 0.f : NEGV);
            } else {
                int g0 = (c - 6) * 64 + cn;
                int gs0 = gseg_s[g0], gs1 = gseg_s[g0 + 1];
                int sp0 = g0 - bid0, sp1 = g0 - bid1;
                s[nt][0] += gb_s[sp0 + 255] + ((mq0 == gs0) ? 0.f : NEGV);
                s[nt][1] += gb_s[sp0 + 256] + ((mq0 == gs1) ? 0.f : NEGV);
                s[nt][2] += gb_s[sp1 + 255] + ((mq1 == gs0) ? 0.f : NEGV);
                s[nt][3] += gb_s[sp1 + 256] + ((mq1 == gs1) ? 0.f : NEGV);
            }
        }

        // ---- online softmax ----
        float mx0 = -1e30f, mx1 = -1e30f;
#pragma unroll
        for (int nt = 0; nt < 8; nt++) {
            mx0 = fmaxf(mx0, fmaxf(s[nt][0], s[nt][1]));
            mx1 = fmaxf(mx1, fmaxf(s[nt][2], s[nt][3]));
        }
        mx0 = fmaxf(mx0, __shfl_xor_sync(0xFFFFFFFF, mx0, 1));
        mx0 = fmaxf(mx0, __shfl_xor_sync(0xFFFFFFFF, mx0, 2));
        mx1 = fmaxf(mx1, __shfl_xor_sync(0xFFFFFFFF, mx1, 1));
        mx1 = fmaxf(mx1, __shfl_xor_sync(0xFFFFFFFF, mx1, 2));
        float nm0 = fmaxf(m0, mx0), nm1 = fmaxf(m1, mx1);
        float rs0 = __expf(m0 - nm0), rs1 = __expf(m1 - nm1);
        m0 = nm0; m1 = nm1;

        float ps0 = 0.f, ps1 = 0.f;
#pragma unroll
        for (int nt = 0; nt < 8; nt++) {
            s[nt][0] = __expf(s[nt][0] - nm0); ps0 += s[nt][0];
            s[nt][1] = __expf(s[nt][1] - nm0); ps0 += s[nt][1];
            s[nt][2] = __expf(s[nt][2] - nm1); ps1 += s[nt][2];
            s[nt][3] = __expf(s[nt][3] - nm1); ps1 += s[nt][3];
        }
        ps0 += __shfl_xor_sync(0xFFFFFFFF, ps0, 1);
        ps0 += __shfl_xor_sync(0xFFFFFFFF, ps0, 2);
        ps1 += __shfl_xor_sync(0xFFFFFFFF, ps1, 1);
        ps1 += __shfl_xor_sync(0xFFFFFFFF, ps1, 2);
        l0 = l0 * rs0 + ps0;
        l1 = l1 * rs1 + ps1;

#pragma unroll
        for (int nt = 0; nt < 8; nt++) {
            o[nt][0] *= rs0; o[nt][1] *= rs0;
            o[nt][2] *= rs1; o[nt][3] *= rs1;
        }

        // ---- O += P V ----
#pragma unroll
        for (int kt = 0; kt < 4; kt++) {
            uint32_t phi[4], vh4[4][4];
            phi[0] = pack2h(s[2 * kt][0],     s[2 * kt][1]);
            phi[1] = pack2h(s[2 * kt][2],     s[2 * kt][3]);
            phi[2] = pack2h(s[2 * kt + 1][0], s[2 * kt + 1][1]);
            phi[3] = pack2h(s[2 * kt + 1][2], s[2 * kt + 1][3]);
#pragma unroll
            for (int nt2 = 0; nt2 < 4; nt2++) {
                uint32_t va = kb + 9216 + (kt * 16 + (lane & 15)) * 144
                            + (nt2 * 16 + (lane >> 4) * 8) * 2;
                ldsm4t(vh4[nt2], va);
            }
#pragma unroll
            for (int nt2 = 0; nt2 < 4; nt2++) {
                mma_f16(o[2 * nt2],     phi, vh4[nt2][0], vh4[nt2][1]);
                mma_f16(o[2 * nt2 + 1], phi, vh4[nt2][2], vh4[nt2][3]);
            }
        }
    }

    // ---- epilogue: ctx hi/lo ----
    float inv0 = 1.0f / l0, inv1 = 1.0f / l1;
    size_t co0 = ((size_t)(b * SS + sq0)) * DD + h * DKK;
    size_t co1 = ((size_t)(b * SS + sq0 + 8)) * DD + h * DKK;
#pragma unroll
    for (int nt = 0; nt < 8; nt++) {
        int cc = 8 * nt + 2 * q4;
        uint32_t hp, lp;
        packhl_h(o[nt][0] * inv0, o[nt][1] * inv0, hp, lp);
        *(uint32_t*)(g_ctx_hi + co0 + cc) = hp;
        *(uint32_t*)(g_ctx_lo + co0 + cc) = lp;
        packhl_h(o[nt][2] * inv1, o[nt][3] * inv1, hp, lp);
        *(uint32_t*)(g_ctx_hi + co1 + cc) = hp;
        *(uint32_t*)(g_ctx_lo + co1 + cc) = lp;
    }
}

// ---------------- launch ----------------
extern "C" void kernel_launch(void* const* d_in, const int* in_sizes, int n_in,
                              void* d_out, int out_size) {
    const float* hs   = (const float*)d_in[0];
    const float* Wq   = (const float*)d_in[1];
    const float* Wk   = (const float*)d_in[2];
    const float* Wv   = (const float*)d_in[3];
    const float* Wo   = (const float*)d_in[4];
    const float* relb = (const float*)d_in[5];
    const float* grel = (const float*)d_in[6];
    const float* gln  = (const float*)d_in[7];
    const int*   mask = (const int*)d_in[8];
    float* out = (float*)d_out;

    __half *hs_hi, *hs_lo, *ctx_hi, *ctx_lo, *gi_hi, *gi_lo, *wqkv, *wo;
    cudaGetSymbolAddress((void**)&hs_hi,  g_hs_hi);
    cudaGetSymbolAddress((void**)&hs_lo,  g_hs_lo);
    cudaGetSymbolAddress((void**)&ctx_hi, g_ctx_hi);
    cudaGetSymbolAddress((void**)&ctx_lo, g_ctx_lo);
    cudaGetSymbolAddress((void**)&gi_hi,  g_gi_hi);
    cudaGetSymbolAddress((void**)&gi_lo,  g_gi_lo);
    cudaGetSymbolAddress((void**)&wqkv,   g_wqkv);
    cudaGetSymbolAddress((void**)&wo,     g_wo);

    cudaFuncSetAttribute(bgemm, cudaFuncAttributeMaxDynamicSharedMemorySize, BGE_SMEM_BYTES);
    cudaFuncSetAttribute(k_attn, cudaFuncAttributeMaxDynamicSharedMemorySize, ATT_SMEM);

    const int NHS4 = BB * SS * DD / 4;
    const int NW4  = DD * DD / 4;

    // #1..#3: prerequisites for the big QKV GEMM
    k_cvt_qkvw<<<(3 * NW4 + 255) / 256, 256>>>((const float4*)Wq, (const float4*)Wk,
                                               (const float4*)Wv, (uint2*)wqkv);
    k_split<<<(NHS4 + 255) / 256, 256>>>((const float4*)hs, (uint2*)hs_hi, (uint2*)hs_lo, NHS4);
    k_block_ids<<<BB, 256>>>(mask);

    // #4: fused QKV GEMM (A 2-term, as in R14)
    bgemm<<<dim3(3 * DD / 128, (BB * SS) / 128), 256, BGE_SMEM_BYTES>>>(
        hs_hi, hs_lo, DD, wqkv, 3 * DD, out /*unused*/, 0, DD, 1, 2);

    // global path (gi 2-term)
    k_global_agg<<<dim3(GLL, BB), 256>>>(hs, gln);
    bgemm<<<dim3(2 * DD / 128, (BB * GLL) / 128), 256, BGE_SMEM_BYTES>>>(
        gi_hi, gi_lo, DD, wqkv + DD, 3 * DD, out /*unused*/, 0, DD, 2, 2);

    // bias tables + Wo convert (single fp16, as in R14)
    k_pgtab<<<(HH * 512 + 255) / 256, 256>>>(relb, grel);
    k_cvt<<<(NW4 + 255) / 256, 256>>>((const float4*)Wo, (uint2*)wo, NW4);

    // attention (Q single term)
    k_attn<<<dim3(HH, SS / BLL, BB), 256, ATT_SMEM>>>(mask);

    // output projection (ctx 2-term @ wo single, as in R14)
    bgemm<<<dim3(DD / 128, (BB * SS) / 128), 256, BGE_SMEM_BYTES>>>(
        ctx_hi, ctx_lo, DD, wo, DD, out, DD, DD, 0, 2);
}